// round 12
// baseline (speedup 1.0000x reference)
#include <cuda_runtime.h>
#include <cuda_bf16.h>
#include <cstdint>
#include <math.h>

#define B_   4
#define LSEQ 1024
#define DM   1024
#define NH   16
#define DKH  64
#define DFF  4096
#define NL   2
#define ROWS (B_*LSEQ)   // 4096

// ================= scratch (device globals: allocation-guard safe) =========
__device__ float g_x  [ROWS*DM];
__device__ float g_tmp[ROWS*DM];
__device__ float g_v  [ROWS*DM];
__device__ float g_ctx[ROWS*DM];
__device__ float g_ffn[(size_t)ROWS*DFF];
// bf16 buffers for attention path
__device__ __nv_bfloat16 g_qh[ROWS*DM], g_ql[ROWS*DM];
__device__ __nv_bfloat16 g_kh[ROWS*DM], g_kl[ROWS*DM];
__device__ __nv_bfloat16 g_vth[ROWS*DM], g_vtl[ROWS*DM];
// int8 split activations + per-row scales
__device__ char  g_x8h[ROWS*DM],  g_x8l[ROWS*DM];
__device__ char  g_c8h[ROWS*DM],  g_c8l[ROWS*DM];
__device__ char  g_f8h[(size_t)ROWS*DFF], g_f8l[(size_t)ROWS*DFF];
__device__ float g_sx[ROWS], g_sc[ROWS], g_sf[ROWS];
// int8 split weights (pre-transposed to [N,K]) + per-out-channel scales
__device__ char g_wq8h[NL*DM*DM], g_wq8l[NL*DM*DM];
__device__ char g_wk8h[NL*DM*DM], g_wk8l[NL*DM*DM];
__device__ char g_wv8h[NL*DM*DM], g_wv8l[NL*DM*DM];
__device__ char g_wo8h[NL*DM*DM], g_wo8l[NL*DM*DM];
__device__ char g_w18h[(size_t)NL*DM*DFF], g_w18l[(size_t)NL*DM*DFF];
__device__ char g_w28h[(size_t)NL*DM*DFF], g_w28l[(size_t)NL*DM*DFF];
__device__ float g_swq[NL*DM], g_swk[NL*DM], g_swv[NL*DM], g_swo[NL*DM];
__device__ float g_sw1[NL*DFF], g_sw2[NL*DM];

// ================= PTX helpers (sm_80-baseline; no tcgen05) ================
#define CP_ASYNC16(smem, gptr) \
  asm volatile("cp.async.cg.shared.global [%0], [%1], 16;" \
               :: "r"(smem), "l"(gptr))
#define CP_COMMIT() asm volatile("cp.async.commit_group;" ::: "memory")
#define CP_WAIT1()  asm volatile("cp.async.wait_group 1;" ::: "memory")

#define LDSM4(r, addr) \
  asm volatile("ldmatrix.sync.aligned.m8n8.x4.shared.b16 {%0,%1,%2,%3}, [%4];" \
    : "=r"((r)[0]), "=r"((r)[1]), "=r"((r)[2]), "=r"((r)[3]) : "r"(addr))

#define MMA16816(d, a, b0v, b1v) \
  asm volatile("mma.sync.aligned.m16n8k16.row.col.f32.bf16.bf16.f32 " \
    "{%0,%1,%2,%3}, {%4,%5,%6,%7}, {%8,%9}, {%0,%1,%2,%3};" \
    : "+f"((d)[0]), "+f"((d)[1]), "+f"((d)[2]), "+f"((d)[3]) \
    : "r"((a)[0]), "r"((a)[1]), "r"((a)[2]), "r"((a)[3]), "r"(b0v), "r"(b1v))

#define IMMA16832(d, a, b0v, b1v) \
  asm volatile("mma.sync.aligned.m16n8k32.row.col.s32.s8.s8.s32 " \
    "{%0,%1,%2,%3}, {%4,%5,%6,%7}, {%8,%9}, {%0,%1,%2,%3};" \
    : "+r"((d)[0]), "+r"((d)[1]), "+r"((d)[2]), "+r"((d)[3]) \
    : "r"((a)[0]), "r"((a)[1]), "r"((a)[2]), "r"((a)[3]), "r"(b0v), "r"(b1v))

__device__ __forceinline__ uint32_t smem_to_u32(const void* p) {
  uint32_t a;
  asm("{ .reg .u64 t; cvta.to.shared.u64 t, %1; cvt.u32.u64 %0, t; }"
      : "=r"(a) : "l"(p));
  return a;
}

// q in [-32512, 32512]; a ~= s*(qh*256 + ql), s = rowmax/32512
__device__ __forceinline__ void quant16(float v, float inv_s, char& qh, char& ql) {
  int q = __float2int_rn(v * inv_s);
  q = max(-32512, min(32512, q));
  int h = (q + 128) >> 8;
  ql = (char)(q - (h << 8));
  qh = (char)h;
}

// ================= int8-split IMMA GEMM: C = A[M,K] @ Bt[N,K]^T ============
// CTA tile 128x128, K chunk 128 int8 (128B rows), 3-stage cp.async pipeline,
// 8 warps, warp tile 64x32. acc_hi (hh terms) + acc_mid (hl + lh terms).
#define NSTAGE   3
#define MATB     16384                  // 128 rows x 128 bytes
#define STAGEB   (4 * MATB)             // Ah, Al, Bh, Bl
#define GEMM_SMEM (NSTAGE * STAGEB)     // 196608

__device__ __forceinline__ void load_stage_i8(
    uint32_t sbase, const char* Ah, const char* Al,
    const char* Bh, const char* Bl,
    size_t rowA, size_t rowB, int K, int kc, int tid) {
#pragma unroll
  for (int i = 0; i < 16; i++) {
    int idx = tid + i * 256;            // 0..4095
    int mat = idx >> 10;                // constant per i
    int sub = idx & 1023;
    int row = sub >> 3, chunk = sub & 7;
    const char* base = (mat == 0) ? Ah : (mat == 1) ? Al
                     : (mat == 2) ? Bh : Bl;
    size_t r0 = (mat < 2) ? rowA : rowB;
    const char* g = base + (r0 + row) * (size_t)K + (size_t)kc * 128 + chunk * 16;
    uint32_t s = sbase + mat * MATB + row * 128 + ((chunk ^ (row & 7)) << 4);
    CP_ASYNC16(s, g);
  }
}

// mode 0: fp32 out (+relu), mode 1: bf16 hi/lo out
__device__ __forceinline__ void gemm_i8_body(
    const char* Ah, const char* Al, const float* sa,
    const char* Bh, const char* Bl, const float* sb,
    float* Cf, __nv_bfloat16* CH, __nv_bfloat16* CL,
    int K, int N, int relu, int mode,
    char* smem, int bx, int by) {
  const uint32_t sbm = smem_to_u32(smem);
  const int tid = threadIdx.x, wid = tid >> 5, lane = tid & 31;

  const size_t rowA = (size_t)by * 128;
  const size_t rowB = (size_t)bx * 128;
  const int nch = K / 128;

  const int mbase = (wid >> 2) * 64;   // 0 or 64
  const int nbase = (wid & 3) * 32;    // 0,32,64,96

  const int aRowOff = ((lane >> 3) & 1) * 8 + (lane & 7);
  const int aCSel   = (lane >> 4) & 1;
  const int bRowOff = ((lane >> 4) & 1) * 8 + (lane & 7);
  const int bCSel   = (lane >> 3) & 1;

  int acc_hi[4][4][4], acc_mid[4][4][4];
#pragma unroll
  for (int mt = 0; mt < 4; mt++)
#pragma unroll
    for (int nt = 0; nt < 4; nt++)
#pragma unroll
      for (int e = 0; e < 4; e++) { acc_hi[mt][nt][e] = 0; acc_mid[mt][nt][e] = 0; }

#pragma unroll
  for (int s = 0; s < NSTAGE - 1; s++) {
    if (s < nch) load_stage_i8(sbm + s * STAGEB, Ah, Al, Bh, Bl, rowA, rowB, K, s, tid);
    CP_COMMIT();
  }

  for (int kc = 0; kc < nch; kc++) {
    CP_WAIT1();
    __syncthreads();
    if (kc + NSTAGE - 1 < nch) {
      load_stage_i8(sbm + ((kc + NSTAGE - 1) % NSTAGE) * STAGEB,
                    Ah, Al, Bh, Bl, rowA, rowB, K, kc + NSTAGE - 1, tid);
    }
    CP_COMMIT();

    const uint32_t bufA_h = sbm + (kc % NSTAGE) * STAGEB;
    const uint32_t bufA_l = bufA_h + MATB;
    const uint32_t bufB_h = bufA_h + 2 * MATB;
    const uint32_t bufB_l = bufA_h + 3 * MATB;

#pragma unroll
    for (int kk = 0; kk < 4; kk++) {     // each kk = k32 int8
      uint32_t a_h[4][4], a_l[4][4];
#pragma unroll
      for (int mt = 0; mt < 4; mt++) {
        int row = mbase + mt * 16 + aRowOff;
        int ci  = kk * 2 + aCSel;
        uint32_t off = row * 128 + ((ci ^ (row & 7)) << 4);
        LDSM4(a_h[mt], bufA_h + off);
        LDSM4(a_l[mt], bufA_l + off);
      }
      uint32_t b_h[2][4], b_l[2][4];
#pragma unroll
      for (int ng = 0; ng < 2; ng++) {
        int row = nbase + ng * 16 + bRowOff;
        int ci  = kk * 2 + bCSel;
        uint32_t off = row * 128 + ((ci ^ (row & 7)) << 4);
        LDSM4(b_h[ng], bufB_h + off);
        LDSM4(b_l[ng], bufB_l + off);
      }
#pragma unroll
      for (int mt = 0; mt < 4; mt++)
#pragma unroll
        for (int nt = 0; nt < 4; nt++) {
          const int ng = nt >> 1, j = (nt & 1) * 2;
          IMMA16832(acc_hi[mt][nt],  a_h[mt], b_h[ng][j], b_h[ng][j + 1]);
          IMMA16832(acc_mid[mt][nt], a_h[mt], b_l[ng][j], b_l[ng][j + 1]);
          IMMA16832(acc_mid[mt][nt], a_l[mt], b_h[ng][j], b_h[ng][j + 1]);
        }
    }
    __syncthreads();
  }

  const int rT = lane >> 2, cT = (lane & 3) * 2;
#pragma unroll
  for (int mt = 0; mt < 4; mt++) {
    const size_t ra = rowA + mbase + mt * 16 + rT;
    const float sa0 = sa[ra], sa1 = sa[ra + 8];
#pragma unroll
    for (int nt = 0; nt < 4; nt++) {
      size_t c0 = rowB + nbase + nt * 8 + cT;
      const float sb0 = sb[c0], sb1 = sb[c0 + 1];
      float v0 = (65536.f * (float)acc_hi[mt][nt][0] + 256.f * (float)acc_mid[mt][nt][0]) * sa0 * sb0;
      float v1 = (65536.f * (float)acc_hi[mt][nt][1] + 256.f * (float)acc_mid[mt][nt][1]) * sa0 * sb1;
      float v2 = (65536.f * (float)acc_hi[mt][nt][2] + 256.f * (float)acc_mid[mt][nt][2]) * sa1 * sb0;
      float v3 = (65536.f * (float)acc_hi[mt][nt][3] + 256.f * (float)acc_mid[mt][nt][3]) * sa1 * sb1;
      if (relu) {
        v0 = fmaxf(v0, 0.f); v1 = fmaxf(v1, 0.f);
        v2 = fmaxf(v2, 0.f); v3 = fmaxf(v3, 0.f);
      }
      if (mode == 0) {
        *(float2*)(Cf + ra * N + c0)       = make_float2(v0, v1);
        *(float2*)(Cf + (ra + 8) * N + c0) = make_float2(v2, v3);
      } else {
        __nv_bfloat16 h0 = __float2bfloat16(v0), h1 = __float2bfloat16(v1);
        __nv_bfloat16 h2 = __float2bfloat16(v2), h3 = __float2bfloat16(v3);
        *(__nv_bfloat162*)(CH + ra * N + c0)       = __nv_bfloat162(h0, h1);
        *(__nv_bfloat162*)(CH + (ra + 8) * N + c0) = __nv_bfloat162(h2, h3);
        *(__nv_bfloat162*)(CL + ra * N + c0) = __nv_bfloat162(
            __float2bfloat16(v0 - __bfloat162float(h0)),
            __float2bfloat16(v1 - __bfloat162float(h1)));
        *(__nv_bfloat162*)(CL + (ra + 8) * N + c0) = __nv_bfloat162(
            __float2bfloat16(v2 - __bfloat162float(h2)),
            __float2bfloat16(v3 - __bfloat162float(h3)));
      }
    }
  }
}

__global__ void __launch_bounds__(256, 1) gemm_i8(
    const char* __restrict__ Ah, const char* __restrict__ Al,
    const float* __restrict__ sa,
    const char* __restrict__ Bh, const char* __restrict__ Bl,
    const float* __restrict__ sb,
    float* __restrict__ Cf, __nv_bfloat16* __restrict__ CH,
    __nv_bfloat16* __restrict__ CL, int K, int N, int relu, int mode) {
  extern __shared__ char smem[];
  gemm_i8_body(Ah, Al, sa, Bh, Bl, sb, Cf, CH, CL, K, N, relu, mode,
               smem, blockIdx.x, blockIdx.y);
}

// fused QKV: z=0 -> Q (bf16 pair), z=1 -> K (bf16 pair), z=2 -> V (fp32)
__global__ void __launch_bounds__(256, 1) qkv_i8(
    const char* __restrict__ x8h, const char* __restrict__ x8l,
    const float* __restrict__ sx,
    const char* __restrict__ wq8h, const char* __restrict__ wq8l, const float* __restrict__ swq,
    const char* __restrict__ wk8h, const char* __restrict__ wk8l, const float* __restrict__ swk,
    const char* __restrict__ wv8h, const char* __restrict__ wv8l, const float* __restrict__ swv,
    __nv_bfloat16* __restrict__ qh, __nv_bfloat16* __restrict__ ql,
    __nv_bfloat16* __restrict__ kh, __nv_bfloat16* __restrict__ kl,
    float* __restrict__ v) {
  extern __shared__ char smem[];
  const int z = blockIdx.z;
  const char* Bh = (z == 0) ? wq8h : (z == 1) ? wk8h : wv8h;
  const char* Bl = (z == 0) ? wq8l : (z == 1) ? wk8l : wv8l;
  const float* sb = (z == 0) ? swq : (z == 1) ? swk : swv;
  __nv_bfloat16* CH = (z == 0) ? qh : kh;
  __nv_bfloat16* CL = (z == 0) ? ql : kl;
  gemm_i8_body(x8h, x8l, sx, Bh, Bl, sb,
               (z == 2) ? v : nullptr, CH, CL, DM, DM, 0, (z == 2) ? 0 : 1,
               smem, blockIdx.x, blockIdx.y);
}

// ================= weight preprocessing ====================================
// colmax: sb[n] = max_k |W[k,n]| / 32512
__global__ void __launch_bounds__(256) colmax_kernel(
    const float* __restrict__ W, float* __restrict__ sb, int K, int N) {
  int n = blockIdx.x * 256 + threadIdx.x;
  if (n >= N) return;
  float m = 0.f;
  for (int k = 0; k < K; k++) m = fmaxf(m, fabsf(W[(size_t)k * N + n]));
  sb[n] = m * (1.0f / 32512.0f);
}

// transpose + int16->2xint8 quantize: W[K,N] -> T8[N,K]
__global__ void __launch_bounds__(256) transpose_quant(
    const float* __restrict__ W, const float* __restrict__ sb,
    char* __restrict__ Th, char* __restrict__ Tl, int K, int N) {
  __shared__ float t[32][33];
  const int n0 = blockIdx.x * 32, k0 = blockIdx.y * 32;
  const int tx = threadIdx.x & 31, ty = threadIdx.x >> 5;  // 32x8
#pragma unroll
  for (int i = 0; i < 4; i++)
    t[ty + i * 8][tx] = W[(size_t)(k0 + ty + i * 8) * N + n0 + tx];
  __syncthreads();
#pragma unroll
  for (int i = 0; i < 4; i++) {
    int n = n0 + ty + i * 8, k = k0 + tx;
    float s = sb[n];
    float inv = (s > 0.f) ? 1.0f / s : 0.f;
    char qh, ql;
    quant16(t[tx][ty + i * 8], inv, qh, ql);
    Th[(size_t)n * K + k] = qh;
    Tl[(size_t)n * K + k] = ql;
  }
}

// ================= per-row activation quantize =============================
__global__ void __launch_bounds__(256) quant_rows(
    const float* __restrict__ src, char* __restrict__ qh8,
    char* __restrict__ ql8, float* __restrict__ scale, int K) {
  const int row = blockIdx.x, tid = threadIdx.x;
  const float* r = src + (size_t)row * K;
  float m = 0.f;
  for (int j = tid * 4; j < K; j += 1024) {
    float4 v = *(const float4*)(r + j);
    m = fmaxf(m, fmaxf(fmaxf(fabsf(v.x), fabsf(v.y)), fmaxf(fabsf(v.z), fabsf(v.w))));
  }
  __shared__ float red[8];
  __shared__ float s_inv, s_val;
#pragma unroll
  for (int off = 16; off > 0; off >>= 1)
    m = fmaxf(m, __shfl_xor_sync(0xFFFFFFFFu, m, off));
  if ((tid & 31) == 0) red[tid >> 5] = m;
  __syncthreads();
  if (tid == 0) {
    float mm = 0.f;
#pragma unroll
    for (int i = 0; i < 8; i++) mm = fmaxf(mm, red[i]);
    s_val = mm * (1.0f / 32512.0f);
    s_inv = (mm > 0.f) ? 32512.0f / mm : 0.f;
    scale[row] = s_val;
  }
  __syncthreads();
  const float inv = s_inv;
  for (int j = tid * 4; j < K; j += 1024) {
    float4 v = *(const float4*)(r + j);
    char h[4], l[4];
    quant16(v.x, inv, h[0], l[0]);
    quant16(v.y, inv, h[1], l[1]);
    quant16(v.z, inv, h[2], l[2]);
    quant16(v.w, inv, h[3], l[3]);
    *(uint32_t*)(qh8 + (size_t)row * K + j) = *(uint32_t*)h;
    *(uint32_t*)(ql8 + (size_t)row * K + j) = *(uint32_t*)l;
  }
}

// ================= V split-transpose: v[row, h*64+d] -> vt[(bh*64+d), l] ===
__global__ void __launch_bounds__(256) vtrans_kernel(
    const float* __restrict__ v, __nv_bfloat16* __restrict__ vth,
    __nv_bfloat16* __restrict__ vtl) {
  __shared__ float t[32][33];
  const int bh = blockIdx.z;                 // b*16+h
  const int l0 = blockIdx.x * 32, d0 = blockIdx.y * 32;
  const int tx = threadIdx.x & 31, ty = threadIdx.x >> 5;
  const int b = bh >> 4, h = bh & 15;
#pragma unroll
  for (int i = 0; i < 4; i++)
    t[ty + i * 8][tx] =
        v[((size_t)b * LSEQ + l0 + ty + i * 8) * DM + h * DKH + d0 + tx];
  __syncthreads();
#pragma unroll
  for (int i = 0; i < 4; i++) {
    int d = d0 + ty + i * 8, l = l0 + tx;
    float val = t[tx][ty + i * 8];
    __nv_bfloat16 hh = __float2bfloat16(val);
    size_t o = ((size_t)bh * DKH + d) * LSEQ + l;
    vth[o] = hh;
    vtl[o] = __float2bfloat16(val - __bfloat162float(hh));
  }
}

// ================= embedding + PE (emits fp32 + int8 split) ================
__global__ void __launch_bounds__(256) embed_kernel(
    const int* __restrict__ toks, const float* __restrict__ emb,
    const float* __restrict__ pe, float* __restrict__ X,
    char* __restrict__ x8h, char* __restrict__ x8l, float* __restrict__ sx) {
  int row = blockIdx.x;
  int l   = row & (LSEQ - 1);
  int tok = toks[row];
  const float4* e = (const float4*)(emb + (size_t)tok * DM);
  const float4* p = (const float4*)(pe  + (size_t)l   * DM);
  int t = threadIdx.x;
  float4 a = e[t], b = p[t];
  float4 v = make_float4(a.x + b.x, a.y + b.y, a.z + b.z, a.w + b.w);
  ((float4*)(X + (size_t)row * DM))[t] = v;
  float m = fmaxf(fmaxf(fabsf(v.x), fabsf(v.y)), fmaxf(fabsf(v.z), fabsf(v.w)));
  __shared__ float red[8];
  __shared__ float s_inv;
#pragma unroll
  for (int off = 16; off > 0; off >>= 1)
    m = fmaxf(m, __shfl_xor_sync(0xFFFFFFFFu, m, off));
  if ((t & 31) == 0) red[t >> 5] = m;
  __syncthreads();
  if (t == 0) {
    float mm = 0.f;
#pragma unroll
    for (int i = 0; i < 8; i++) mm = fmaxf(mm, red[i]);
    sx[row] = mm * (1.0f / 32512.0f);
    s_inv = (mm > 0.f) ? 32512.0f / mm : 0.f;
  }
  __syncthreads();
  const float inv = s_inv;
  char h[4], lo[4];
  quant16(v.x, inv, h[0], lo[0]);
  quant16(v.y, inv, h[1], lo[1]);
  quant16(v.z, inv, h[2], lo[2]);
  quant16(v.w, inv, h[3], lo[3]);
  *(uint32_t*)(x8h + (size_t)row * DM + t * 4) = *(uint32_t*)h;
  *(uint32_t*)(x8l + (size_t)row * DM + t * 4) = *(uint32_t*)lo;
}

// ================= HMMA fused attention (bf16 3-term, fp32 ctx out) ========
#define PP 1028
#define ATT_PROBS_B (32 * PP * 4)        // 131584
#define ATT_Q_B     8192
#define ATT_MASK_B  4096
#define ATT_CHUNK_B 65536
#define ATT_SMEM (ATT_PROBS_B + ATT_Q_B + ATT_MASK_B + ATT_CHUNK_B)

__global__ void __launch_bounds__(256, 1) attn_mma(
    const __nv_bfloat16* __restrict__ qh, const __nv_bfloat16* __restrict__ ql,
    const __nv_bfloat16* __restrict__ kh, const __nv_bfloat16* __restrict__ kl,
    const __nv_bfloat16* __restrict__ vth, const __nv_bfloat16* __restrict__ vtl,
    const int* __restrict__ toks, float* __restrict__ attn_out,
    float* __restrict__ ctx) {
  extern __shared__ char asmem[];
  float* probs = (float*)asmem;
  char* qbuf   = asmem + ATT_PROBS_B;
  float* maskb = (float*)(qbuf + ATT_Q_B);
  char* chunk  = qbuf + ATT_Q_B + ATT_MASK_B;
  const uint32_t qb = smem_to_u32(qbuf);
  const uint32_t kb = smem_to_u32(chunk);

  const int b = blockIdx.z, h = blockIdx.y;
  const int q0 = blockIdx.x * 32;
  const int tid = threadIdx.x, wid = tid >> 5, lane = tid & 31;

  const int aRowOff = ((lane >> 3) & 1) * 8 + (lane & 7);
  const int aCSel   = (lane >> 4) & 1;
  const int bRowOff = ((lane >> 4) & 1) * 8 + (lane & 7);
  const int bCSel   = (lane >> 3) & 1;
  const int rT = lane >> 2, cT = (lane & 3) * 2;

#pragma unroll
  for (int i = 0; i < 2; i++) {
    int id = tid + i * 256;
    int buf = id >> 8;
    int r = (id & 255) >> 3, seg = id & 7;
    const __nv_bfloat16* src = (buf ? ql : qh)
        + ((size_t)b * LSEQ + q0 + r) * DM + h * DKH + seg * 8;
    uint4 val = *(const uint4*)src;
    *(uint4*)(qbuf + buf * 4096 + r * 128 + ((seg ^ (r & 7)) << 4)) = val;
  }
  for (int j = tid; j < LSEQ; j += 256)
    maskb[j] = (toks[b * LSEQ + j] == 0) ? -1e9f : 0.f;
  __syncthreads();

  // ---- Pass 1: scores, 4 chunks of 256 keys ----
  for (int c = 0; c < 4; c++) {
    if (c) __syncthreads();
#pragma unroll
    for (int i = 0; i < 16; i++) {
      int id = tid + i * 256;
      int buf = id >> 11;
      int sub = id & 2047;
      int r = sub >> 3, seg = sub & 7;
      const __nv_bfloat16* src = (buf ? kl : kh)
          + ((size_t)b * LSEQ + c * 256 + r) * DM + h * DKH + seg * 8;
      uint4 val = *(const uint4*)src;
      *(uint4*)(chunk + buf * 32768 + r * 128 + ((seg ^ (r & 7)) << 4)) = val;
    }
    __syncthreads();

    float acc[2][4][4];
#pragma unroll
    for (int mt = 0; mt < 2; mt++)
#pragma unroll
      for (int nt = 0; nt < 4; nt++)
#pragma unroll
        for (int e = 0; e < 4; e++) acc[mt][nt][e] = 0.f;

#pragma unroll
    for (int kk = 0; kk < 4; kk++) {
      uint32_t a_h[2][4], a_l[2][4];
#pragma unroll
      for (int mt = 0; mt < 2; mt++) {
        int row = mt * 16 + aRowOff;
        int ci  = kk * 2 + aCSel;
        uint32_t off = row * 128 + ((ci ^ (row & 7)) << 4);
        LDSM4(a_h[mt], qb + off);
        LDSM4(a_l[mt], qb + 4096 + off);
      }
      uint32_t b_h[2][4], b_l[2][4];
#pragma unroll
      for (int ng = 0; ng < 2; ng++) {
        int row = wid * 32 + ng * 16 + bRowOff;
        int ci  = kk * 2 + bCSel;
        uint32_t off = row * 128 + ((ci ^ (row & 7)) << 4);
        LDSM4(b_h[ng], kb + off);
        LDSM4(b_l[ng], kb + 32768 + off);
      }
#pragma unroll
      for (int mt = 0; mt < 2; mt++)
#pragma unroll
        for (int nt = 0; nt < 4; nt++) {
          const int ng = nt >> 1, j = (nt & 1) * 2;
          MMA16816(acc[mt][nt], a_h[mt], b_h[ng][j], b_h[ng][j + 1]);
          MMA16816(acc[mt][nt], a_h[mt], b_l[ng][j], b_l[ng][j + 1]);
          MMA16816(acc[mt][nt], a_l[mt], b_h[ng][j], b_h[ng][j + 1]);
        }
    }
#pragma unroll
    for (int mt = 0; mt < 2; mt++)
#pragma unroll
      for (int nt = 0; nt < 4; nt++) {
        int col = c * 256 + wid * 32 + nt * 8 + cT;
        float b0 = maskb[col], b1 = maskb[col + 1];
        int r0 = mt * 16 + rT;
        probs[r0 * PP + col]           = acc[mt][nt][0] * 0.125f + b0;
        probs[r0 * PP + col + 1]       = acc[mt][nt][1] * 0.125f + b1;
        probs[(r0 + 8) * PP + col]     = acc[mt][nt][2] * 0.125f + b0;
        probs[(r0 + 8) * PP + col + 1] = acc[mt][nt][3] * 0.125f + b1;
      }
  }
  __syncthreads();

  // ---- Pass 2: softmax ----
#pragma unroll
  for (int rr = 0; rr < 4; rr++) {
    int r = wid + rr * 8;
    float* pr = &probs[r * PP];
    float m = -1e30f;
    for (int j = lane; j < LSEQ; j += 32) m = fmaxf(m, pr[j]);
#pragma unroll
    for (int off = 16; off > 0; off >>= 1)
      m = fmaxf(m, __shfl_xor_sync(0xFFFFFFFFu, m, off));
    float s = 0.f;
    for (int j = lane; j < LSEQ; j += 32) {
      float e = __expf(pr[j] - m);
      pr[j] = e; s += e;
    }
#pragma unroll
    for (int off = 16; off > 0; off >>= 1)
      s += __shfl_xor_sync(0xFFFFFFFFu, s, off);
    float inv = 1.0f / s;
    if (attn_out) {
      float* ao = attn_out + ((size_t)(b * NH + h) * LSEQ + q0 + r) * LSEQ;
      for (int j = lane; j < LSEQ; j += 32) {
        float p = pr[j] * inv; pr[j] = p; ao[j] = p;
      }
    } else {
      for (int j = lane; j < LSEQ; j += 32) pr[j] *= inv;
    }
  }

  // ---- Pass 3: ctx = P @ V, 8 chunks of 128 keys ----
  const uint32_t pb = kb;
  const uint32_t vb = kb + 16384;
  const int mt_w = wid >> 2;
  const int ng_w = wid & 3;
  float cacc[2][4] = {};
  for (int c = 0; c < 8; c++) {
    __syncthreads();
#pragma unroll
    for (int i = 0; i < 2; i++) {
      int id = tid + i * 256;
      int r = id >> 4, seg = id & 15;
      const float* pr = &probs[r * PP + c * 128 + seg * 8];
      float4 p0 = *(const float4*)pr;
      float4 p1 = *(const float4*)(pr + 4);
      __nv_bfloat16 hh[8], ll[8];
      float pv[8] = {p0.x, p0.y, p0.z, p0.w, p1.x, p1.y, p1.z, p1.w};
#pragma unroll
      for (int e = 0; e < 8; e++) {
        hh[e] = __float2bfloat16(pv[e]);
        ll[e] = __float2bfloat16(pv[e] - __bfloat162float(hh[e]));
      }
      uint32_t off = r * 256 + ((seg ^ (r & 7)) << 4);
      *(uint4*)(chunk + off)        = *(uint4*)hh;
      *(uint4*)(chunk + 8192 + off) = *(uint4*)ll;
    }
#pragma unroll
    for (int i = 0; i < 8; i++) {
      int id = tid + i * 256;
      int buf = id >> 10;
      int sub = id & 1023;
      int r = sub >> 4, seg = sub & 15;
      const __nv_bfloat16* src = (buf ? vtl : vth)
          + ((size_t)(b * NH + h) * DKH + r) * LSEQ + c * 128 + seg * 8;
      uint4 val = *(const uint4*)src;
      *(uint4*)(chunk + 16384 + buf * 16384 + r * 256 +
                ((seg ^ (r & 7)) << 4)) = val;
    }
    __syncthreads();
#pragma unroll
    for (int kk = 0; kk < 8; kk++) {
      uint32_t p_h[4], p_l[4];
      {
        int row = mt_w * 16 + aRowOff;
        int ci  = kk * 2 + aCSel;
        uint32_t off = row * 256 + ((ci ^ (row & 7)) << 4);
        LDSM4(p_h, pb + off);
        LDSM4(p_l, pb + 8192 + off);
      }
      uint32_t v_h[4], v_l[4];
      {
        int row = ng_w * 16 + bRowOff;
        int ci  = kk * 2 + bCSel;
        uint32_t off = row * 256 + ((ci ^ (row & 7)) << 4);
        LDSM4(v_h, vb + off);
        LDSM4(v_l, vb + 16384 + off);
      }
#pragma unroll
      for (int nt = 0; nt < 2; nt++) {
        const int j = nt * 2;
        MMA16816(cacc[nt], p_h, v_h[j], v_h[j + 1]);
        MMA16816(cacc[nt], p_h, v_l[j], v_l[j + 1]);
        MMA16816(cacc[nt], p_l, v_h[j], v_h[j + 1]);
      }
    }
  }
#pragma unroll
  for (int nt = 0; nt < 2; nt++) {
    size_t r0 = (size_t)b * LSEQ + q0 + mt_w * 16 + rT;
    size_t c0 = h * DKH + ng_w * 16 + nt * 8 + cT;
    *(float2*)(ctx + r0 * DM + c0)       = make_float2(cacc[nt][0], cacc[nt][1]);
    *(float2*)(ctx + (r0 + 8) * DM + c0) = make_float2(cacc[nt][2], cacc[nt][3]);
  }
}

// ================= residual add + LayerNorm (fp32 + int8 split out) ========
__global__ void __launch_bounds__(256) ln_res(
    const float* __restrict__ A, const float* __restrict__ Xin,
    float* __restrict__ Xout,
    char* __restrict__ x8h, char* __restrict__ x8l, float* __restrict__ sx) {
  const int row = blockIdx.x, t = threadIdx.x;
  const float4* a4 = (const float4*)(A + (size_t)row * DM);
  const float4* xi = (const float4*)(Xin + (size_t)row * DM);
  float4 a = a4[t], x = xi[t];
  float v0 = a.x + x.x, v1 = a.y + x.y, v2 = a.z + x.z, v3 = a.w + x.w;
  float s = v0 + v1 + v2 + v3;
  float q = v0 * v0 + v1 * v1 + v2 * v2 + v3 * v3;
#pragma unroll
  for (int off = 16; off > 0; off >>= 1) {
    s += __shfl_xor_sync(0xFFFFFFFFu, s, off);
    q += __shfl_xor_sync(0xFFFFFFFFu, q, off);
  }
  __shared__ float rs[8], rq[8], rm[8];
  __shared__ float mu_s, rstd_s, inv_s;
  int warp = t >> 5, lane = t & 31;
  if (lane == 0) { rs[warp] = s; rq[warp] = q; }
  __syncthreads();
  if (t == 0) {
    float S = 0.f, Qq = 0.f;
#pragma unroll
    for (int i = 0; i < 8; i++) { S += rs[i]; Qq += rq[i]; }
    float mu = S * (1.0f / DM);
    float var = Qq * (1.0f / DM) - mu * mu;
    mu_s = mu;
    rstd_s = rsqrtf(var + 1e-5f);
  }
  __syncthreads();
  float mu = mu_s, r = rstd_s;
  float o0 = (v0 - mu) * r, o1 = (v1 - mu) * r;
  float o2 = (v2 - mu) * r, o3 = (v3 - mu) * r;
  ((float4*)(Xout + (size_t)row * DM))[t] = make_float4(o0, o1, o2, o3);
  // row max of |o| for int16 quantization
  float m = fmaxf(fmaxf(fabsf(o0), fabsf(o1)), fmaxf(fabsf(o2), fabsf(o3)));
#pragma unroll
  for (int off = 16; off > 0; off >>= 1)
    m = fmaxf(m, __shfl_xor_sync(0xFFFFFFFFu, m, off));
  if (lane == 0) rm[warp] = m;
  __syncthreads();
  if (t == 0) {
    float mm = 0.f;
#pragma unroll
    for (int i = 0; i < 8; i++) mm = fmaxf(mm, rm[i]);
    sx[row] = mm * (1.0f / 32512.0f);
    inv_s = (mm > 0.f) ? 32512.0f / mm : 0.f;
  }
  __syncthreads();
  const float inv = inv_s;
  char h[4], lo[4];
  quant16(o0, inv, h[0], lo[0]);
  quant16(o1, inv, h[1], lo[1]);
  quant16(o2, inv, h[2], lo[2]);
  quant16(o3, inv, h[3], lo[3]);
  *(uint32_t*)(x8h + (size_t)row * DM + t * 4) = *(uint32_t*)h;
  *(uint32_t*)(x8l + (size_t)row * DM + t * 4) = *(uint32_t*)lo;
}

// ================= launcher ================================================
extern "C" void kernel_launch(void* const* d_in, const int* in_sizes, int n_in,
                              void* d_out, int out_size) {
  const int*   toks = (const int*)  d_in[0];
  const float* emb  = (const float*)d_in[1];
  const float* pe   = (const float*)d_in[2];
  const float* WQ   = (const float*)d_in[3];
  const float* WK   = (const float*)d_in[4];
  const float* WV   = (const float*)d_in[5];
  const float* WO   = (const float*)d_in[6];
  const float* W1   = (const float*)d_in[7];
  const float* W2   = (const float*)d_in[8];
  float* out = (float*)d_out;

  float *x, *tmp, *v, *ctx, *ffn;
  cudaGetSymbolAddress((void**)&x,   g_x);
  cudaGetSymbolAddress((void**)&tmp, g_tmp);
  cudaGetSymbolAddress((void**)&v,   g_v);
  cudaGetSymbolAddress((void**)&ctx, g_ctx);
  cudaGetSymbolAddress((void**)&ffn, g_ffn);

  __nv_bfloat16 *qh,*ql,*kh,*kl,*vth,*vtl;
  cudaGetSymbolAddress((void**)&qh, g_qh);  cudaGetSymbolAddress((void**)&ql, g_ql);
  cudaGetSymbolAddress((void**)&kh, g_kh);  cudaGetSymbolAddress((void**)&kl, g_kl);
  cudaGetSymbolAddress((void**)&vth, g_vth); cudaGetSymbolAddress((void**)&vtl, g_vtl);

  char *x8h,*x8l,*c8h,*c8l,*f8h,*f8l;
  float *sx,*sc,*sf;
  cudaGetSymbolAddress((void**)&x8h, g_x8h); cudaGetSymbolAddress((void**)&x8l, g_x8l);
  cudaGetSymbolAddress((void**)&c8h, g_c8h); cudaGetSymbolAddress((void**)&c8l, g_c8l);
  cudaGetSymbolAddress((void**)&f8h, g_f8h); cudaGetSymbolAddress((void**)&f8l, g_f8l);
  cudaGetSymbolAddress((void**)&sx, g_sx);   cudaGetSymbolAddress((void**)&sc, g_sc);
  cudaGetSymbolAddress((void**)&sf, g_sf);

  char *wq8h,*wq8l,*wk8h,*wk8l,*wv8h,*wv8l,*wo8h,*wo8l,*w18h,*w18l,*w28h,*w28l;
  float *swq,*swk,*swv,*swo,*sw1,*sw2;
  cudaGetSymbolAddress((void**)&wq8h, g_wq8h); cudaGetSymbolAddress((void**)&wq8l, g_wq8l);
  cudaGetSymbolAddress((void**)&wk8h, g_wk8h); cudaGetSymbolAddress((void**)&wk8l, g_wk8l);
  cudaGetSymbolAddress((void**)&wv8h, g_wv8h); cudaGetSymbolAddress((void**)&wv8l, g_wv8l);
  cudaGetSymbolAddress((void**)&wo8h, g_wo8h); cudaGetSymbolAddress((void**)&wo8l, g_wo8l);
  cudaGetSymbolAddress((void**)&w18h, g_w18h); cudaGetSymbolAddress((void**)&w18l, g_w18l);
  cudaGetSymbolAddress((void**)&w28h, g_w28h); cudaGetSymbolAddress((void**)&w28l, g_w28l);
  cudaGetSymbolAddress((void**)&swq, g_swq); cudaGetSymbolAddress((void**)&swk, g_swk);
  cudaGetSymbolAddress((void**)&swv, g_swv); cudaGetSymbolAddress((void**)&swo, g_swo);
  cudaGetSymbolAddress((void**)&sw1, g_sw1); cudaGetSymbolAddress((void**)&sw2, g_sw2);

  const size_t XE = (size_t)ROWS * DM;
  const size_t AE = (size_t)NL * B_ * NH * LSEQ * LSEQ;
  float* attn_base = ((size_t)out_size >= XE + AE) ? (out + XE) : nullptr;

  cudaFuncSetAttribute(attn_mma, cudaFuncAttributeMaxDynamicSharedMemorySize, ATT_SMEM);
  cudaFuncSetAttribute(gemm_i8, cudaFuncAttributeMaxDynamicSharedMemorySize, GEMM_SMEM);
  cudaFuncSetAttribute(qkv_i8,  cudaFuncAttributeMaxDynamicSharedMemorySize, GEMM_SMEM);

  // ---- weight preprocessing: colmax + transpose-quant ----
  for (int l = 0; l < NL; l++) {
    size_t o1 = (size_t)l * DM * DM;
    size_t o2 = (size_t)l * DM * DFF;
    colmax_kernel<<<DM/256, 256>>>(WQ + o1, swq + l*DM, DM, DM);
    colmax_kernel<<<DM/256, 256>>>(WK + o1, swk + l*DM, DM, DM);
    colmax_kernel<<<DM/256, 256>>>(WV + o1, swv + l*DM, DM, DM);
    colmax_kernel<<<DM/256, 256>>>(WO + o1, swo + l*DM, DM, DM);
    colmax_kernel<<<DFF/256, 256>>>(W1 + o2, sw1 + l*DFF, DM, DFF);
    colmax_kernel<<<DM/256, 256>>>(W2 + o2, sw2 + l*DM, DFF, DM);
    transpose_quant<<<dim3(DM/32, DM/32), 256>>>(WQ + o1, swq + l*DM, wq8h + o1, wq8l + o1, DM, DM);
    transpose_quant<<<dim3(DM/32, DM/32), 256>>>(WK + o1, swk + l*DM, wk8h + o1, wk8l + o1, DM, DM);
    transpose_quant<<<dim3(DM/32, DM/32), 256>>>(WV + o1, swv + l*DM, wv8h + o1, wv8l + o1, DM, DM);
    transpose_quant<<<dim3(DM/32, DM/32), 256>>>(WO + o1, swo + l*DM, wo8h + o1, wo8l + o1, DM, DM);
    transpose_quant<<<dim3(DFF/32, DM/32), 256>>>(W1 + o2, sw1 + l*DFF, w18h + o2, w18l + o2, DM, DFF);
    transpose_quant<<<dim3(DM/32, DFF/32), 256>>>(W2 + o2, sw2 + l*DM, w28h + o2, w28l + o2, DFF, DM);
  }

  embed_kernel<<<ROWS, 256>>>(toks, emb, pe, x, x8h, x8l, sx);

  const dim3 gProj(DM / 128, ROWS / 128);          // (8, 32)
  const dim3 gQKV (DM / 128, ROWS / 128, 3);       // fused QKV
  const dim3 gFF1 (DFF / 128, ROWS / 128);         // (32, 32)

  for (int l = 0; l < NL; l++) {
    size_t o1 = (size_t)l * DM * DM;
    size_t o2 = (size_t)l * DM * DFF;

    qkv_i8<<<gQKV, 256, GEMM_SMEM>>>(
        x8h, x8l, sx,
        wq8h + o1, wq8l + o1, swq + l*DM,
        wk8h + o1, wk8l + o1, swk + l*DM,
        wv8h + o1, wv8l + o1, swv + l*DM,
        qh, ql, kh, kl, v);
    vtrans_kernel<<<dim3(LSEQ/32, DKH/32, B_*NH), 256>>>(v, vth, vtl);

    float* ao = attn_base ? attn_base + (size_t)l * B_ * NH * LSEQ * LSEQ : nullptr;
    attn_mma<<<dim3(LSEQ/32, NH, B_), 256, ATT_SMEM>>>(
        qh, ql, kh, kl, vth, vtl, toks, ao, ctx);

    quant_rows<<<ROWS, 256>>>(ctx, c8h, c8l, sc, DM);
    gemm_i8<<<gProj, 256, GEMM_SMEM>>>(c8h, c8l, sc, wo8h + o1, wo8l + o1,
                                       swo + l*DM, tmp, nullptr, nullptr,
                                       DM, DM, 0, 0);
    ln_res<<<ROWS, 256>>>(tmp, x, x, x8h, x8l, sx);

    gemm_i8<<<gFF1, 256, GEMM_SMEM>>>(x8h, x8l, sx, w18h + o2, w18l + o2,
                                      sw1 + l*DFF, ffn, nullptr, nullptr,
                                      DM, DFF, 1, 0);
    quant_rows<<<ROWS, 256>>>(ffn, f8h, f8l, sf, DFF);
    gemm_i8<<<gProj, 256, GEMM_SMEM>>>(f8h, f8l, sf, w28h + o2, w28l + o2,
                                       sw2 + l*DM, tmp, nullptr, nullptr,
                                       DFF, DM, 0, 0);
    float* xdst = (l == NL - 1) ? out : x;
    ln_res<<<ROWS, 256>>>(tmp, x, xdst, x8h, x8l, sx);
  }
}

// round 13
// speedup vs baseline: 3.1504x; 3.1504x over previous
#include <cuda_runtime.h>
#include <cuda_fp16.h>
#include <cstdint>
#include <math.h>

#define B_   4
#define LSEQ 1024
#define DM   1024
#define NH   16
#define DKH  64
#define DFF  4096
#define NL   2
#define ROWS (B_*LSEQ)   // 4096

// ================= scratch (device globals: allocation-guard safe) =========
__device__ float g_x  [ROWS*DM];
__device__ float g_tmp[ROWS*DM];
__device__ float g_v  [ROWS*DM];
// fp16 hi/lo activation pairs
__device__ __half g_xh[ROWS*DM],  g_xl[ROWS*DM];
__device__ __half g_qh[ROWS*DM],  g_ql[ROWS*DM];
__device__ __half g_kh[ROWS*DM],  g_kl[ROWS*DM];
__device__ __half g_vth[ROWS*DM], g_vtl[ROWS*DM];
__device__ __half g_ch[ROWS*DM],  g_cl[ROWS*DM];
__device__ __half g_fh[(size_t)ROWS*DFF], g_fl[(size_t)ROWS*DFF];
// fp16 hi/lo weights, pre-transposed to [N,K]
__device__ __half g_wqh[NL*DM*DM], g_wql[NL*DM*DM];
__device__ __half g_wkh[NL*DM*DM], g_wkl[NL*DM*DM];
__device__ __half g_wvh[NL*DM*DM], g_wvl[NL*DM*DM];
__device__ __half g_woh[NL*DM*DM], g_wol[NL*DM*DM];
__device__ __half g_w1h[(size_t)NL*DM*DFF], g_w1l[(size_t)NL*DM*DFF];
__device__ __half g_w2h[(size_t)NL*DM*DFF], g_w2l[(size_t)NL*DM*DFF];

// ================= PTX helpers (sm_80-baseline; no tcgen05) ================
#define CP_ASYNC16(smem, gptr) \
  asm volatile("cp.async.cg.shared.global [%0], [%1], 16;" \
               :: "r"(smem), "l"(gptr))
#define CP_COMMIT() asm volatile("cp.async.commit_group;" ::: "memory")
#define CP_WAIT1()  asm volatile("cp.async.wait_group 1;" ::: "memory")

#define LDSM4(r, addr) \
  asm volatile("ldmatrix.sync.aligned.m8n8.x4.shared.b16 {%0,%1,%2,%3}, [%4];" \
    : "=r"((r)[0]), "=r"((r)[1]), "=r"((r)[2]), "=r"((r)[3]) : "r"(addr))

#define MMAF16(d, a, b0v, b1v) \
  asm volatile("mma.sync.aligned.m16n8k16.row.col.f32.f16.f16.f32 " \
    "{%0,%1,%2,%3}, {%4,%5,%6,%7}, {%8,%9}, {%0,%1,%2,%3};" \
    : "+f"((d)[0]), "+f"((d)[1]), "+f"((d)[2]), "+f"((d)[3]) \
    : "r"((a)[0]), "r"((a)[1]), "r"((a)[2]), "r"((a)[3]), "r"(b0v), "r"(b1v))

__device__ __forceinline__ uint32_t smem_to_u32(const void* p) {
  uint32_t a;
  asm("{ .reg .u64 t; cvta.to.shared.u64 t, %1; cvt.u32.u64 %0, t; }"
      : "=r"(a) : "l"(p));
  return a;
}

__device__ __forceinline__ void split_h(float v, __half& h, __half& l) {
  h = __float2half_rn(v);
  l = __float2half_rn(v - __half2float(h));
}

// ================= fp16 split GEMM: C = A[M,K] @ Bt[N,K]^T =================
// NTERMS=3: C = Ah*Bh + Ah*Bl + Al*Bh  (err ~2^-22)  [QKV]
// NTERMS=2: C = Ah*Bh + Al*Bh          (err ~2^-11)  [WO/FF]
// CTA tile 128x128, BK=64 fp16 (128B rows), cp.async pipeline, 8 warps.
// modes: 0 = fp32 out, 1 = half-pair out, 2 = half-pair out + relu
#define MATB 16384                       // 128 rows x 128 bytes

template<int NTERMS, int NSTAGE>
__device__ __forceinline__ void load_stage_h(
    uint32_t sbase, const __half* Ah, const __half* Al,
    const __half* Bh, const __half* Bl,
    size_t rowA, size_t rowB, int K, int kc, int tid) {
  const int NM = NTERMS + 1;             // 3 or 4 matrices
#pragma unroll
  for (int i = 0; i < NM * 4; i++) {
    int idx = tid + i * 256;
    int mat = idx >> 10;                 // constant per i
    int sub = idx & 1023;
    int row = sub >> 3, seg = sub & 7;
    const __half* base = (mat == 0) ? Ah : (mat == 1) ? Al
                       : (mat == 2) ? Bh : Bl;
    size_t r0 = (mat < 2) ? rowA : rowB;
    const __half* g = base + (r0 + row) * (size_t)K + (size_t)kc * 64 + seg * 8;
    uint32_t s = sbase + mat * MATB + row * 128 + ((seg ^ (row & 7)) << 4);
    CP_ASYNC16(s, g);
  }
}

template<int NTERMS, int NSTAGE>
__device__ __forceinline__ void gemm_h_body(
    const __half* Ah, const __half* Al,
    const __half* Bh, const __half* Bl,
    float* Cf, __half* CH, __half* CL,
    int K, int N, int mode, char* smem, int bx, int by) {
  const uint32_t sbm = smem_to_u32(smem);
  const int STAGEB = (NTERMS + 1) * MATB;
  const int tid = threadIdx.x, wid = tid >> 5, lane = tid & 31;

  const size_t rowA = (size_t)by * 128;
  const size_t rowB = (size_t)bx * 128;
  const int nch = K / 64;

  const int mbase = (wid >> 2) * 64;
  const int nbase = (wid & 3) * 32;

  const int aRowOff = ((lane >> 3) & 1) * 8 + (lane & 7);
  const int aCSel   = (lane >> 4) & 1;
  const int bRowOff = ((lane >> 4) & 1) * 8 + (lane & 7);
  const int bCSel   = (lane >> 3) & 1;

  float acc[4][4][4];
#pragma unroll
  for (int mt = 0; mt < 4; mt++)
#pragma unroll
    for (int nt = 0; nt < 4; nt++)
#pragma unroll
      for (int e = 0; e < 4; e++) acc[mt][nt][e] = 0.f;

#pragma unroll
  for (int s = 0; s < NSTAGE - 1; s++) {
    load_stage_h<NTERMS, NSTAGE>(sbm + s * STAGEB, Ah, Al, Bh, Bl,
                                 rowA, rowB, K, s, tid);
    CP_COMMIT();
  }

  for (int kc = 0; kc < nch; kc++) {
    if (NSTAGE == 2) {
      if (kc + 1 < nch)
        load_stage_h<NTERMS, NSTAGE>(sbm + ((kc + 1) & 1) * STAGEB,
                                     Ah, Al, Bh, Bl, rowA, rowB, K, kc + 1, tid);
      CP_COMMIT();
      CP_WAIT1();
      __syncthreads();
    } else {
      CP_WAIT1();
      __syncthreads();
      if (kc + NSTAGE - 1 < nch)
        load_stage_h<NTERMS, NSTAGE>(sbm + ((kc + NSTAGE - 1) % NSTAGE) * STAGEB,
                                     Ah, Al, Bh, Bl, rowA, rowB, K,
                                     kc + NSTAGE - 1, tid);
      CP_COMMIT();
    }

    const uint32_t bufA_h = sbm + (kc % NSTAGE) * STAGEB;
    const uint32_t bufA_l = bufA_h + MATB;
    const uint32_t bufB_h = bufA_h + 2 * MATB;
    const uint32_t bufB_l = bufA_h + 3 * MATB;

#pragma unroll
    for (int kk = 0; kk < 4; kk++) {
      uint32_t a_h[4][4], a_l[4][4];
#pragma unroll
      for (int mt = 0; mt < 4; mt++) {
        int row = mbase + mt * 16 + aRowOff;
        int ci  = kk * 2 + aCSel;
        uint32_t off = row * 128 + ((ci ^ (row & 7)) << 4);
        LDSM4(a_h[mt], bufA_h + off);
        LDSM4(a_l[mt], bufA_l + off);
      }
      uint32_t b_h[2][4], b_l[2][4];
#pragma unroll
      for (int ng = 0; ng < 2; ng++) {
        int row = nbase + ng * 16 + bRowOff;
        int ci  = kk * 2 + bCSel;
        uint32_t off = row * 128 + ((ci ^ (row & 7)) << 4);
        LDSM4(b_h[ng], bufB_h + off);
        if (NTERMS == 3) LDSM4(b_l[ng], bufB_l + off);
      }
#pragma unroll
      for (int mt = 0; mt < 4; mt++)
#pragma unroll
        for (int nt = 0; nt < 4; nt++) {
          const int ng = nt >> 1, j = (nt & 1) * 2;
          MMAF16(acc[mt][nt], a_h[mt], b_h[ng][j], b_h[ng][j + 1]);
          MMAF16(acc[mt][nt], a_l[mt], b_h[ng][j], b_h[ng][j + 1]);
          if (NTERMS == 3)
            MMAF16(acc[mt][nt], a_h[mt], b_l[ng][j], b_l[ng][j + 1]);
        }
    }
    __syncthreads();
  }

  const int rT = lane >> 2, cT = (lane & 3) * 2;
#pragma unroll
  for (int mt = 0; mt < 4; mt++) {
#pragma unroll
    for (int nt = 0; nt < 4; nt++) {
      size_t r0 = rowA + mbase + mt * 16 + rT;
      size_t c0 = rowB + nbase + nt * 8 + cT;
      float v0 = acc[mt][nt][0], v1 = acc[mt][nt][1];
      float v2 = acc[mt][nt][2], v3 = acc[mt][nt][3];
      if (mode == 2) {
        v0 = fmaxf(v0, 0.f); v1 = fmaxf(v1, 0.f);
        v2 = fmaxf(v2, 0.f); v3 = fmaxf(v3, 0.f);
      }
      if (mode == 0) {
        *(float2*)(Cf + r0 * N + c0)       = make_float2(v0, v1);
        *(float2*)(Cf + (r0 + 8) * N + c0) = make_float2(v2, v3);
      } else {
        __half h0, h1, h2, h3, l0, l1, l2, l3;
        split_h(v0, h0, l0); split_h(v1, h1, l1);
        split_h(v2, h2, l2); split_h(v3, h3, l3);
        *(__half2*)(CH + r0 * N + c0)       = __halves2half2(h0, h1);
        *(__half2*)(CH + (r0 + 8) * N + c0) = __halves2half2(h2, h3);
        *(__half2*)(CL + r0 * N + c0)       = __halves2half2(l0, l1);
        *(__half2*)(CL + (r0 + 8) * N + c0) = __halves2half2(l2, l3);
      }
    }
  }
}

#define GEMM_SMEM3 (3 * 4 * MATB)   // 196608 (3-term, 3 stages, occ 1)
#define GEMM_SMEM2 (2 * 3 * MATB)   // 98304  (2-term, 2 stages, occ 2)

// fused QKV (3-term): z=0 -> Q pair, z=1 -> K pair, z=2 -> V fp32
__global__ void __launch_bounds__(256, 1) qkv_h(
    const __half* __restrict__ xh, const __half* __restrict__ xl,
    const __half* __restrict__ wqh, const __half* __restrict__ wql,
    const __half* __restrict__ wkh, const __half* __restrict__ wkl,
    const __half* __restrict__ wvh, const __half* __restrict__ wvl,
    __half* __restrict__ qh, __half* __restrict__ ql,
    __half* __restrict__ kh, __half* __restrict__ kl,
    float* __restrict__ v) {
  extern __shared__ char smem[];
  const int z = blockIdx.z;
  const __half* Bh = (z == 0) ? wqh : (z == 1) ? wkh : wvh;
  const __half* Bl = (z == 0) ? wql : (z == 1) ? wkl : wvl;
  __half* CH = (z == 0) ? qh : kh;
  __half* CL = (z == 0) ? ql : kl;
  gemm_h_body<3, 3>(xh, xl, Bh, Bl, (z == 2) ? v : nullptr, CH, CL,
                    DM, DM, (z == 2) ? 0 : 1, smem, blockIdx.x, blockIdx.y);
}

// 2-term GEMM (WO / FF1 / FF2), occupancy 2
__global__ void __launch_bounds__(256, 2) gemm2_h(
    const __half* __restrict__ Ah, const __half* __restrict__ Al,
    const __half* __restrict__ Bh,
    float* __restrict__ Cf, __half* __restrict__ CH, __half* __restrict__ CL,
    int K, int N, int mode) {
  extern __shared__ char smem[];
  gemm_h_body<2, 2>(Ah, Al, Bh, nullptr, Cf, CH, CL, K, N, mode,
                    smem, blockIdx.x, blockIdx.y);
}

// ================= weight transpose + fp16 hi/lo: W[K,N] -> T[N,K] =========
__global__ void __launch_bounds__(256) transpose_split_h(
    const float* __restrict__ W, __half* __restrict__ Th,
    __half* __restrict__ Tl, int K, int N) {
  __shared__ float t[32][33];
  const int n0 = blockIdx.x * 32, k0 = blockIdx.y * 32;
  const int tx = threadIdx.x & 31, ty = threadIdx.x >> 5;
#pragma unroll
  for (int i = 0; i < 4; i++)
    t[ty + i * 8][tx] = W[(size_t)(k0 + ty + i * 8) * N + n0 + tx];
  __syncthreads();
#pragma unroll
  for (int i = 0; i < 4; i++) {
    int n = n0 + ty + i * 8, k = k0 + tx;
    __half h, l;
    split_h(t[tx][ty + i * 8], h, l);
    Th[(size_t)n * K + k] = h;
    Tl[(size_t)n * K + k] = l;
  }
}

// ================= V split-transpose: v[row, h*64+d] -> vt[(bh*64+d), l] ===
__global__ void __launch_bounds__(256) vtrans_kernel(
    const float* __restrict__ v, __half* __restrict__ vth,
    __half* __restrict__ vtl) {
  __shared__ float t[32][33];
  const int bh = blockIdx.z;
  const int l0 = blockIdx.x * 32, d0 = blockIdx.y * 32;
  const int tx = threadIdx.x & 31, ty = threadIdx.x >> 5;
  const int b = bh >> 4, h = bh & 15;
#pragma unroll
  for (int i = 0; i < 4; i++)
    t[ty + i * 8][tx] =
        v[((size_t)b * LSEQ + l0 + ty + i * 8) * DM + h * DKH + d0 + tx];
  __syncthreads();
#pragma unroll
  for (int i = 0; i < 4; i++) {
    int d = d0 + ty + i * 8, l = l0 + tx;
    __half hh, ll;
    split_h(t[tx][ty + i * 8], hh, ll);
    size_t o = ((size_t)bh * DKH + d) * LSEQ + l;
    vth[o] = hh;
    vtl[o] = ll;
  }
}

// ================= embedding + PE (fp32 + fp16 pair out) ===================
__global__ void __launch_bounds__(256) embed_kernel(
    const int* __restrict__ toks, const float* __restrict__ emb,
    const float* __restrict__ pe, float* __restrict__ X,
    __half* __restrict__ XH, __half* __restrict__ XL) {
  int row = blockIdx.x;
  int l   = row & (LSEQ - 1);
  int tok = toks[row];
  const float4* e = (const float4*)(emb + (size_t)tok * DM);
  const float4* p = (const float4*)(pe  + (size_t)l   * DM);
  int t = threadIdx.x;
  float4 a = e[t], b = p[t];
  float4 v = make_float4(a.x + b.x, a.y + b.y, a.z + b.z, a.w + b.w);
  ((float4*)(X + (size_t)row * DM))[t] = v;
  __half h0, h1, h2, h3, l0, l1, l2, l3;
  split_h(v.x, h0, l0); split_h(v.y, h1, l1);
  split_h(v.z, h2, l2); split_h(v.w, h3, l3);
  __half2* H = (__half2*)(XH + (size_t)row * DM);
  __half2* L = (__half2*)(XL + (size_t)row * DM);
  H[2 * t]     = __halves2half2(h0, h1);
  H[2 * t + 1] = __halves2half2(h2, h3);
  L[2 * t]     = __halves2half2(l0, l1);
  L[2 * t + 1] = __halves2half2(l2, l3);
}

// ================= fp16 HMMA fused attention (3-term) ======================
#define PP 1028
#define ATT_PROBS_B (32 * PP * 4)        // 131584
#define ATT_Q_B     8192
#define ATT_MASK_B  4096
#define ATT_CHUNK_B 65536
#define ATT_SMEM (ATT_PROBS_B + ATT_Q_B + ATT_MASK_B + ATT_CHUNK_B)

__global__ void __launch_bounds__(256, 1) attn_mma(
    const __half* __restrict__ qh, const __half* __restrict__ ql,
    const __half* __restrict__ kh, const __half* __restrict__ kl,
    const __half* __restrict__ vth, const __half* __restrict__ vtl,
    const int* __restrict__ toks, float* __restrict__ attn_out,
    __half* __restrict__ ch, __half* __restrict__ cl) {
  extern __shared__ char asmem[];
  float* probs = (float*)asmem;
  char* qbuf   = asmem + ATT_PROBS_B;
  float* maskb = (float*)(qbuf + ATT_Q_B);
  char* chunk  = qbuf + ATT_Q_B + ATT_MASK_B;
  const uint32_t qb = smem_to_u32(qbuf);
  const uint32_t kb = smem_to_u32(chunk);

  const int b = blockIdx.z, h = blockIdx.y;
  const int q0 = blockIdx.x * 32;
  const int tid = threadIdx.x, wid = tid >> 5, lane = tid & 31;

  const int aRowOff = ((lane >> 3) & 1) * 8 + (lane & 7);
  const int aCSel   = (lane >> 4) & 1;
  const int bRowOff = ((lane >> 4) & 1) * 8 + (lane & 7);
  const int bCSel   = (lane >> 3) & 1;
  const int rT = lane >> 2, cT = (lane & 3) * 2;

#pragma unroll
  for (int i = 0; i < 2; i++) {
    int id = tid + i * 256;
    int buf = id >> 8;
    int r = (id & 255) >> 3, seg = id & 7;
    const __half* src = (buf ? ql : qh)
        + ((size_t)b * LSEQ + q0 + r) * DM + h * DKH + seg * 8;
    uint4 val = *(const uint4*)src;
    *(uint4*)(qbuf + buf * 4096 + r * 128 + ((seg ^ (r & 7)) << 4)) = val;
  }
  for (int j = tid; j < LSEQ; j += 256)
    maskb[j] = (toks[b * LSEQ + j] == 0) ? -1e9f : 0.f;
  __syncthreads();

  // ---- Pass 1: scores, 4 chunks of 256 keys ----
  for (int c = 0; c < 4; c++) {
    if (c) __syncthreads();
#pragma unroll
    for (int i = 0; i < 16; i++) {
      int id = tid + i * 256;
      int buf = id >> 11;
      int sub = id & 2047;
      int r = sub >> 3, seg = sub & 7;
      const __half* src = (buf ? kl : kh)
          + ((size_t)b * LSEQ + c * 256 + r) * DM + h * DKH + seg * 8;
      uint4 val = *(const uint4*)src;
      *(uint4*)(chunk + buf * 32768 + r * 128 + ((seg ^ (r & 7)) << 4)) = val;
    }
    __syncthreads();

    float acc[2][4][4];
#pragma unroll
    for (int mt = 0; mt < 2; mt++)
#pragma unroll
      for (int nt = 0; nt < 4; nt++)
#pragma unroll
        for (int e = 0; e < 4; e++) acc[mt][nt][e] = 0.f;

#pragma unroll
    for (int kk = 0; kk < 4; kk++) {
      uint32_t a_h[2][4], a_l[2][4];
#pragma unroll
      for (int mt = 0; mt < 2; mt++) {
        int row = mt * 16 + aRowOff;
        int ci  = kk * 2 + aCSel;
        uint32_t off = row * 128 + ((ci ^ (row & 7)) << 4);
        LDSM4(a_h[mt], qb + off);
        LDSM4(a_l[mt], qb + 4096 + off);
      }
      uint32_t b_h[2][4], b_l[2][4];
#pragma unroll
      for (int ng = 0; ng < 2; ng++) {
        int row = wid * 32 + ng * 16 + bRowOff;
        int ci  = kk * 2 + bCSel;
        uint32_t off = row * 128 + ((ci ^ (row & 7)) << 4);
        LDSM4(b_h[ng], kb + off);
        LDSM4(b_l[ng], kb + 32768 + off);
      }
#pragma unroll
      for (int mt = 0; mt < 2; mt++)
#pragma unroll
        for (int nt = 0; nt < 4; nt++) {
          const int ng = nt >> 1, j = (nt & 1) * 2;
          MMAF16(acc[mt][nt], a_h[mt], b_h[ng][j], b_h[ng][j + 1]);
          MMAF16(acc[mt][nt], a_h[mt], b_l[ng][j], b_l[ng][j + 1]);
          MMAF16(acc[mt][nt], a_l[mt], b_h[ng][j], b_h[ng][j + 1]);
        }
    }
#pragma unroll
    for (int mt = 0; mt < 2; mt++)
#pragma unroll
      for (int nt = 0; nt < 4; nt++) {
        int col = c * 256 + wid * 32 + nt * 8 + cT;
        float b0 = maskb[col], b1 = maskb[col + 1];
        int r0 = mt * 16 + rT;
        probs[r0 * PP + col]           = acc[mt][nt][0] * 0.125f + b0;
        probs[r0 * PP + col + 1]       = acc[mt][nt][1] * 0.125f + b1;
        probs[(r0 + 8) * PP + col]     = acc[mt][nt][2] * 0.125f + b0;
        probs[(r0 + 8) * PP + col + 1] = acc[mt][nt][3] * 0.125f + b1;
      }
  }
  __syncthreads();

  // ---- Pass 2: softmax ----
#pragma unroll
  for (int rr = 0; rr < 4; rr++) {
    int r = wid + rr * 8;
    float* pr = &probs[r * PP];
    float m = -1e30f;
    for (int j = lane; j < LSEQ; j += 32) m = fmaxf(m, pr[j]);
#pragma unroll
    for (int off = 16; off > 0; off >>= 1)
      m = fmaxf(m, __shfl_xor_sync(0xFFFFFFFFu, m, off));
    float s = 0.f;
    for (int j = lane; j < LSEQ; j += 32) {
      float e = __expf(pr[j] - m);
      pr[j] = e; s += e;
    }
#pragma unroll
    for (int off = 16; off > 0; off >>= 1)
      s += __shfl_xor_sync(0xFFFFFFFFu, s, off);
    float inv = 1.0f / s;
    if (attn_out) {
      float* ao = attn_out + ((size_t)(b * NH + h) * LSEQ + q0 + r) * LSEQ;
      for (int j = lane; j < LSEQ; j += 32) {
        float p = pr[j] * inv; pr[j] = p; ao[j] = p;
      }
    } else {
      for (int j = lane; j < LSEQ; j += 32) pr[j] *= inv;
    }
  }

  // ---- Pass 3: ctx = P @ V, 8 chunks of 128 keys ----
  const uint32_t pb = kb;
  const uint32_t vb = kb + 16384;
  const int mt_w = wid >> 2;
  const int ng_w = wid & 3;
  float cacc[2][4] = {};
  for (int c = 0; c < 8; c++) {
    __syncthreads();
#pragma unroll
    for (int i = 0; i < 2; i++) {
      int id = tid + i * 256;
      int r = id >> 4, seg = id & 15;
      const float* pr = &probs[r * PP + c * 128 + seg * 8];
      float4 p0 = *(const float4*)pr;
      float4 p1 = *(const float4*)(pr + 4);
      __half hh[8], ll[8];
      float pv[8] = {p0.x, p0.y, p0.z, p0.w, p1.x, p1.y, p1.z, p1.w};
#pragma unroll
      for (int e = 0; e < 8; e++) split_h(pv[e], hh[e], ll[e]);
      uint32_t off = r * 256 + ((seg ^ (r & 7)) << 4);
      *(uint4*)(chunk + off)        = *(uint4*)hh;
      *(uint4*)(chunk + 8192 + off) = *(uint4*)ll;
    }
#pragma unroll
    for (int i = 0; i < 8; i++) {
      int id = tid + i * 256;
      int buf = id >> 10;
      int sub = id & 1023;
      int r = sub >> 4, seg = sub & 15;
      const __half* src = (buf ? vtl : vth)
          + ((size_t)(b * NH + h) * DKH + r) * LSEQ + c * 128 + seg * 8;
      uint4 val = *(const uint4*)src;
      *(uint4*)(chunk + 16384 + buf * 16384 + r * 256 +
                ((seg ^ (r & 7)) << 4)) = val;
    }
    __syncthreads();
#pragma unroll
    for (int kk = 0; kk < 8; kk++) {
      uint32_t p_h[4], p_l[4];
      {
        int row = mt_w * 16 + aRowOff;
        int ci  = kk * 2 + aCSel;
        uint32_t off = row * 256 + ((ci ^ (row & 7)) << 4);
        LDSM4(p_h, pb + off);
        LDSM4(p_l, pb + 8192 + off);
      }
      uint32_t v_h[4], v_l[4];
      {
        int row = ng_w * 16 + bRowOff;
        int ci  = kk * 2 + bCSel;
        uint32_t off = row * 256 + ((ci ^ (row & 7)) << 4);
        LDSM4(v_h, vb + off);
        LDSM4(v_l, vb + 16384 + off);
      }
#pragma unroll
      for (int nt = 0; nt < 2; nt++) {
        const int j = nt * 2;
        MMAF16(cacc[nt], p_h, v_h[j], v_h[j + 1]);
        MMAF16(cacc[nt], p_h, v_l[j], v_l[j + 1]);
        MMAF16(cacc[nt], p_l, v_h[j], v_h[j + 1]);
      }
    }
  }
#pragma unroll
  for (int nt = 0; nt < 2; nt++) {
    size_t r0 = (size_t)b * LSEQ + q0 + mt_w * 16 + rT;
    size_t c0 = h * DKH + ng_w * 16 + nt * 8 + cT;
    __half h0, h1, h2, h3, l0, l1, l2, l3;
    split_h(cacc[nt][0], h0, l0); split_h(cacc[nt][1], h1, l1);
    split_h(cacc[nt][2], h2, l2); split_h(cacc[nt][3], h3, l3);
    *(__half2*)(ch + r0 * DM + c0)       = __halves2half2(h0, h1);
    *(__half2*)(ch + (r0 + 8) * DM + c0) = __halves2half2(h2, h3);
    *(__half2*)(cl + r0 * DM + c0)       = __halves2half2(l0, l1);
    *(__half2*)(cl + (r0 + 8) * DM + c0) = __halves2half2(l2, l3);
  }
}

// ================= residual add + LayerNorm (fp32 + fp16 pair out) =========
__global__ void __launch_bounds__(256) ln_res(
    const float* __restrict__ A, const float* __restrict__ Xin,
    float* __restrict__ Xout,
    __half* __restrict__ XH, __half* __restrict__ XL) {
  const int row = blockIdx.x, t = threadIdx.x;
  const float4* a4 = (const float4*)(A + (size_t)row * DM);
  const float4* xi = (const float4*)(Xin + (size_t)row * DM);
  float4 a = a4[t], x = xi[t];
  float v0 = a.x + x.x, v1 = a.y + x.y, v2 = a.z + x.z, v3 = a.w + x.w;
  float s = v0 + v1 + v2 + v3;
  float q = v0 * v0 + v1 * v1 + v2 * v2 + v3 * v3;
#pragma unroll
  for (int off = 16; off > 0; off >>= 1) {
    s += __shfl_xor_sync(0xFFFFFFFFu, s, off);
    q += __shfl_xor_sync(0xFFFFFFFFu, q, off);
  }
  __shared__ float rs[8], rq[8];
  __shared__ float mu_s, rstd_s;
  int warp = t >> 5, lane = t & 31;
  if (lane == 0) { rs[warp] = s; rq[warp] = q; }
  __syncthreads();
  if (t == 0) {
    float S = 0.f, Qq = 0.f;
#pragma unroll
    for (int i = 0; i < 8; i++) { S += rs[i]; Qq += rq[i]; }
    float mu = S * (1.0f / DM);
    float var = Qq * (1.0f / DM) - mu * mu;
    mu_s = mu;
    rstd_s = rsqrtf(var + 1e-5f);
  }
  __syncthreads();
  float mu = mu_s, r = rstd_s;
  float o0 = (v0 - mu) * r, o1 = (v1 - mu) * r;
  float o2 = (v2 - mu) * r, o3 = (v3 - mu) * r;
  ((float4*)(Xout + (size_t)row * DM))[t] = make_float4(o0, o1, o2, o3);
  __half h0, h1, h2, h3, l0, l1, l2, l3;
  split_h(o0, h0, l0); split_h(o1, h1, l1);
  split_h(o2, h2, l2); split_h(o3, h3, l3);
  __half2* H = (__half2*)(XH + (size_t)row * DM);
  __half2* L = (__half2*)(XL + (size_t)row * DM);
  H[2 * t]     = __halves2half2(h0, h1);
  H[2 * t + 1] = __halves2half2(h2, h3);
  L[2 * t]     = __halves2half2(l0, l1);
  L[2 * t + 1] = __halves2half2(l2, l3);
}

// ================= launcher ================================================
extern "C" void kernel_launch(void* const* d_in, const int* in_sizes, int n_in,
                              void* d_out, int out_size) {
  const int*   toks = (const int*)  d_in[0];
  const float* emb  = (const float*)d_in[1];
  const float* pe   = (const float*)d_in[2];
  const float* WQ   = (const float*)d_in[3];
  const float* WK   = (const float*)d_in[4];
  const float* WV   = (const float*)d_in[5];
  const float* WO   = (const float*)d_in[6];
  const float* W1   = (const float*)d_in[7];
  const float* W2   = (const float*)d_in[8];
  float* out = (float*)d_out;

  float *x, *tmp, *v;
  cudaGetSymbolAddress((void**)&x,   g_x);
  cudaGetSymbolAddress((void**)&tmp, g_tmp);
  cudaGetSymbolAddress((void**)&v,   g_v);

  __half *xh,*xl,*qh,*ql,*kh,*kl,*vth,*vtl,*ch,*cl,*fh,*fl;
  cudaGetSymbolAddress((void**)&xh, g_xh);  cudaGetSymbolAddress((void**)&xl, g_xl);
  cudaGetSymbolAddress((void**)&qh, g_qh);  cudaGetSymbolAddress((void**)&ql, g_ql);
  cudaGetSymbolAddress((void**)&kh, g_kh);  cudaGetSymbolAddress((void**)&kl, g_kl);
  cudaGetSymbolAddress((void**)&vth, g_vth); cudaGetSymbolAddress((void**)&vtl, g_vtl);
  cudaGetSymbolAddress((void**)&ch, g_ch);  cudaGetSymbolAddress((void**)&cl, g_cl);
  cudaGetSymbolAddress((void**)&fh, g_fh);  cudaGetSymbolAddress((void**)&fl, g_fl);

  __half *wqh,*wql,*wkh,*wkl,*wvh,*wvl,*woh,*wol,*w1h,*w1l,*w2h,*w2l;
  cudaGetSymbolAddress((void**)&wqh, g_wqh); cudaGetSymbolAddress((void**)&wql, g_wql);
  cudaGetSymbolAddress((void**)&wkh, g_wkh); cudaGetSymbolAddress((void**)&wkl, g_wkl);
  cudaGetSymbolAddress((void**)&wvh, g_wvh); cudaGetSymbolAddress((void**)&wvl, g_wvl);
  cudaGetSymbolAddress((void**)&woh, g_woh); cudaGetSymbolAddress((void**)&wol, g_wol);
  cudaGetSymbolAddress((void**)&w1h, g_w1h); cudaGetSymbolAddress((void**)&w1l, g_w1l);
  cudaGetSymbolAddress((void**)&w2h, g_w2h); cudaGetSymbolAddress((void**)&w2l, g_w2l);

  const size_t XE = (size_t)ROWS * DM;
  const size_t AE = (size_t)NL * B_ * NH * LSEQ * LSEQ;
  float* attn_base = ((size_t)out_size >= XE + AE) ? (out + XE) : nullptr;

  cudaFuncSetAttribute(attn_mma, cudaFuncAttributeMaxDynamicSharedMemorySize, ATT_SMEM);
  cudaFuncSetAttribute(qkv_h,   cudaFuncAttributeMaxDynamicSharedMemorySize, GEMM_SMEM3);
  cudaFuncSetAttribute(gemm2_h, cudaFuncAttributeMaxDynamicSharedMemorySize, GEMM_SMEM2);

  // ---- weight preprocessing: transpose + fp16 hi/lo ----
  for (int l = 0; l < NL; l++) {
    size_t o1 = (size_t)l * DM * DM;
    size_t o2 = (size_t)l * DM * DFF;
    transpose_split_h<<<dim3(DM/32, DM/32), 256>>>(WQ + o1, wqh + o1, wql + o1, DM, DM);
    transpose_split_h<<<dim3(DM/32, DM/32), 256>>>(WK + o1, wkh + o1, wkl + o1, DM, DM);
    transpose_split_h<<<dim3(DM/32, DM/32), 256>>>(WV + o1, wvh + o1, wvl + o1, DM, DM);
    transpose_split_h<<<dim3(DM/32, DM/32), 256>>>(WO + o1, woh + o1, wol + o1, DM, DM);
    transpose_split_h<<<dim3(DFF/32, DM/32), 256>>>(W1 + o2, w1h + o2, w1l + o2, DM, DFF);
    transpose_split_h<<<dim3(DM/32, DFF/32), 256>>>(W2 + o2, w2h + o2, w2l + o2, DFF, DM);
  }

  embed_kernel<<<ROWS, 256>>>(toks, emb, pe, x, xh, xl);

  const dim3 gQKV (DM / 128, ROWS / 128, 3);       // (8, 32, 3)
  const dim3 gProj(DM / 128, ROWS / 128);          // (8, 32)
  const dim3 gFF1 (DFF / 128, ROWS / 128);         // (32, 32)

  for (int l = 0; l < NL; l++) {
    size_t o1 = (size_t)l * DM * DM;
    size_t o2 = (size_t)l * DM * DFF;

    qkv_h<<<gQKV, 256, GEMM_SMEM3>>>(xh, xl,
                                     wqh + o1, wql + o1,
                                     wkh + o1, wkl + o1,
                                     wvh + o1, wvl + o1,
                                     qh, ql, kh, kl, v);
    vtrans_kernel<<<dim3(LSEQ/32, DKH/32, B_*NH), 256>>>(v, vth, vtl);

    float* ao = attn_base ? attn_base + (size_t)l * B_ * NH * LSEQ * LSEQ : nullptr;
    attn_mma<<<dim3(LSEQ/32, NH, B_), 256, ATT_SMEM>>>(
        qh, ql, kh, kl, vth, vtl, toks, ao, ch, cl);

    gemm2_h<<<gProj, 256, GEMM_SMEM2>>>(ch, cl, woh + o1,
                                        tmp, nullptr, nullptr, DM, DM, 0);
    ln_res<<<ROWS, 256>>>(tmp, x, x, xh, xl);

    gemm2_h<<<gFF1, 256, GEMM_SMEM2>>>(xh, xl, w1h + o2,
                                       nullptr, fh, fl, DM, DFF, 2);
    gemm2_h<<<gProj, 256, GEMM_SMEM2>>>(fh, fl, w2h + o2,
                                        tmp, nullptr, nullptr, DFF, DM, 0);
    float* xdst = (l == NL - 1) ? out : x;
    ln_res<<<ROWS, 256>>>(tmp, x, xdst, xh, xl);
  }
}

// round 14
// speedup vs baseline: 3.3134x; 1.0517x over previous
#include <cuda_runtime.h>
#include <cuda_fp16.h>
#include <cstdint>
#include <math.h>

#define B_   4
#define LSEQ 1024
#define DM   1024
#define NH   16
#define DKH  64
#define DFF  4096
#define NL   2
#define ROWS (B_*LSEQ)   // 4096

// ================= scratch (device globals: allocation-guard safe) =========
__device__ float g_x  [ROWS*DM];
__device__ float g_tmp[ROWS*DM];
__device__ float g_v  [ROWS*DM];
// fp16 hi/lo activation pairs
__device__ __half g_xh[ROWS*DM],  g_xl[ROWS*DM];
__device__ __half g_qh[ROWS*DM],  g_ql[ROWS*DM];
__device__ __half g_kh[ROWS*DM],  g_kl[ROWS*DM];
__device__ __half g_vth[ROWS*DM];
__device__ __half g_ch[ROWS*DM],  g_cl[ROWS*DM];
__device__ __half g_fh[(size_t)ROWS*DFF], g_fl[(size_t)ROWS*DFF];
// fp16 hi/lo weights, pre-transposed to [N,K]
__device__ __half g_wqh[NL*DM*DM], g_wql[NL*DM*DM];
__device__ __half g_wkh[NL*DM*DM], g_wkl[NL*DM*DM];
__device__ __half g_wvh[NL*DM*DM], g_wvl[NL*DM*DM];
__device__ __half g_woh[NL*DM*DM], g_wol[NL*DM*DM];
__device__ __half g_w1h[(size_t)NL*DM*DFF], g_w1l[(size_t)NL*DM*DFF];
__device__ __half g_w2h[(size_t)NL*DM*DFF], g_w2l[(size_t)NL*DM*DFF];

// ================= PTX helpers (sm_80-baseline; no tcgen05) ================
#define CP_ASYNC16(smem, gptr) \
  asm volatile("cp.async.cg.shared.global [%0], [%1], 16;" \
               :: "r"(smem), "l"(gptr))
#define CP_COMMIT() asm volatile("cp.async.commit_group;" ::: "memory")
#define CP_WAIT1()  asm volatile("cp.async.wait_group 1;" ::: "memory")

#define LDSM4(r, addr) \
  asm volatile("ldmatrix.sync.aligned.m8n8.x4.shared.b16 {%0,%1,%2,%3}, [%4];" \
    : "=r"((r)[0]), "=r"((r)[1]), "=r"((r)[2]), "=r"((r)[3]) : "r"(addr))

#define MMAF16(d, a, b0v, b1v) \
  asm volatile("mma.sync.aligned.m16n8k16.row.col.f32.f16.f16.f32 " \
    "{%0,%1,%2,%3}, {%4,%5,%6,%7}, {%8,%9}, {%0,%1,%2,%3};" \
    : "+f"((d)[0]), "+f"((d)[1]), "+f"((d)[2]), "+f"((d)[3]) \
    : "r"((a)[0]), "r"((a)[1]), "r"((a)[2]), "r"((a)[3]), "r"(b0v), "r"(b1v))

__device__ __forceinline__ uint32_t smem_to_u32(const void* p) {
  uint32_t a;
  asm("{ .reg .u64 t; cvta.to.shared.u64 t, %1; cvt.u32.u64 %0, t; }"
      : "=r"(a) : "l"(p));
  return a;
}

__device__ __forceinline__ void split_h(float v, __half& h, __half& l) {
  h = __float2half_rn(v);
  l = __float2half_rn(v - __half2float(h));
}

// ================= fp16 split GEMM: C = A[M,K] @ Bt[N,K]^T =================
// NTERMS=3 (+runtime third): C = Ah*Bh + Al*Bh [+ Ah*Bl]
// NTERMS=2:                  C = Ah*Bh + Al*Bh
// modes: 0 = fp32 out, 1 = half-pair out, 2 = half-pair out + relu
#define MATB 16384                       // 128 rows x 128 bytes

template<int NTERMS>
__device__ __forceinline__ void load_stage_h(
    uint32_t sbase, const __half* Ah, const __half* Al,
    const __half* Bh, const __half* Bl,
    size_t rowA, size_t rowB, int K, int kc, int tid, bool loadBl) {
  const int NM = NTERMS + 1;             // 3 or 4 matrices
#pragma unroll
  for (int i = 0; i < NM * 4; i++) {
    int idx = tid + i * 256;
    int mat = idx >> 10;                 // constant per i (256 threads)
    if (mat == 3 && !loadBl) continue;
    int sub = idx & 1023;
    int row = sub >> 3, seg = sub & 7;
    const __half* base = (mat == 0) ? Ah : (mat == 1) ? Al
                       : (mat == 2) ? Bh : Bl;
    size_t r0 = (mat < 2) ? rowA : rowB;
    const __half* g = base + (r0 + row) * (size_t)K + (size_t)kc * 64 + seg * 8;
    uint32_t s = sbase + mat * MATB + row * 128 + ((seg ^ (row & 7)) << 4);
    CP_ASYNC16(s, g);
  }
}

template<int NTERMS, int NSTAGE>
__device__ __forceinline__ void gemm_h_body(
    const __half* Ah, const __half* Al,
    const __half* Bh, const __half* Bl,
    float* Cf, __half* CH, __half* CL,
    int K, int N, int mode, bool third, char* smem, int bx, int by) {
  const uint32_t sbm = smem_to_u32(smem);
  const int STAGEB = (NTERMS + 1) * MATB;
  const int tid = threadIdx.x, wid = tid >> 5, lane = tid & 31;

  const size_t rowA = (size_t)by * 128;
  const size_t rowB = (size_t)bx * 128;
  const int nch = K / 64;

  const int mbase = (wid >> 2) * 64;
  const int nbase = (wid & 3) * 32;

  const int aRowOff = ((lane >> 3) & 1) * 8 + (lane & 7);
  const int aCSel   = (lane >> 4) & 1;
  const int bRowOff = ((lane >> 4) & 1) * 8 + (lane & 7);
  const int bCSel   = (lane >> 3) & 1;

  float acc[4][4][4];
#pragma unroll
  for (int mt = 0; mt < 4; mt++)
#pragma unroll
    for (int nt = 0; nt < 4; nt++)
#pragma unroll
      for (int e = 0; e < 4; e++) acc[mt][nt][e] = 0.f;

#pragma unroll
  for (int s = 0; s < NSTAGE - 1; s++) {
    load_stage_h<NTERMS>(sbm + s * STAGEB, Ah, Al, Bh, Bl,
                         rowA, rowB, K, s, tid, third);
    CP_COMMIT();
  }

  for (int kc = 0; kc < nch; kc++) {
    if (NSTAGE == 2) {
      if (kc + 1 < nch)
        load_stage_h<NTERMS>(sbm + ((kc + 1) & 1) * STAGEB,
                             Ah, Al, Bh, Bl, rowA, rowB, K, kc + 1, tid, third);
      CP_COMMIT();
      CP_WAIT1();
      __syncthreads();
    } else {
      CP_WAIT1();
      __syncthreads();
      if (kc + NSTAGE - 1 < nch)
        load_stage_h<NTERMS>(sbm + ((kc + NSTAGE - 1) % NSTAGE) * STAGEB,
                             Ah, Al, Bh, Bl, rowA, rowB, K,
                             kc + NSTAGE - 1, tid, third);
      CP_COMMIT();
    }

    const uint32_t bufA_h = sbm + (kc % NSTAGE) * STAGEB;
    const uint32_t bufA_l = bufA_h + MATB;
    const uint32_t bufB_h = bufA_h + 2 * MATB;
    const uint32_t bufB_l = bufA_h + 3 * MATB;

#pragma unroll
    for (int kk = 0; kk < 4; kk++) {
      uint32_t a_h[4][4], a_l[4][4];
#pragma unroll
      for (int mt = 0; mt < 4; mt++) {
        int row = mbase + mt * 16 + aRowOff;
        int ci  = kk * 2 + aCSel;
        uint32_t off = row * 128 + ((ci ^ (row & 7)) << 4);
        LDSM4(a_h[mt], bufA_h + off);
        LDSM4(a_l[mt], bufA_l + off);
      }
      uint32_t b_h[2][4], b_l[2][4];
#pragma unroll
      for (int ng = 0; ng < 2; ng++) {
        int row = nbase + ng * 16 + bRowOff;
        int ci  = kk * 2 + bCSel;
        uint32_t off = row * 128 + ((ci ^ (row & 7)) << 4);
        LDSM4(b_h[ng], bufB_h + off);
        if (NTERMS == 3 && third) LDSM4(b_l[ng], bufB_l + off);
      }
#pragma unroll
      for (int mt = 0; mt < 4; mt++)
#pragma unroll
        for (int nt = 0; nt < 4; nt++) {
          const int ng = nt >> 1, j = (nt & 1) * 2;
          MMAF16(acc[mt][nt], a_h[mt], b_h[ng][j], b_h[ng][j + 1]);
          MMAF16(acc[mt][nt], a_l[mt], b_h[ng][j], b_h[ng][j + 1]);
          if (NTERMS == 3 && third)
            MMAF16(acc[mt][nt], a_h[mt], b_l[ng][j], b_l[ng][j + 1]);
        }
    }
    __syncthreads();
  }

  const int rT = lane >> 2, cT = (lane & 3) * 2;
#pragma unroll
  for (int mt = 0; mt < 4; mt++) {
#pragma unroll
    for (int nt = 0; nt < 4; nt++) {
      size_t r0 = rowA + mbase + mt * 16 + rT;
      size_t c0 = rowB + nbase + nt * 8 + cT;
      float v0 = acc[mt][nt][0], v1 = acc[mt][nt][1];
      float v2 = acc[mt][nt][2], v3 = acc[mt][nt][3];
      if (mode == 2) {
        v0 = fmaxf(v0, 0.f); v1 = fmaxf(v1, 0.f);
        v2 = fmaxf(v2, 0.f); v3 = fmaxf(v3, 0.f);
      }
      if (mode == 0) {
        *(float2*)(Cf + r0 * N + c0)       = make_float2(v0, v1);
        *(float2*)(Cf + (r0 + 8) * N + c0) = make_float2(v2, v3);
      } else {
        __half h0, h1, h2, h3, l0, l1, l2, l3;
        split_h(v0, h0, l0); split_h(v1, h1, l1);
        split_h(v2, h2, l2); split_h(v3, h3, l3);
        *(__half2*)(CH + r0 * N + c0)       = __halves2half2(h0, h1);
        *(__half2*)(CH + (r0 + 8) * N + c0) = __halves2half2(h2, h3);
        *(__half2*)(CL + r0 * N + c0)       = __halves2half2(l0, l1);
        *(__half2*)(CL + (r0 + 8) * N + c0) = __halves2half2(l2, l3);
      }
    }
  }
}

#define GEMM_SMEM3 (3 * 4 * MATB)   // 196608 (3-term, 3 stages, occ 1)
#define GEMM_SMEM2 (2 * 3 * MATB)   // 98304  (2-term, 2 stages, occ 2)

// fused QKV: z=0 -> Q pair (3-term), z=1 -> K pair (3-term), z=2 -> V fp32 (2-term)
__global__ void __launch_bounds__(256, 1) qkv_h(
    const __half* __restrict__ xh, const __half* __restrict__ xl,
    const __half* __restrict__ wqh, const __half* __restrict__ wql,
    const __half* __restrict__ wkh, const __half* __restrict__ wkl,
    const __half* __restrict__ wvh, const __half* __restrict__ wvl,
    __half* __restrict__ qh, __half* __restrict__ ql,
    __half* __restrict__ kh, __half* __restrict__ kl,
    float* __restrict__ v) {
  extern __shared__ char smem[];
  const int z = blockIdx.z;
  const __half* Bh = (z == 0) ? wqh : (z == 1) ? wkh : wvh;
  const __half* Bl = (z == 0) ? wql : (z == 1) ? wkl : wvl;
  __half* CH = (z == 0) ? qh : kh;
  __half* CL = (z == 0) ? ql : kl;
  gemm_h_body<3, 3>(xh, xl, Bh, Bl, (z == 2) ? v : nullptr, CH, CL,
                    DM, DM, (z == 2) ? 0 : 1, z != 2,
                    smem, blockIdx.x, blockIdx.y);
}

// 2-term GEMM (WO / FF1 / FF2), occupancy 2
__global__ void __launch_bounds__(256, 2) gemm2_h(
    const __half* __restrict__ Ah, const __half* __restrict__ Al,
    const __half* __restrict__ Bh,
    float* __restrict__ Cf, __half* __restrict__ CH, __half* __restrict__ CL,
    int K, int N, int mode) {
  extern __shared__ char smem[];
  gemm_h_body<2, 2>(Ah, Al, Bh, nullptr, Cf, CH, CL, K, N, mode, false,
                    smem, blockIdx.x, blockIdx.y);
}

// ================= weight transpose + fp16 hi/lo, layer-batched ============
__global__ void __launch_bounds__(256) transpose_split_h(
    const float* __restrict__ W, __half* __restrict__ Th,
    __half* __restrict__ Tl, int K, int N) {
  __shared__ float t[32][33];
  const size_t lo = (size_t)blockIdx.z * K * N;
  const int n0 = blockIdx.x * 32, k0 = blockIdx.y * 32;
  const int tx = threadIdx.x & 31, ty = threadIdx.x >> 5;
#pragma unroll
  for (int i = 0; i < 4; i++)
    t[ty + i * 8][tx] = W[lo + (size_t)(k0 + ty + i * 8) * N + n0 + tx];
  __syncthreads();
#pragma unroll
  for (int i = 0; i < 4; i++) {
    int n = n0 + ty + i * 8, k = k0 + tx;
    __half h, l;
    split_h(t[tx][ty + i * 8], h, l);
    Th[lo + (size_t)n * K + k] = h;
    Tl[lo + (size_t)n * K + k] = l;
  }
}

// ================= V transpose (hi only): v[row,h*64+d] -> vt[(bh*64+d),l] =
__global__ void __launch_bounds__(256) vtrans_kernel(
    const float* __restrict__ v, __half* __restrict__ vth) {
  __shared__ float t[32][33];
  const int bh = blockIdx.z;
  const int l0 = blockIdx.x * 32, d0 = blockIdx.y * 32;
  const int tx = threadIdx.x & 31, ty = threadIdx.x >> 5;
  const int b = bh >> 4, h = bh & 15;
#pragma unroll
  for (int i = 0; i < 4; i++)
    t[ty + i * 8][tx] =
        v[((size_t)b * LSEQ + l0 + ty + i * 8) * DM + h * DKH + d0 + tx];
  __syncthreads();
#pragma unroll
  for (int i = 0; i < 4; i++) {
    int d = d0 + ty + i * 8, l = l0 + tx;
    vth[((size_t)bh * DKH + d) * LSEQ + l] = __float2half_rn(t[tx][ty + i * 8]);
  }
}

// ================= embedding + PE (fp32 + fp16 pair out) ===================
__global__ void __launch_bounds__(256) embed_kernel(
    const int* __restrict__ toks, const float* __restrict__ emb,
    const float* __restrict__ pe, float* __restrict__ X,
    __half* __restrict__ XH, __half* __restrict__ XL) {
  int row = blockIdx.x;
  int l   = row & (LSEQ - 1);
  int tok = toks[row];
  const float4* e = (const float4*)(emb + (size_t)tok * DM);
  const float4* p = (const float4*)(pe  + (size_t)l   * DM);
  int t = threadIdx.x;
  float4 a = e[t], b = p[t];
  float4 v = make_float4(a.x + b.x, a.y + b.y, a.z + b.z, a.w + b.w);
  ((float4*)(X + (size_t)row * DM))[t] = v;
  __half h0, h1, h2, h3, l0, l1, l2, l3;
  split_h(v.x, h0, l0); split_h(v.y, h1, l1);
  split_h(v.z, h2, l2); split_h(v.w, h3, l3);
  __half2* H = (__half2*)(XH + (size_t)row * DM);
  __half2* L = (__half2*)(XL + (size_t)row * DM);
  H[2 * t]     = __halves2half2(h0, h1);
  H[2 * t + 1] = __halves2half2(h2, h3);
  L[2 * t]     = __halves2half2(l0, l1);
  L[2 * t + 1] = __halves2half2(l2, l3);
}

// ================= fp16 HMMA fused attention ===============================
// Pass 1 (scores): 3-term. Pass 3 (ctx): 2-term, V hi only.
#define PP 1028
#define ATT_PROBS_B (32 * PP * 4)        // 131584
#define ATT_Q_B     8192
#define ATT_MASK_B  4096
#define ATT_CHUNK_B 65536
#define ATT_SMEM (ATT_PROBS_B + ATT_Q_B + ATT_MASK_B + ATT_CHUNK_B)

__global__ void __launch_bounds__(256, 1) attn_mma(
    const __half* __restrict__ qh, const __half* __restrict__ ql,
    const __half* __restrict__ kh, const __half* __restrict__ kl,
    const __half* __restrict__ vth,
    const int* __restrict__ toks, float* __restrict__ attn_out,
    __half* __restrict__ ch, __half* __restrict__ cl) {
  extern __shared__ char asmem[];
  float* probs = (float*)asmem;
  char* qbuf   = asmem + ATT_PROBS_B;
  float* maskb = (float*)(qbuf + ATT_Q_B);
  char* chunk  = qbuf + ATT_Q_B + ATT_MASK_B;
  const uint32_t qb = smem_to_u32(qbuf);
  const uint32_t kb = smem_to_u32(chunk);

  const int b = blockIdx.z, h = blockIdx.y;
  const int q0 = blockIdx.x * 32;
  const int tid = threadIdx.x, wid = tid >> 5, lane = tid & 31;

  const int aRowOff = ((lane >> 3) & 1) * 8 + (lane & 7);
  const int aCSel   = (lane >> 4) & 1;
  const int bRowOff = ((lane >> 4) & 1) * 8 + (lane & 7);
  const int bCSel   = (lane >> 3) & 1;
  const int rT = lane >> 2, cT = (lane & 3) * 2;

#pragma unroll
  for (int i = 0; i < 2; i++) {
    int id = tid + i * 256;
    int buf = id >> 8;
    int r = (id & 255) >> 3, seg = id & 7;
    const __half* src = (buf ? ql : qh)
        + ((size_t)b * LSEQ + q0 + r) * DM + h * DKH + seg * 8;
    uint4 val = *(const uint4*)src;
    *(uint4*)(qbuf + buf * 4096 + r * 128 + ((seg ^ (r & 7)) << 4)) = val;
  }
  for (int j = tid; j < LSEQ; j += 256)
    maskb[j] = (toks[b * LSEQ + j] == 0) ? -1e9f : 0.f;
  __syncthreads();

  // ---- Pass 1: scores, 4 chunks of 256 keys (3-term) ----
  for (int c = 0; c < 4; c++) {
    if (c) __syncthreads();
#pragma unroll
    for (int i = 0; i < 16; i++) {
      int id = tid + i * 256;
      int buf = id >> 11;
      int sub = id & 2047;
      int r = sub >> 3, seg = sub & 7;
      const __half* src = (buf ? kl : kh)
          + ((size_t)b * LSEQ + c * 256 + r) * DM + h * DKH + seg * 8;
      uint4 val = *(const uint4*)src;
      *(uint4*)(chunk + buf * 32768 + r * 128 + ((seg ^ (r & 7)) << 4)) = val;
    }
    __syncthreads();

    float acc[2][4][4];
#pragma unroll
    for (int mt = 0; mt < 2; mt++)
#pragma unroll
      for (int nt = 0; nt < 4; nt++)
#pragma unroll
        for (int e = 0; e < 4; e++) acc[mt][nt][e] = 0.f;

#pragma unroll
    for (int kk = 0; kk < 4; kk++) {
      uint32_t a_h[2][4], a_l[2][4];
#pragma unroll
      for (int mt = 0; mt < 2; mt++) {
        int row = mt * 16 + aRowOff;
        int ci  = kk * 2 + aCSel;
        uint32_t off = row * 128 + ((ci ^ (row & 7)) << 4);
        LDSM4(a_h[mt], qb + off);
        LDSM4(a_l[mt], qb + 4096 + off);
      }
      uint32_t b_h[2][4], b_l[2][4];
#pragma unroll
      for (int ng = 0; ng < 2; ng++) {
        int row = wid * 32 + ng * 16 + bRowOff;
        int ci  = kk * 2 + bCSel;
        uint32_t off = row * 128 + ((ci ^ (row & 7)) << 4);
        LDSM4(b_h[ng], kb + off);
        LDSM4(b_l[ng], kb + 32768 + off);
      }
#pragma unroll
      for (int mt = 0; mt < 2; mt++)
#pragma unroll
        for (int nt = 0; nt < 4; nt++) {
          const int ng = nt >> 1, j = (nt & 1) * 2;
          MMAF16(acc[mt][nt], a_h[mt], b_h[ng][j], b_h[ng][j + 1]);
          MMAF16(acc[mt][nt], a_h[mt], b_l[ng][j], b_l[ng][j + 1]);
          MMAF16(acc[mt][nt], a_l[mt], b_h[ng][j], b_h[ng][j + 1]);
        }
    }
#pragma unroll
    for (int mt = 0; mt < 2; mt++)
#pragma unroll
      for (int nt = 0; nt < 4; nt++) {
        int col = c * 256 + wid * 32 + nt * 8 + cT;
        float b0 = maskb[col], b1 = maskb[col + 1];
        int r0 = mt * 16 + rT;
        probs[r0 * PP + col]           = acc[mt][nt][0] * 0.125f + b0;
        probs[r0 * PP + col + 1]       = acc[mt][nt][1] * 0.125f + b1;
        probs[(r0 + 8) * PP + col]     = acc[mt][nt][2] * 0.125f + b0;
        probs[(r0 + 8) * PP + col + 1] = acc[mt][nt][3] * 0.125f + b1;
      }
  }
  __syncthreads();

  // ---- Pass 2: softmax ----
#pragma unroll
  for (int rr = 0; rr < 4; rr++) {
    int r = wid + rr * 8;
    float* pr = &probs[r * PP];
    float m = -1e30f;
    for (int j = lane; j < LSEQ; j += 32) m = fmaxf(m, pr[j]);
#pragma unroll
    for (int off = 16; off > 0; off >>= 1)
      m = fmaxf(m, __shfl_xor_sync(0xFFFFFFFFu, m, off));
    float s = 0.f;
    for (int j = lane; j < LSEQ; j += 32) {
      float e = __expf(pr[j] - m);
      pr[j] = e; s += e;
    }
#pragma unroll
    for (int off = 16; off > 0; off >>= 1)
      s += __shfl_xor_sync(0xFFFFFFFFu, s, off);
    float inv = 1.0f / s;
    if (attn_out) {
      float* ao = attn_out + ((size_t)(b * NH + h) * LSEQ + q0 + r) * LSEQ;
      for (int j = lane; j < LSEQ; j += 32) {
        float p = pr[j] * inv; pr[j] = p; ao[j] = p;
      }
    } else {
      for (int j = lane; j < LSEQ; j += 32) pr[j] *= inv;
    }
  }

  // ---- Pass 3: ctx = P @ V, 8 chunks of 128 keys (2-term, V hi) ----
  // chunk layout: Ph [32x256B]=8192, Pl 8192, Vh [64x256B]=16384
  const uint32_t pb = kb;
  const uint32_t vb = kb + 16384;
  const int mt_w = wid >> 2;
  const int ng_w = wid & 3;
  float cacc[2][4] = {};
  for (int c = 0; c < 8; c++) {
    __syncthreads();
#pragma unroll
    for (int i = 0; i < 2; i++) {
      int id = tid + i * 256;
      int r = id >> 4, seg = id & 15;
      const float* pr = &probs[r * PP + c * 128 + seg * 8];
      float4 p0 = *(const float4*)pr;
      float4 p1 = *(const float4*)(pr + 4);
      __half hh[8], ll[8];
      float pv[8] = {p0.x, p0.y, p0.z, p0.w, p1.x, p1.y, p1.z, p1.w};
#pragma unroll
      for (int e = 0; e < 8; e++) split_h(pv[e], hh[e], ll[e]);
      uint32_t off = r * 256 + ((seg ^ (r & 7)) << 4);
      *(uint4*)(chunk + off)        = *(uint4*)hh;
      *(uint4*)(chunk + 8192 + off) = *(uint4*)ll;
    }
    // V hi chunk: 64 d-rows x 128 keys (pitch 256B)
#pragma unroll
    for (int i = 0; i < 4; i++) {
      int id = tid + i * 256;          // 0..1023
      int r = id >> 4, seg = id & 15;
      const __half* src = vth
          + ((size_t)(b * NH + h) * DKH + r) * LSEQ + c * 128 + seg * 8;
      uint4 val = *(const uint4*)src;
      *(uint4*)(chunk + 16384 + r * 256 + ((seg ^ (r & 7)) << 4)) = val;
    }
    __syncthreads();
#pragma unroll
    for (int kk = 0; kk < 8; kk++) {
      uint32_t p_h[4], p_l[4];
      {
        int row = mt_w * 16 + aRowOff;
        int ci  = kk * 2 + aCSel;
        uint32_t off = row * 256 + ((ci ^ (row & 7)) << 4);
        LDSM4(p_h, pb + off);
        LDSM4(p_l, pb + 8192 + off);
      }
      uint32_t v_h[4];
      {
        int row = ng_w * 16 + bRowOff;
        int ci  = kk * 2 + bCSel;
        uint32_t off = row * 256 + ((ci ^ (row & 7)) << 4);
        LDSM4(v_h, vb + off);
      }
#pragma unroll
      for (int nt = 0; nt < 2; nt++) {
        const int j = nt * 2;
        MMAF16(cacc[nt], p_h, v_h[j], v_h[j + 1]);
        MMAF16(cacc[nt], p_l, v_h[j], v_h[j + 1]);
      }
    }
  }
#pragma unroll
  for (int nt = 0; nt < 2; nt++) {
    size_t r0 = (size_t)b * LSEQ + q0 + mt_w * 16 + rT;
    size_t c0 = h * DKH + ng_w * 16 + nt * 8 + cT;
    __half h0, h1, h2, h3, l0, l1, l2, l3;
    split_h(cacc[nt][0], h0, l0); split_h(cacc[nt][1], h1, l1);
    split_h(cacc[nt][2], h2, l2); split_h(cacc[nt][3], h3, l3);
    *(__half2*)(ch + r0 * DM + c0)       = __halves2half2(h0, h1);
    *(__half2*)(ch + (r0 + 8) * DM + c0) = __halves2half2(h2, h3);
    *(__half2*)(cl + r0 * DM + c0)       = __halves2half2(l0, l1);
    *(__half2*)(cl + (r0 + 8) * DM + c0) = __halves2half2(l2, l3);
  }
}

// ================= residual add + LayerNorm (fp32 + fp16 pair out) =========
__global__ void __launch_bounds__(256) ln_res(
    const float* __restrict__ A, const float* __restrict__ Xin,
    float* __restrict__ Xout,
    __half* __restrict__ XH, __half* __restrict__ XL) {
  const int row = blockIdx.x, t = threadIdx.x;
  const float4* a4 = (const float4*)(A + (size_t)row * DM);
  const float4* xi = (const float4*)(Xin + (size_t)row * DM);
  float4 a = a4[t], x = xi[t];
  float v0 = a.x + x.x, v1 = a.y + x.y, v2 = a.z + x.z, v3 = a.w + x.w;
  float s = v0 + v1 + v2 + v3;
  float q = v0 * v0 + v1 * v1 + v2 * v2 + v3 * v3;
#pragma unroll
  for (int off = 16; off > 0; off >>= 1) {
    s += __shfl_xor_sync(0xFFFFFFFFu, s, off);
    q += __shfl_xor_sync(0xFFFFFFFFu, q, off);
  }
  __shared__ float rs[8], rq[8];
  __shared__ float mu_s, rstd_s;
  int warp = t >> 5, lane = t & 31;
  if (lane == 0) { rs[warp] = s; rq[warp] = q; }
  __syncthreads();
  if (t == 0) {
    float S = 0.f, Qq = 0.f;
#pragma unroll
    for (int i = 0; i < 8; i++) { S += rs[i]; Qq += rq[i]; }
    float mu = S * (1.0f / DM);
    float var = Qq * (1.0f / DM) - mu * mu;
    mu_s = mu;
    rstd_s = rsqrtf(var + 1e-5f);
  }
  __syncthreads();
  float mu = mu_s, r = rstd_s;
  float o0 = (v0 - mu) * r, o1 = (v1 - mu) * r;
  float o2 = (v2 - mu) * r, o3 = (v3 - mu) * r;
  ((float4*)(Xout + (size_t)row * DM))[t] = make_float4(o0, o1, o2, o3);
  __half h0, h1, h2, h3, l0, l1, l2, l3;
  split_h(o0, h0, l0); split_h(o1, h1, l1);
  split_h(o2, h2, l2); split_h(o3, h3, l3);
  __half2* H = (__half2*)(XH + (size_t)row * DM);
  __half2* L = (__half2*)(XL + (size_t)row * DM);
  H[2 * t]     = __halves2half2(h0, h1);
  H[2 * t + 1] = __halves2half2(h2, h3);
  L[2 * t]     = __halves2half2(l0, l1);
  L[2 * t + 1] = __halves2half2(l2, l3);
}

// ================= launcher ================================================
extern "C" void kernel_launch(void* const* d_in, const int* in_sizes, int n_in,
                              void* d_out, int out_size) {
  const int*   toks = (const int*)  d_in[0];
  const float* emb  = (const float*)d_in[1];
  const float* pe   = (const float*)d_in[2];
  const float* WQ   = (const float*)d_in[3];
  const float* WK   = (const float*)d_in[4];
  const float* WV   = (const float*)d_in[5];
  const float* WO   = (const float*)d_in[6];
  const float* W1   = (const float*)d_in[7];
  const float* W2   = (const float*)d_in[8];
  float* out = (float*)d_out;

  float *x, *tmp, *v;
  cudaGetSymbolAddress((void**)&x,   g_x);
  cudaGetSymbolAddress((void**)&tmp, g_tmp);
  cudaGetSymbolAddress((void**)&v,   g_v);

  __half *xh,*xl,*qh,*ql,*kh,*kl,*vth,*ch,*cl,*fh,*fl;
  cudaGetSymbolAddress((void**)&xh, g_xh);  cudaGetSymbolAddress((void**)&xl, g_xl);
  cudaGetSymbolAddress((void**)&qh, g_qh);  cudaGetSymbolAddress((void**)&ql, g_ql);
  cudaGetSymbolAddress((void**)&kh, g_kh);  cudaGetSymbolAddress((void**)&kl, g_kl);
  cudaGetSymbolAddress((void**)&vth, g_vth);
  cudaGetSymbolAddress((void**)&ch, g_ch);  cudaGetSymbolAddress((void**)&cl, g_cl);
  cudaGetSymbolAddress((void**)&fh, g_fh);  cudaGetSymbolAddress((void**)&fl, g_fl);

  __half *wqh,*wql,*wkh,*wkl,*wvh,*wvl,*woh,*wol,*w1h,*w1l,*w2h,*w2l;
  cudaGetSymbolAddress((void**)&wqh, g_wqh); cudaGetSymbolAddress((void**)&wql, g_wql);
  cudaGetSymbolAddress((void**)&wkh, g_wkh); cudaGetSymbolAddress((void**)&wkl, g_wkl);
  cudaGetSymbolAddress((void**)&wvh, g_wvh); cudaGetSymbolAddress((void**)&wvl, g_wvl);
  cudaGetSymbolAddress((void**)&woh, g_woh); cudaGetSymbolAddress((void**)&wol, g_wol);
  cudaGetSymbolAddress((void**)&w1h, g_w1h); cudaGetSymbolAddress((void**)&w1l, g_w1l);
  cudaGetSymbolAddress((void**)&w2h, g_w2h); cudaGetSymbolAddress((void**)&w2l, g_w2l);

  const size_t XE = (size_t)ROWS * DM;
  const size_t AE = (size_t)NL * B_ * NH * LSEQ * LSEQ;
  float* attn_base = ((size_t)out_size >= XE + AE) ? (out + XE) : nullptr;

  cudaFuncSetAttribute(attn_mma, cudaFuncAttributeMaxDynamicSharedMemorySize, ATT_SMEM);
  cudaFuncSetAttribute(qkv_h,   cudaFuncAttributeMaxDynamicSharedMemorySize, GEMM_SMEM3);
  cudaFuncSetAttribute(gemm2_h, cudaFuncAttributeMaxDynamicSharedMemorySize, GEMM_SMEM2);

  // ---- weight preprocessing: transpose + fp16 hi/lo, layer-batched ----
  transpose_split_h<<<dim3(DM/32, DM/32, NL), 256>>>(WQ, wqh, wql, DM, DM);
  transpose_split_h<<<dim3(DM/32, DM/32, NL), 256>>>(WK, wkh, wkl, DM, DM);
  transpose_split_h<<<dim3(DM/32, DM/32, NL), 256>>>(WV, wvh, wvl, DM, DM);
  transpose_split_h<<<dim3(DM/32, DM/32, NL), 256>>>(WO, woh, wol, DM, DM);
  transpose_split_h<<<dim3(DFF/32, DM/32, NL), 256>>>(W1, w1h, w1l, DM, DFF);
  transpose_split_h<<<dim3(DM/32, DFF/32, NL), 256>>>(W2, w2h, w2l, DFF, DM);

  embed_kernel<<<ROWS, 256>>>(toks, emb, pe, x, xh, xl);

  const dim3 gQKV (DM / 128, ROWS / 128, 3);       // (8, 32, 3)
  const dim3 gProj(DM / 128, ROWS / 128);          // (8, 32)
  const dim3 gFF1 (DFF / 128, ROWS / 128);         // (32, 32)

  for (int l = 0; l < NL; l++) {
    size_t o1 = (size_t)l * DM * DM;
    size_t o2 = (size_t)l * DM * DFF;

    qkv_h<<<gQKV, 256, GEMM_SMEM3>>>(xh, xl,
                                     wqh + o1, wql + o1,
                                     wkh + o1, wkl + o1,
                                     wvh + o1, wvl + o1,
                                     qh, ql, kh, kl, v);
    vtrans_kernel<<<dim3(LSEQ/32, DKH/32, B_*NH), 256>>>(v, vth);

    float* ao = attn_base ? attn_base + (size_t)l * B_ * NH * LSEQ * LSEQ : nullptr;
    attn_mma<<<dim3(LSEQ/32, NH, B_), 256, ATT_SMEM>>>(
        qh, ql, kh, kl, vth, toks, ao, ch, cl);

    gemm2_h<<<gProj, 256, GEMM_SMEM2>>>(ch, cl, woh + o1,
                                        tmp, nullptr, nullptr, DM, DM, 0);
    ln_res<<<ROWS, 256>>>(tmp, x, x, xh, xl);

    gemm2_h<<<gFF1, 256, GEMM_SMEM2>>>(xh, xl, w1h + o2,
                                       nullptr, fh, fl, DM, DFF, 2);
    gemm2_h<<<gProj, 256, GEMM_SMEM2>>>(fh, fl, w2h + o2,
                                        tmp, nullptr, nullptr, DFF, DM, 0);
    float* xdst = (l == NL - 1) ? out : x;
    ln_res<<<ROWS, 256>>>(tmp, x, xdst, xh, xl);
  }
}

// round 15
// speedup vs baseline: 4.0374x; 1.2185x over previous
#include <cuda_runtime.h>
#include <cuda_fp16.h>
#include <cstdint>
#include <math.h>

#define B_   4
#define LSEQ 1024
#define DM   1024
#define NH   16
#define DKH  64
#define DFF  4096
#define NL   2
#define ROWS (B_*LSEQ)   // 4096

// ================= scratch (device globals: allocation-guard safe) =========
__device__ float g_x  [ROWS*DM];
__device__ float g_tmp[ROWS*DM];
__device__ float g_v  [ROWS*DM];
// fp16 hi/lo activation pairs
__device__ __half g_xh[ROWS*DM],  g_xl[ROWS*DM];
__device__ __half g_qh[ROWS*DM],  g_ql[ROWS*DM];
__device__ __half g_kh[ROWS*DM],  g_kl[ROWS*DM];
__device__ __half g_vth[ROWS*DM];
__device__ __half g_ch[ROWS*DM],  g_cl[ROWS*DM];
__device__ __half g_fh[(size_t)ROWS*DFF];
// fp16 weights, pre-transposed to [N,K]; hi/lo for QKV+WO, hi-only for W1/W2
__device__ __half g_wqh[NL*DM*DM], g_wql[NL*DM*DM];
__device__ __half g_wkh[NL*DM*DM], g_wkl[NL*DM*DM];
__device__ __half g_wvh[NL*DM*DM], g_wvl[NL*DM*DM];
__device__ __half g_woh[NL*DM*DM], g_wol[NL*DM*DM];
__device__ __half g_w1h[(size_t)NL*DM*DFF];
__device__ __half g_w2h[(size_t)NL*DM*DFF];

// ================= PTX helpers (sm_80-baseline; no tcgen05) ================
#define CP_ASYNC16(smem, gptr) \
  asm volatile("cp.async.cg.shared.global [%0], [%1], 16;" \
               :: "r"(smem), "l"(gptr))
#define CP_COMMIT() asm volatile("cp.async.commit_group;" ::: "memory")
#define CP_WAIT1()  asm volatile("cp.async.wait_group 1;" ::: "memory")

#define LDSM4(r, addr) \
  asm volatile("ldmatrix.sync.aligned.m8n8.x4.shared.b16 {%0,%1,%2,%3}, [%4];" \
    : "=r"((r)[0]), "=r"((r)[1]), "=r"((r)[2]), "=r"((r)[3]) : "r"(addr))

#define MMAF16(d, a, b0v, b1v) \
  asm volatile("mma.sync.aligned.m16n8k16.row.col.f32.f16.f16.f32 " \
    "{%0,%1,%2,%3}, {%4,%5,%6,%7}, {%8,%9}, {%0,%1,%2,%3};" \
    : "+f"((d)[0]), "+f"((d)[1]), "+f"((d)[2]), "+f"((d)[3]) \
    : "r"((a)[0]), "r"((a)[1]), "r"((a)[2]), "r"((a)[3]), "r"(b0v), "r"(b1v))

__device__ __forceinline__ uint32_t smem_to_u32(const void* p) {
  uint32_t a;
  asm("{ .reg .u64 t; cvta.to.shared.u64 t, %1; cvt.u32.u64 %0, t; }"
      : "=r"(a) : "l"(p));
  return a;
}

__device__ __forceinline__ void split_h(float v, __half& h, __half& l) {
  h = __float2half_rn(v);
  l = __float2half_rn(v - __half2float(h));
}

// ================= fp16 split GEMM: C = A[M,K] @ Bt[N,K]^T =================
// NTERMS=3 (+runtime third): C = Ah*Bh + Al*Bh [+ Ah*Bl]
// NTERMS=2:                  C = Ah*Bh + Al*Bh
// NTERMS=1:                  C = Ah*Bh
// modes: 0 = fp32 out, 1 = half-pair out, 2 = half-pair + relu,
//        3 = half hi-only + relu
#define MATB 16384                       // 128 rows x 128 bytes

template<int NTERMS>
__device__ __forceinline__ void load_stage_h(
    uint32_t sbase, const __half* Ah, const __half* Al,
    const __half* Bh, const __half* Bl,
    size_t rowA, size_t rowB, int K, int kc, int tid, bool loadBl) {
  const int NM = (NTERMS == 1) ? 2 : NTERMS + 1;
#pragma unroll
  for (int i = 0; i < NM * 4; i++) {
    int idx = tid + i * 256;
    int mat = idx >> 10;                 // constant per i (256 threads)
    if (NTERMS == 3 && mat == 3 && !loadBl) continue;
    int sub = idx & 1023;
    int row = sub >> 3, seg = sub & 7;
    const __half* base;
    size_t r0;
    if (NTERMS == 1) {
      base = (mat == 0) ? Ah : Bh;
      r0 = (mat == 0) ? rowA : rowB;
    } else {
      base = (mat == 0) ? Ah : (mat == 1) ? Al : (mat == 2) ? Bh : Bl;
      r0 = (mat < 2) ? rowA : rowB;
    }
    const __half* g = base + (r0 + row) * (size_t)K + (size_t)kc * 64 + seg * 8;
    uint32_t s = sbase + mat * MATB + row * 128 + ((seg ^ (row & 7)) << 4);
    CP_ASYNC16(s, g);
  }
}

template<int NTERMS, int NSTAGE>
__device__ __forceinline__ void gemm_h_body(
    const __half* Ah, const __half* Al,
    const __half* Bh, const __half* Bl,
    float* Cf, __half* CH, __half* CL,
    int K, int N, int mode, bool third, char* smem, int bx, int by) {
  const uint32_t sbm = smem_to_u32(smem);
  const int STAGEB = ((NTERMS == 1) ? 2 : NTERMS + 1) * MATB;
  const int tid = threadIdx.x, wid = tid >> 5, lane = tid & 31;

  const size_t rowA = (size_t)by * 128;
  const size_t rowB = (size_t)bx * 128;
  const int nch = K / 64;

  const int mbase = (wid >> 2) * 64;
  const int nbase = (wid & 3) * 32;

  const int aRowOff = ((lane >> 3) & 1) * 8 + (lane & 7);
  const int aCSel   = (lane >> 4) & 1;
  const int bRowOff = ((lane >> 4) & 1) * 8 + (lane & 7);
  const int bCSel   = (lane >> 3) & 1;

  float acc[4][4][4];
#pragma unroll
  for (int mt = 0; mt < 4; mt++)
#pragma unroll
    for (int nt = 0; nt < 4; nt++)
#pragma unroll
      for (int e = 0; e < 4; e++) acc[mt][nt][e] = 0.f;

#pragma unroll
  for (int s = 0; s < NSTAGE - 1; s++) {
    load_stage_h<NTERMS>(sbm + s * STAGEB, Ah, Al, Bh, Bl,
                         rowA, rowB, K, s, tid, third);
    CP_COMMIT();
  }

  for (int kc = 0; kc < nch; kc++) {
    if (NSTAGE == 2) {
      if (kc + 1 < nch)
        load_stage_h<NTERMS>(sbm + ((kc + 1) & 1) * STAGEB,
                             Ah, Al, Bh, Bl, rowA, rowB, K, kc + 1, tid, third);
      CP_COMMIT();
      CP_WAIT1();
      __syncthreads();
    } else {
      CP_WAIT1();
      __syncthreads();
      if (kc + NSTAGE - 1 < nch)
        load_stage_h<NTERMS>(sbm + ((kc + NSTAGE - 1) % NSTAGE) * STAGEB,
                             Ah, Al, Bh, Bl, rowA, rowB, K,
                             kc + NSTAGE - 1, tid, third);
      CP_COMMIT();
    }

    const uint32_t bufA_h = sbm + (kc % NSTAGE) * STAGEB;
    const uint32_t bufA_l = bufA_h + MATB;
    const uint32_t bufB_h = (NTERMS == 1) ? bufA_h + MATB : bufA_h + 2 * MATB;
    const uint32_t bufB_l = bufA_h + 3 * MATB;

#pragma unroll
    for (int kk = 0; kk < 4; kk++) {
      uint32_t a_h[4][4], a_l[4][4];
#pragma unroll
      for (int mt = 0; mt < 4; mt++) {
        int row = mbase + mt * 16 + aRowOff;
        int ci  = kk * 2 + aCSel;
        uint32_t off = row * 128 + ((ci ^ (row & 7)) << 4);
        LDSM4(a_h[mt], bufA_h + off);
        if (NTERMS >= 2) LDSM4(a_l[mt], bufA_l + off);
      }
      uint32_t b_h[2][4], b_l[2][4];
#pragma unroll
      for (int ng = 0; ng < 2; ng++) {
        int row = nbase + ng * 16 + bRowOff;
        int ci  = kk * 2 + bCSel;
        uint32_t off = row * 128 + ((ci ^ (row & 7)) << 4);
        LDSM4(b_h[ng], bufB_h + off);
        if (NTERMS == 3 && third) LDSM4(b_l[ng], bufB_l + off);
      }
#pragma unroll
      for (int mt = 0; mt < 4; mt++)
#pragma unroll
        for (int nt = 0; nt < 4; nt++) {
          const int ng = nt >> 1, j = (nt & 1) * 2;
          MMAF16(acc[mt][nt], a_h[mt], b_h[ng][j], b_h[ng][j + 1]);
          if (NTERMS >= 2)
            MMAF16(acc[mt][nt], a_l[mt], b_h[ng][j], b_h[ng][j + 1]);
          if (NTERMS == 3 && third)
            MMAF16(acc[mt][nt], a_h[mt], b_l[ng][j], b_l[ng][j + 1]);
        }
    }
    __syncthreads();
  }

  const int rT = lane >> 2, cT = (lane & 3) * 2;
#pragma unroll
  for (int mt = 0; mt < 4; mt++) {
#pragma unroll
    for (int nt = 0; nt < 4; nt++) {
      size_t r0 = rowA + mbase + mt * 16 + rT;
      size_t c0 = rowB + nbase + nt * 8 + cT;
      float v0 = acc[mt][nt][0], v1 = acc[mt][nt][1];
      float v2 = acc[mt][nt][2], v3 = acc[mt][nt][3];
      if (mode >= 2) {
        v0 = fmaxf(v0, 0.f); v1 = fmaxf(v1, 0.f);
        v2 = fmaxf(v2, 0.f); v3 = fmaxf(v3, 0.f);
      }
      if (mode == 0) {
        *(float2*)(Cf + r0 * N + c0)       = make_float2(v0, v1);
        *(float2*)(Cf + (r0 + 8) * N + c0) = make_float2(v2, v3);
      } else if (mode == 3) {
        *(__half2*)(CH + r0 * N + c0) =
            __halves2half2(__float2half_rn(v0), __float2half_rn(v1));
        *(__half2*)(CH + (r0 + 8) * N + c0) =
            __halves2half2(__float2half_rn(v2), __float2half_rn(v3));
      } else {
        __half h0, h1, h2, h3, l0, l1, l2, l3;
        split_h(v0, h0, l0); split_h(v1, h1, l1);
        split_h(v2, h2, l2); split_h(v3, h3, l3);
        *(__half2*)(CH + r0 * N + c0)       = __halves2half2(h0, h1);
        *(__half2*)(CH + (r0 + 8) * N + c0) = __halves2half2(h2, h3);
        *(__half2*)(CL + r0 * N + c0)       = __halves2half2(l0, l1);
        *(__half2*)(CL + (r0 + 8) * N + c0) = __halves2half2(l2, l3);
      }
    }
  }
}

#define GEMM_SMEM3 (3 * 4 * MATB)   // 196608 (3-term, 3 stages, occ 1)
#define GEMM_SMEM2 (2 * 3 * MATB)   // 98304  (2-term, 2 stages, occ 2)
#define GEMM_SMEM1 (3 * 2 * MATB)   // 98304  (1-term, 3 stages, occ 2)

// fused QKV: z=0 -> Q pair (3-term), z=1 -> K pair (3-term), z=2 -> V fp32 (2-term)
__global__ void __launch_bounds__(256, 1) qkv_h(
    const __half* __restrict__ xh, const __half* __restrict__ xl,
    const __half* __restrict__ wqh, const __half* __restrict__ wql,
    const __half* __restrict__ wkh, const __half* __restrict__ wkl,
    const __half* __restrict__ wvh, const __half* __restrict__ wvl,
    __half* __restrict__ qh, __half* __restrict__ ql,
    __half* __restrict__ kh, __half* __restrict__ kl,
    float* __restrict__ v) {
  extern __shared__ char smem[];
  const int z = blockIdx.z;
  const __half* Bh = (z == 0) ? wqh : (z == 1) ? wkh : wvh;
  const __half* Bl = (z == 0) ? wql : (z == 1) ? wkl : wvl;
  __half* CH = (z == 0) ? qh : kh;
  __half* CL = (z == 0) ? ql : kl;
  gemm_h_body<3, 3>(xh, xl, Bh, Bl, (z == 2) ? v : nullptr, CH, CL,
                    DM, DM, (z == 2) ? 0 : 1, z != 2,
                    smem, blockIdx.x, blockIdx.y);
}

// 2-term GEMM (WO), occupancy 2
__global__ void __launch_bounds__(256, 2) gemm2_h(
    const __half* __restrict__ Ah, const __half* __restrict__ Al,
    const __half* __restrict__ Bh,
    float* __restrict__ Cf, __half* __restrict__ CH, __half* __restrict__ CL,
    int K, int N, int mode) {
  extern __shared__ char smem[];
  gemm_h_body<2, 2>(Ah, Al, Bh, nullptr, Cf, CH, CL, K, N, mode, false,
                    smem, blockIdx.x, blockIdx.y);
}

// 1-term GEMM (FF1 / FF2), occupancy 2, 3-stage
__global__ void __launch_bounds__(256, 2) gemm1_h(
    const __half* __restrict__ Ah, const __half* __restrict__ Bh,
    float* __restrict__ Cf, __half* __restrict__ CH,
    int K, int N, int mode) {
  extern __shared__ char smem[];
  gemm_h_body<1, 3>(Ah, nullptr, Bh, nullptr, Cf, CH, nullptr, K, N, mode,
                    false, smem, blockIdx.x, blockIdx.y);
}

// ================= weight transpose, layer-batched =========================
__global__ void __launch_bounds__(256) transpose_split_h(
    const float* __restrict__ W, __half* __restrict__ Th,
    __half* __restrict__ Tl, int K, int N) {
  __shared__ float t[32][33];
  const size_t lo = (size_t)blockIdx.z * K * N;
  const int n0 = blockIdx.x * 32, k0 = blockIdx.y * 32;
  const int tx = threadIdx.x & 31, ty = threadIdx.x >> 5;
#pragma unroll
  for (int i = 0; i < 4; i++)
    t[ty + i * 8][tx] = W[lo + (size_t)(k0 + ty + i * 8) * N + n0 + tx];
  __syncthreads();
#pragma unroll
  for (int i = 0; i < 4; i++) {
    int n = n0 + ty + i * 8, k = k0 + tx;
    __half h, l;
    split_h(t[tx][ty + i * 8], h, l);
    Th[lo + (size_t)n * K + k] = h;
    if (Tl) Tl[lo + (size_t)n * K + k] = l;
  }
}

// ================= V transpose (hi only): v[row,h*64+d] -> vt[(bh*64+d),l] =
__global__ void __launch_bounds__(256) vtrans_kernel(
    const float* __restrict__ v, __half* __restrict__ vth) {
  __shared__ float t[32][33];
  const int bh = blockIdx.z;
  const int l0 = blockIdx.x * 32, d0 = blockIdx.y * 32;
  const int tx = threadIdx.x & 31, ty = threadIdx.x >> 5;
  const int b = bh >> 4, h = bh & 15;
#pragma unroll
  for (int i = 0; i < 4; i++)
    t[ty + i * 8][tx] =
        v[((size_t)b * LSEQ + l0 + ty + i * 8) * DM + h * DKH + d0 + tx];
  __syncthreads();
#pragma unroll
  for (int i = 0; i < 4; i++) {
    int d = d0 + ty + i * 8, l = l0 + tx;
    vth[((size_t)bh * DKH + d) * LSEQ + l] = __float2half_rn(t[tx][ty + i * 8]);
  }
}

// ================= embedding + PE (fp32 + fp16 pair out) ===================
__global__ void __launch_bounds__(256) embed_kernel(
    const int* __restrict__ toks, const float* __restrict__ emb,
    const float* __restrict__ pe, float* __restrict__ X,
    __half* __restrict__ XH, __half* __restrict__ XL) {
  int row = blockIdx.x;
  int l   = row & (LSEQ - 1);
  int tok = toks[row];
  const float4* e = (const float4*)(emb + (size_t)tok * DM);
  const float4* p = (const float4*)(pe  + (size_t)l   * DM);
  int t = threadIdx.x;
  float4 a = e[t], b = p[t];
  float4 v = make_float4(a.x + b.x, a.y + b.y, a.z + b.z, a.w + b.w);
  ((float4*)(X + (size_t)row * DM))[t] = v;
  __half h0, h1, h2, h3, l0, l1, l2, l3;
  split_h(v.x, h0, l0); split_h(v.y, h1, l1);
  split_h(v.z, h2, l2); split_h(v.w, h3, l3);
  __half2* H = (__half2*)(XH + (size_t)row * DM);
  __half2* L = (__half2*)(XL + (size_t)row * DM);
  H[2 * t]     = __halves2half2(h0, h1);
  H[2 * t + 1] = __halves2half2(h2, h3);
  L[2 * t]     = __halves2half2(l0, l1);
  L[2 * t + 1] = __halves2half2(l2, l3);
}

// ================= fp16 HMMA fused attention ===============================
// Pass 1 (scores): 3-term. Pass 3 (ctx): 2-term, V hi only.
#define PP 1028
#define ATT_PROBS_B (32 * PP * 4)        // 131584
#define ATT_Q_B     8192
#define ATT_MASK_B  4096
#define ATT_CHUNK_B 65536
#define ATT_SMEM (ATT_PROBS_B + ATT_Q_B + ATT_MASK_B + ATT_CHUNK_B)

__global__ void __launch_bounds__(256, 1) attn_mma(
    const __half* __restrict__ qh, const __half* __restrict__ ql,
    const __half* __restrict__ kh, const __half* __restrict__ kl,
    const __half* __restrict__ vth,
    const int* __restrict__ toks, float* __restrict__ attn_out,
    __half* __restrict__ ch, __half* __restrict__ cl) {
  extern __shared__ char asmem[];
  float* probs = (float*)asmem;
  char* qbuf   = asmem + ATT_PROBS_B;
  float* maskb = (float*)(qbuf + ATT_Q_B);
  char* chunk  = qbuf + ATT_Q_B + ATT_MASK_B;
  const uint32_t qb = smem_to_u32(qbuf);
  const uint32_t kb = smem_to_u32(chunk);

  const int b = blockIdx.z, h = blockIdx.y;
  const int q0 = blockIdx.x * 32;
  const int tid = threadIdx.x, wid = tid >> 5, lane = tid & 31;

  const int aRowOff = ((lane >> 3) & 1) * 8 + (lane & 7);
  const int aCSel   = (lane >> 4) & 1;
  const int bRowOff = ((lane >> 4) & 1) * 8 + (lane & 7);
  const int bCSel   = (lane >> 3) & 1;
  const int rT = lane >> 2, cT = (lane & 3) * 2;

#pragma unroll
  for (int i = 0; i < 2; i++) {
    int id = tid + i * 256;
    int buf = id >> 8;
    int r = (id & 255) >> 3, seg = id & 7;
    const __half* src = (buf ? ql : qh)
        + ((size_t)b * LSEQ + q0 + r) * DM + h * DKH + seg * 8;
    uint4 val = *(const uint4*)src;
    *(uint4*)(qbuf + buf * 4096 + r * 128 + ((seg ^ (r & 7)) << 4)) = val;
  }
  for (int j = tid; j < LSEQ; j += 256)
    maskb[j] = (toks[b * LSEQ + j] == 0) ? -1e9f : 0.f;
  __syncthreads();

  // ---- Pass 1: scores, 4 chunks of 256 keys (3-term) ----
  for (int c = 0; c < 4; c++) {
    if (c) __syncthreads();
#pragma unroll
    for (int i = 0; i < 16; i++) {
      int id = tid + i * 256;
      int buf = id >> 11;
      int sub = id & 2047;
      int r = sub >> 3, seg = sub & 7;
      const __half* src = (buf ? kl : kh)
          + ((size_t)b * LSEQ + c * 256 + r) * DM + h * DKH + seg * 8;
      uint4 val = *(const uint4*)src;
      *(uint4*)(chunk + buf * 32768 + r * 128 + ((seg ^ (r & 7)) << 4)) = val;
    }
    __syncthreads();

    float acc[2][4][4];
#pragma unroll
    for (int mt = 0; mt < 2; mt++)
#pragma unroll
      for (int nt = 0; nt < 4; nt++)
#pragma unroll
        for (int e = 0; e < 4; e++) acc[mt][nt][e] = 0.f;

#pragma unroll
    for (int kk = 0; kk < 4; kk++) {
      uint32_t a_h[2][4], a_l[2][4];
#pragma unroll
      for (int mt = 0; mt < 2; mt++) {
        int row = mt * 16 + aRowOff;
        int ci  = kk * 2 + aCSel;
        uint32_t off = row * 128 + ((ci ^ (row & 7)) << 4);
        LDSM4(a_h[mt], qb + off);
        LDSM4(a_l[mt], qb + 4096 + off);
      }
      uint32_t b_h[2][4], b_l[2][4];
#pragma unroll
      for (int ng = 0; ng < 2; ng++) {
        int row = wid * 32 + ng * 16 + bRowOff;
        int ci  = kk * 2 + bCSel;
        uint32_t off = row * 128 + ((ci ^ (row & 7)) << 4);
        LDSM4(b_h[ng], kb + off);
        LDSM4(b_l[ng], kb + 32768 + off);
      }
#pragma unroll
      for (int mt = 0; mt < 2; mt++)
#pragma unroll
        for (int nt = 0; nt < 4; nt++) {
          const int ng = nt >> 1, j = (nt & 1) * 2;
          MMAF16(acc[mt][nt], a_h[mt], b_h[ng][j], b_h[ng][j + 1]);
          MMAF16(acc[mt][nt], a_h[mt], b_l[ng][j], b_l[ng][j + 1]);
          MMAF16(acc[mt][nt], a_l[mt], b_h[ng][j], b_h[ng][j + 1]);
        }
    }
#pragma unroll
    for (int mt = 0; mt < 2; mt++)
#pragma unroll
      for (int nt = 0; nt < 4; nt++) {
        int col = c * 256 + wid * 32 + nt * 8 + cT;
        float b0 = maskb[col], b1 = maskb[col + 1];
        int r0 = mt * 16 + rT;
        probs[r0 * PP + col]           = acc[mt][nt][0] * 0.125f + b0;
        probs[r0 * PP + col + 1]       = acc[mt][nt][1] * 0.125f + b1;
        probs[(r0 + 8) * PP + col]     = acc[mt][nt][2] * 0.125f + b0;
        probs[(r0 + 8) * PP + col + 1] = acc[mt][nt][3] * 0.125f + b1;
      }
  }
  __syncthreads();

  // ---- Pass 2: softmax ----
#pragma unroll
  for (int rr = 0; rr < 4; rr++) {
    int r = wid + rr * 8;
    float* pr = &probs[r * PP];
    float m = -1e30f;
    for (int j = lane; j < LSEQ; j += 32) m = fmaxf(m, pr[j]);
#pragma unroll
    for (int off = 16; off > 0; off >>= 1)
      m = fmaxf(m, __shfl_xor_sync(0xFFFFFFFFu, m, off));
    float s = 0.f;
    for (int j = lane; j < LSEQ; j += 32) {
      float e = __expf(pr[j] - m);
      pr[j] = e; s += e;
    }
#pragma unroll
    for (int off = 16; off > 0; off >>= 1)
      s += __shfl_xor_sync(0xFFFFFFFFu, s, off);
    float inv = 1.0f / s;
    if (attn_out) {
      float* ao = attn_out + ((size_t)(b * NH + h) * LSEQ + q0 + r) * LSEQ;
      for (int j = lane; j < LSEQ; j += 32) {
        float p = pr[j] * inv; pr[j] = p; ao[j] = p;
      }
    } else {
      for (int j = lane; j < LSEQ; j += 32) pr[j] *= inv;
    }
  }

  // ---- Pass 3: ctx = P @ V, 8 chunks of 128 keys (2-term, V hi) ----
  const uint32_t pb = kb;
  const uint32_t vb = kb + 16384;
  const int mt_w = wid >> 2;
  const int ng_w = wid & 3;
  float cacc[2][4] = {};
  for (int c = 0; c < 8; c++) {
    __syncthreads();
#pragma unroll
    for (int i = 0; i < 2; i++) {
      int id = tid + i * 256;
      int r = id >> 4, seg = id & 15;
      const float* pr = &probs[r * PP + c * 128 + seg * 8];
      float4 p0 = *(const float4*)pr;
      float4 p1 = *(const float4*)(pr + 4);
      __half hh[8], ll[8];
      float pv[8] = {p0.x, p0.y, p0.z, p0.w, p1.x, p1.y, p1.z, p1.w};
#pragma unroll
      for (int e = 0; e < 8; e++) split_h(pv[e], hh[e], ll[e]);
      uint32_t off = r * 256 + ((seg ^ (r & 7)) << 4);
      *(uint4*)(chunk + off)        = *(uint4*)hh;
      *(uint4*)(chunk + 8192 + off) = *(uint4*)ll;
    }
#pragma unroll
    for (int i = 0; i < 4; i++) {
      int id = tid + i * 256;
      int r = id >> 4, seg = id & 15;
      const __half* src = vth
          + ((size_t)(b * NH + h) * DKH + r) * LSEQ + c * 128 + seg * 8;
      uint4 val = *(const uint4*)src;
      *(uint4*)(chunk + 16384 + r * 256 + ((seg ^ (r & 7)) << 4)) = val;
    }
    __syncthreads();
#pragma unroll
    for (int kk = 0; kk < 8; kk++) {
      uint32_t p_h[4], p_l[4];
      {
        int row = mt_w * 16 + aRowOff;
        int ci  = kk * 2 + aCSel;
        uint32_t off = row * 256 + ((ci ^ (row & 7)) << 4);
        LDSM4(p_h, pb + off);
        LDSM4(p_l, pb + 8192 + off);
      }
      uint32_t v_h[4];
      {
        int row = ng_w * 16 + bRowOff;
        int ci  = kk * 2 + bCSel;
        uint32_t off = row * 256 + ((ci ^ (row & 7)) << 4);
        LDSM4(v_h, vb + off);
      }
#pragma unroll
      for (int nt = 0; nt < 2; nt++) {
        const int j = nt * 2;
        MMAF16(cacc[nt], p_h, v_h[j], v_h[j + 1]);
        MMAF16(cacc[nt], p_l, v_h[j], v_h[j + 1]);
      }
    }
  }
#pragma unroll
  for (int nt = 0; nt < 2; nt++) {
    size_t r0 = (size_t)b * LSEQ + q0 + mt_w * 16 + rT;
    size_t c0 = h * DKH + ng_w * 16 + nt * 8 + cT;
    __half h0, h1, h2, h3, l0, l1, l2, l3;
    split_h(cacc[nt][0], h0, l0); split_h(cacc[nt][1], h1, l1);
    split_h(cacc[nt][2], h2, l2); split_h(cacc[nt][3], h3, l3);
    *(__half2*)(ch + r0 * DM + c0)       = __halves2half2(h0, h1);
    *(__half2*)(ch + (r0 + 8) * DM + c0) = __halves2half2(h2, h3);
    *(__half2*)(cl + r0 * DM + c0)       = __halves2half2(l0, l1);
    *(__half2*)(cl + (r0 + 8) * DM + c0) = __halves2half2(l2, l3);
  }
}

// ================= residual add + LayerNorm (fp32 + fp16 pair out) =========
__global__ void __launch_bounds__(256) ln_res(
    const float* __restrict__ A, const float* __restrict__ Xin,
    float* __restrict__ Xout,
    __half* __restrict__ XH, __half* __restrict__ XL) {
  const int row = blockIdx.x, t = threadIdx.x;
  const float4* a4 = (const float4*)(A + (size_t)row * DM);
  const float4* xi = (const float4*)(Xin + (size_t)row * DM);
  float4 a = a4[t], x = xi[t];
  float v0 = a.x + x.x, v1 = a.y + x.y, v2 = a.z + x.z, v3 = a.w + x.w;
  float s = v0 + v1 + v2 + v3;
  float q = v0 * v0 + v1 * v1 + v2 * v2 + v3 * v3;
#pragma unroll
  for (int off = 16; off > 0; off >>= 1) {
    s += __shfl_xor_sync(0xFFFFFFFFu, s, off);
    q += __shfl_xor_sync(0xFFFFFFFFu, q, off);
  }
  __shared__ float rs[8], rq[8];
  __shared__ float mu_s, rstd_s;
  int warp = t >> 5, lane = t & 31;
  if (lane == 0) { rs[warp] = s; rq[warp] = q; }
  __syncthreads();
  if (t == 0) {
    float S = 0.f, Qq = 0.f;
#pragma unroll
    for (int i = 0; i < 8; i++) { S += rs[i]; Qq += rq[i]; }
    float mu = S * (1.0f / DM);
    float var = Qq * (1.0f / DM) - mu * mu;
    mu_s = mu;
    rstd_s = rsqrtf(var + 1e-5f);
  }
  __syncthreads();
  float mu = mu_s, r = rstd_s;
  float o0 = (v0 - mu) * r, o1 = (v1 - mu) * r;
  float o2 = (v2 - mu) * r, o3 = (v3 - mu) * r;
  ((float4*)(Xout + (size_t)row * DM))[t] = make_float4(o0, o1, o2, o3);
  __half h0, h1, h2, h3, l0, l1, l2, l3;
  split_h(o0, h0, l0); split_h(o1, h1, l1);
  split_h(o2, h2, l2); split_h(o3, h3, l3);
  __half2* H = (__half2*)(XH + (size_t)row * DM);
  __half2* L = (__half2*)(XL + (size_t)row * DM);
  H[2 * t]     = __halves2half2(h0, h1);
  H[2 * t + 1] = __halves2half2(h2, h3);
  L[2 * t]     = __halves2half2(l0, l1);
  L[2 * t + 1] = __halves2half2(l2, l3);
}

// ================= launcher ================================================
extern "C" void kernel_launch(void* const* d_in, const int* in_sizes, int n_in,
                              void* d_out, int out_size) {
  const int*   toks = (const int*)  d_in[0];
  const float* emb  = (const float*)d_in[1];
  const float* pe   = (const float*)d_in[2];
  const float* WQ   = (const float*)d_in[3];
  const float* WK   = (const float*)d_in[4];
  const float* WV   = (const float*)d_in[5];
  const float* WO   = (const float*)d_in[6];
  const float* W1   = (const float*)d_in[7];
  const float* W2   = (const float*)d_in[8];
  float* out = (float*)d_out;

  float *x, *tmp, *v;
  cudaGetSymbolAddress((void**)&x,   g_x);
  cudaGetSymbolAddress((void**)&tmp, g_tmp);
  cudaGetSymbolAddress((void**)&v,   g_v);

  __half *xh,*xl,*qh,*ql,*kh,*kl,*vth,*ch,*cl,*fh;
  cudaGetSymbolAddress((void**)&xh, g_xh);  cudaGetSymbolAddress((void**)&xl, g_xl);
  cudaGetSymbolAddress((void**)&qh, g_qh);  cudaGetSymbolAddress((void**)&ql, g_ql);
  cudaGetSymbolAddress((void**)&kh, g_kh);  cudaGetSymbolAddress((void**)&kl, g_kl);
  cudaGetSymbolAddress((void**)&vth, g_vth);
  cudaGetSymbolAddress((void**)&ch, g_ch);  cudaGetSymbolAddress((void**)&cl, g_cl);
  cudaGetSymbolAddress((void**)&fh, g_fh);

  __half *wqh,*wql,*wkh,*wkl,*wvh,*wvl,*woh,*wol,*w1h,*w2h;
  cudaGetSymbolAddress((void**)&wqh, g_wqh); cudaGetSymbolAddress((void**)&wql, g_wql);
  cudaGetSymbolAddress((void**)&wkh, g_wkh); cudaGetSymbolAddress((void**)&wkl, g_wkl);
  cudaGetSymbolAddress((void**)&wvh, g_wvh); cudaGetSymbolAddress((void**)&wvl, g_wvl);
  cudaGetSymbolAddress((void**)&woh, g_woh); cudaGetSymbolAddress((void**)&wol, g_wol);
  cudaGetSymbolAddress((void**)&w1h, g_w1h);
  cudaGetSymbolAddress((void**)&w2h, g_w2h);

  const size_t XE = (size_t)ROWS * DM;
  const size_t AE = (size_t)NL * B_ * NH * LSEQ * LSEQ;
  float* attn_base = ((size_t)out_size >= XE + AE) ? (out + XE) : nullptr;

  cudaFuncSetAttribute(attn_mma, cudaFuncAttributeMaxDynamicSharedMemorySize, ATT_SMEM);
  cudaFuncSetAttribute(qkv_h,   cudaFuncAttributeMaxDynamicSharedMemorySize, GEMM_SMEM3);
  cudaFuncSetAttribute(gemm2_h, cudaFuncAttributeMaxDynamicSharedMemorySize, GEMM_SMEM2);
  cudaFuncSetAttribute(gemm1_h, cudaFuncAttributeMaxDynamicSharedMemorySize, GEMM_SMEM1);

  // ---- weight preprocessing ----
  transpose_split_h<<<dim3(DM/32, DM/32, NL), 256>>>(WQ, wqh, wql, DM, DM);
  transpose_split_h<<<dim3(DM/32, DM/32, NL), 256>>>(WK, wkh, wkl, DM, DM);
  transpose_split_h<<<dim3(DM/32, DM/32, NL), 256>>>(WV, wvh, wvl, DM, DM);
  transpose_split_h<<<dim3(DM/32, DM/32, NL), 256>>>(WO, woh, wol, DM, DM);
  transpose_split_h<<<dim3(DFF/32, DM/32, NL), 256>>>(W1, w1h, nullptr, DM, DFF);
  transpose_split_h<<<dim3(DM/32, DFF/32, NL), 256>>>(W2, w2h, nullptr, DFF, DM);

  embed_kernel<<<ROWS, 256>>>(toks, emb, pe, x, xh, xl);

  const dim3 gQKV (DM / 128, ROWS / 128, 3);       // (8, 32, 3)
  const dim3 gProj(DM / 128, ROWS / 128);          // (8, 32)
  const dim3 gFF1 (DFF / 128, ROWS / 128);         // (32, 32)

  for (int l = 0; l < NL; l++) {
    size_t o1 = (size_t)l * DM * DM;
    size_t o2 = (size_t)l * DM * DFF;

    qkv_h<<<gQKV, 256, GEMM_SMEM3>>>(xh, xl,
                                     wqh + o1, wql + o1,
                                     wkh + o1, wkl + o1,
                                     wvh + o1, wvl + o1,
                                     qh, ql, kh, kl, v);
    vtrans_kernel<<<dim3(LSEQ/32, DKH/32, B_*NH), 256>>>(v, vth);

    float* ao = attn_base ? attn_base + (size_t)l * B_ * NH * LSEQ * LSEQ : nullptr;
    attn_mma<<<dim3(LSEQ/32, NH, B_), 256, ATT_SMEM>>>(
        qh, ql, kh, kl, vth, toks, ao, ch, cl);

    gemm2_h<<<gProj, 256, GEMM_SMEM2>>>(ch, cl, woh + o1,
                                        tmp, nullptr, nullptr, DM, DM, 0);
    ln_res<<<ROWS, 256>>>(tmp, x, x, xh, xl);

    gemm1_h<<<gFF1, 256, GEMM_SMEM1>>>(xh, w1h + o2,
                                       nullptr, fh, DM, DFF, 3);
    gemm1_h<<<gProj, 256, GEMM_SMEM1>>>(fh, w2h + o2,
                                        tmp, nullptr, DFF, DM, 0);
    float* xdst = (l == NL - 1) ? out : x;
    ln_res<<<ROWS, 256>>>(tmp, x, xdst, xh, xl);
  }
}

// round 16
// speedup vs baseline: 4.4251x; 1.0960x over previous
#include <cuda_runtime.h>
#include <cuda_fp16.h>
#include <cstdint>
#include <math.h>

#define B_   4
#define LSEQ 1024
#define DM   1024
#define NH   16
#define DKH  64
#define DFF  4096
#define NL   2
#define ROWS (B_*LSEQ)   // 4096

// ================= scratch (device globals: allocation-guard safe) =========
__device__ float g_x  [ROWS*DM];
__device__ float g_tmp[ROWS*DM];
__device__ float g_v  [ROWS*DM];
// fp16 activations
__device__ __half g_xh[ROWS*DM],  g_xl[ROWS*DM];
__device__ __half g_qh[ROWS*DM],  g_ql[ROWS*DM];
__device__ __half g_kh[ROWS*DM];
__device__ __half g_vth[ROWS*DM];
__device__ __half g_ch[ROWS*DM];
__device__ __half g_fh[(size_t)ROWS*DFF];
// fp16 weights, pre-transposed to [N,K]; hi/lo only for WQ
__device__ __half g_wqh[NL*DM*DM], g_wql[NL*DM*DM];
__device__ __half g_wkh[NL*DM*DM];
__device__ __half g_wvh[NL*DM*DM];
__device__ __half g_woh[NL*DM*DM];
__device__ __half g_w1h[(size_t)NL*DM*DFF];
__device__ __half g_w2h[(size_t)NL*DM*DFF];

// ================= PTX helpers (sm_80-baseline; no tcgen05) ================
#define CP_ASYNC16(smem, gptr) \
  asm volatile("cp.async.cg.shared.global [%0], [%1], 16;" \
               :: "r"(smem), "l"(gptr))
#define CP_COMMIT() asm volatile("cp.async.commit_group;" ::: "memory")
#define CP_WAIT1()  asm volatile("cp.async.wait_group 1;" ::: "memory")

#define LDSM4(r, addr) \
  asm volatile("ldmatrix.sync.aligned.m8n8.x4.shared.b16 {%0,%1,%2,%3}, [%4];" \
    : "=r"((r)[0]), "=r"((r)[1]), "=r"((r)[2]), "=r"((r)[3]) : "r"(addr))

#define MMAF16(d, a, b0v, b1v) \
  asm volatile("mma.sync.aligned.m16n8k16.row.col.f32.f16.f16.f32 " \
    "{%0,%1,%2,%3}, {%4,%5,%6,%7}, {%8,%9}, {%0,%1,%2,%3};" \
    : "+f"((d)[0]), "+f"((d)[1]), "+f"((d)[2]), "+f"((d)[3]) \
    : "r"((a)[0]), "r"((a)[1]), "r"((a)[2]), "r"((a)[3]), "r"(b0v), "r"(b1v))

__device__ __forceinline__ uint32_t smem_to_u32(const void* p) {
  uint32_t a;
  asm("{ .reg .u64 t; cvta.to.shared.u64 t, %1; cvt.u32.u64 %0, t; }"
      : "=r"(a) : "l"(p));
  return a;
}

__device__ __forceinline__ void split_h(float v, __half& h, __half& l) {
  h = __float2half_rn(v);
  l = __float2half_rn(v - __half2float(h));
}

// ================= fp16 split GEMM: C = A[M,K] @ Bt[N,K]^T =================
// NTERMS=3 template with runtime flags:
//   C = Ah*Bh [+ Al*Bh if second] [+ Ah*Bl if third]
// NTERMS=1 template: C = Ah*Bh
// modes: 0 = fp32 out, 1 = half-pair out, 2 = half hi-only out
#define MATB 16384                       // 128 rows x 128 bytes

template<int NTERMS>
__device__ __forceinline__ void load_stage_h(
    uint32_t sbase, const __half* Ah, const __half* Al,
    const __half* Bh, const __half* Bl,
    size_t rowA, size_t rowB, int K, int kc, int tid,
    bool second, bool third) {
  const int NM = (NTERMS == 1) ? 2 : 4;
#pragma unroll
  for (int i = 0; i < NM * 4; i++) {
    int idx = tid + i * 256;
    int mat = idx >> 10;                 // constant per i (256 threads)
    if (NTERMS == 3) {
      if (mat == 1 && !second) continue;
      if (mat == 3 && !third) continue;
    }
    int sub = idx & 1023;
    int row = sub >> 3, seg = sub & 7;
    const __half* base;
    size_t r0;
    if (NTERMS == 1) {
      base = (mat == 0) ? Ah : Bh;
      r0 = (mat == 0) ? rowA : rowB;
    } else {
      base = (mat == 0) ? Ah : (mat == 1) ? Al : (mat == 2) ? Bh : Bl;
      r0 = (mat < 2) ? rowA : rowB;
    }
    const __half* g = base + (r0 + row) * (size_t)K + (size_t)kc * 64 + seg * 8;
    uint32_t s = sbase + mat * MATB + row * 128 + ((seg ^ (row & 7)) << 4);
    CP_ASYNC16(s, g);
  }
}

template<int NTERMS, int NSTAGE>
__device__ __forceinline__ void gemm_h_body(
    const __half* Ah, const __half* Al,
    const __half* Bh, const __half* Bl,
    float* Cf, __half* CH, __half* CL,
    int K, int N, int mode, bool relu, bool second, bool third,
    char* smem, int bx, int by) {
  const uint32_t sbm = smem_to_u32(smem);
  const int STAGEB = ((NTERMS == 1) ? 2 : 4) * MATB;
  const int tid = threadIdx.x, wid = tid >> 5, lane = tid & 31;

  const size_t rowA = (size_t)by * 128;
  const size_t rowB = (size_t)bx * 128;
  const int nch = K / 64;

  const int mbase = (wid >> 2) * 64;
  const int nbase = (wid & 3) * 32;

  const int aRowOff = ((lane >> 3) & 1) * 8 + (lane & 7);
  const int aCSel   = (lane >> 4) & 1;
  const int bRowOff = ((lane >> 4) & 1) * 8 + (lane & 7);
  const int bCSel   = (lane >> 3) & 1;

  float acc[4][4][4];
#pragma unroll
  for (int mt = 0; mt < 4; mt++)
#pragma unroll
    for (int nt = 0; nt < 4; nt++)
#pragma unroll
      for (int e = 0; e < 4; e++) acc[mt][nt][e] = 0.f;

#pragma unroll
  for (int s = 0; s < NSTAGE - 1; s++) {
    load_stage_h<NTERMS>(sbm + s * STAGEB, Ah, Al, Bh, Bl,
                         rowA, rowB, K, s, tid, second, third);
    CP_COMMIT();
  }

  for (int kc = 0; kc < nch; kc++) {
    if (NSTAGE == 2) {
      if (kc + 1 < nch)
        load_stage_h<NTERMS>(sbm + ((kc + 1) & 1) * STAGEB,
                             Ah, Al, Bh, Bl, rowA, rowB, K, kc + 1, tid,
                             second, third);
      CP_COMMIT();
      CP_WAIT1();
      __syncthreads();
    } else {
      CP_WAIT1();
      __syncthreads();
      if (kc + NSTAGE - 1 < nch)
        load_stage_h<NTERMS>(sbm + ((kc + NSTAGE - 1) % NSTAGE) * STAGEB,
                             Ah, Al, Bh, Bl, rowA, rowB, K,
                             kc + NSTAGE - 1, tid, second, third);
      CP_COMMIT();
    }

    const uint32_t bufA_h = sbm + (kc % NSTAGE) * STAGEB;
    const uint32_t bufA_l = bufA_h + MATB;
    const uint32_t bufB_h = (NTERMS == 1) ? bufA_h + MATB : bufA_h + 2 * MATB;
    const uint32_t bufB_l = bufA_h + 3 * MATB;

#pragma unroll
    for (int kk = 0; kk < 4; kk++) {
      uint32_t a_h[4][4], a_l[4][4];
#pragma unroll
      for (int mt = 0; mt < 4; mt++) {
        int row = mbase + mt * 16 + aRowOff;
        int ci  = kk * 2 + aCSel;
        uint32_t off = row * 128 + ((ci ^ (row & 7)) << 4);
        LDSM4(a_h[mt], bufA_h + off);
        if (NTERMS == 3 && second) LDSM4(a_l[mt], bufA_l + off);
      }
      uint32_t b_h[2][4], b_l[2][4];
#pragma unroll
      for (int ng = 0; ng < 2; ng++) {
        int row = nbase + ng * 16 + bRowOff;
        int ci  = kk * 2 + bCSel;
        uint32_t off = row * 128 + ((ci ^ (row & 7)) << 4);
        LDSM4(b_h[ng], bufB_h + off);
        if (NTERMS == 3 && third) LDSM4(b_l[ng], bufB_l + off);
      }
#pragma unroll
      for (int mt = 0; mt < 4; mt++)
#pragma unroll
        for (int nt = 0; nt < 4; nt++) {
          const int ng = nt >> 1, j = (nt & 1) * 2;
          MMAF16(acc[mt][nt], a_h[mt], b_h[ng][j], b_h[ng][j + 1]);
          if (NTERMS == 3 && second)
            MMAF16(acc[mt][nt], a_l[mt], b_h[ng][j], b_h[ng][j + 1]);
          if (NTERMS == 3 && third)
            MMAF16(acc[mt][nt], a_h[mt], b_l[ng][j], b_l[ng][j + 1]);
        }
    }
    __syncthreads();
  }

  const int rT = lane >> 2, cT = (lane & 3) * 2;
#pragma unroll
  for (int mt = 0; mt < 4; mt++) {
#pragma unroll
    for (int nt = 0; nt < 4; nt++) {
      size_t r0 = rowA + mbase + mt * 16 + rT;
      size_t c0 = rowB + nbase + nt * 8 + cT;
      float v0 = acc[mt][nt][0], v1 = acc[mt][nt][1];
      float v2 = acc[mt][nt][2], v3 = acc[mt][nt][3];
      if (relu) {
        v0 = fmaxf(v0, 0.f); v1 = fmaxf(v1, 0.f);
        v2 = fmaxf(v2, 0.f); v3 = fmaxf(v3, 0.f);
      }
      if (mode == 0) {
        *(float2*)(Cf + r0 * N + c0)       = make_float2(v0, v1);
        *(float2*)(Cf + (r0 + 8) * N + c0) = make_float2(v2, v3);
      } else if (mode == 2) {
        *(__half2*)(CH + r0 * N + c0) =
            __halves2half2(__float2half_rn(v0), __float2half_rn(v1));
        *(__half2*)(CH + (r0 + 8) * N + c0) =
            __halves2half2(__float2half_rn(v2), __float2half_rn(v3));
      } else {
        __half h0, h1, h2, h3, l0, l1, l2, l3;
        split_h(v0, h0, l0); split_h(v1, h1, l1);
        split_h(v2, h2, l2); split_h(v3, h3, l3);
        *(__half2*)(CH + r0 * N + c0)       = __halves2half2(h0, h1);
        *(__half2*)(CH + (r0 + 8) * N + c0) = __halves2half2(h2, h3);
        *(__half2*)(CL + r0 * N + c0)       = __halves2half2(l0, l1);
        *(__half2*)(CL + (r0 + 8) * N + c0) = __halves2half2(l2, l3);
      }
    }
  }
}

#define GEMM_SMEM3 (3 * 4 * MATB)   // 196608 (QKV, 3 stages, occ 1)
#define GEMM_SMEM1 (3 * 2 * MATB)   // 98304  (1-term, 3 stages, occ 2)

// fused QKV: z=0 Q 3-term -> pair; z=1 K 2-term -> hi; z=2 V 1-term -> fp32
__global__ void __launch_bounds__(256, 1) qkv_h(
    const __half* __restrict__ xh, const __half* __restrict__ xl,
    const __half* __restrict__ wqh, const __half* __restrict__ wql,
    const __half* __restrict__ wkh, const __half* __restrict__ wvh,
    __half* __restrict__ qh, __half* __restrict__ ql,
    __half* __restrict__ kh, float* __restrict__ v) {
  extern __shared__ char smem[];
  const int z = blockIdx.z;
  const __half* Bh = (z == 0) ? wqh : (z == 1) ? wkh : wvh;
  const __half* Bl = wql;
  const bool second = (z != 2);
  const bool third  = (z == 0);
  const int mode = (z == 0) ? 1 : (z == 1) ? 2 : 0;
  __half* CH = (z == 0) ? qh : kh;
  gemm_h_body<3, 3>(xh, xl, Bh, Bl, (z == 2) ? v : nullptr, CH, ql,
                    DM, DM, mode, false, second, third,
                    smem, blockIdx.x, blockIdx.y);
}

// 1-term GEMM (WO / FF1 / FF2), occupancy 2, 3-stage
__global__ void __launch_bounds__(256, 2) gemm1_h(
    const __half* __restrict__ Ah, const __half* __restrict__ Bh,
    float* __restrict__ Cf, __half* __restrict__ CH,
    int K, int N, int mode, int relu) {
  extern __shared__ char smem[];
  gemm_h_body<1, 3>(Ah, nullptr, Bh, nullptr, Cf, CH, nullptr, K, N, mode,
                    relu != 0, false, false, smem, blockIdx.x, blockIdx.y);
}

// ================= weight transpose, layer-batched =========================
__global__ void __launch_bounds__(256) transpose_split_h(
    const float* __restrict__ W, __half* __restrict__ Th,
    __half* __restrict__ Tl, int K, int N) {
  __shared__ float t[32][33];
  const size_t lo = (size_t)blockIdx.z * K * N;
  const int n0 = blockIdx.x * 32, k0 = blockIdx.y * 32;
  const int tx = threadIdx.x & 31, ty = threadIdx.x >> 5;
#pragma unroll
  for (int i = 0; i < 4; i++)
    t[ty + i * 8][tx] = W[lo + (size_t)(k0 + ty + i * 8) * N + n0 + tx];
  __syncthreads();
#pragma unroll
  for (int i = 0; i < 4; i++) {
    int n = n0 + ty + i * 8, k = k0 + tx;
    __half h, l;
    split_h(t[tx][ty + i * 8], h, l);
    Th[lo + (size_t)n * K + k] = h;
    if (Tl) Tl[lo + (size_t)n * K + k] = l;
  }
}

// ================= V transpose (hi only): v[row,h*64+d] -> vt[(bh*64+d),l] =
__global__ void __launch_bounds__(256) vtrans_kernel(
    const float* __restrict__ v, __half* __restrict__ vth) {
  __shared__ float t[32][33];
  const int bh = blockIdx.z;
  const int l0 = blockIdx.x * 32, d0 = blockIdx.y * 32;
  const int tx = threadIdx.x & 31, ty = threadIdx.x >> 5;
  const int b = bh >> 4, h = bh & 15;
#pragma unroll
  for (int i = 0; i < 4; i++)
    t[ty + i * 8][tx] =
        v[((size_t)b * LSEQ + l0 + ty + i * 8) * DM + h * DKH + d0 + tx];
  __syncthreads();
#pragma unroll
  for (int i = 0; i < 4; i++) {
    int d = d0 + ty + i * 8, l = l0 + tx;
    vth[((size_t)bh * DKH + d) * LSEQ + l] = __float2half_rn(t[tx][ty + i * 8]);
  }
}

// ================= embedding + PE (fp32 + fp16 pair out) ===================
__global__ void __launch_bounds__(256) embed_kernel(
    const int* __restrict__ toks, const float* __restrict__ emb,
    const float* __restrict__ pe, float* __restrict__ X,
    __half* __restrict__ XH, __half* __restrict__ XL) {
  int row = blockIdx.x;
  int l   = row & (LSEQ - 1);
  int tok = toks[row];
  const float4* e = (const float4*)(emb + (size_t)tok * DM);
  const float4* p = (const float4*)(pe  + (size_t)l   * DM);
  int t = threadIdx.x;
  float4 a = e[t], b = p[t];
  float4 v = make_float4(a.x + b.x, a.y + b.y, a.z + b.z, a.w + b.w);
  ((float4*)(X + (size_t)row * DM))[t] = v;
  __half h0, h1, h2, h3, l0, l1, l2, l3;
  split_h(v.x, h0, l0); split_h(v.y, h1, l1);
  split_h(v.z, h2, l2); split_h(v.w, h3, l3);
  __half2* H = (__half2*)(XH + (size_t)row * DM);
  __half2* L = (__half2*)(XL + (size_t)row * DM);
  H[2 * t]     = __halves2half2(h0, h1);
  H[2 * t + 1] = __halves2half2(h2, h3);
  L[2 * t]     = __halves2half2(l0, l1);
  L[2 * t + 1] = __halves2half2(l2, l3);
}

// ================= fp16 HMMA fused attention ===============================
// Pass 1 (scores): (Qh+Ql)@Kh (2-term). Pass 3 (ctx): (Ph+Pl)@Vh (2-term).
#define PP 1028
#define ATT_PROBS_B (32 * PP * 4)        // 131584
#define ATT_Q_B     8192
#define ATT_MASK_B  4096
#define ATT_CHUNK_B 32768
#define ATT_SMEM (ATT_PROBS_B + ATT_Q_B + ATT_MASK_B + ATT_CHUNK_B)

__global__ void __launch_bounds__(256, 1) attn_mma(
    const __half* __restrict__ qh, const __half* __restrict__ ql,
    const __half* __restrict__ kh, const __half* __restrict__ vth,
    const int* __restrict__ toks, float* __restrict__ attn_out,
    __half* __restrict__ ch) {
  extern __shared__ char asmem[];
  float* probs = (float*)asmem;
  char* qbuf   = asmem + ATT_PROBS_B;
  float* maskb = (float*)(qbuf + ATT_Q_B);
  char* chunk  = qbuf + ATT_Q_B + ATT_MASK_B;
  const uint32_t qb = smem_to_u32(qbuf);
  const uint32_t kb = smem_to_u32(chunk);

  const int b = blockIdx.z, h = blockIdx.y;
  const int q0 = blockIdx.x * 32;
  const int tid = threadIdx.x, wid = tid >> 5, lane = tid & 31;

  const int aRowOff = ((lane >> 3) & 1) * 8 + (lane & 7);
  const int aCSel   = (lane >> 4) & 1;
  const int bRowOff = ((lane >> 4) & 1) * 8 + (lane & 7);
  const int bCSel   = (lane >> 3) & 1;
  const int rT = lane >> 2, cT = (lane & 3) * 2;

#pragma unroll
  for (int i = 0; i < 2; i++) {
    int id = tid + i * 256;
    int buf = id >> 8;
    int r = (id & 255) >> 3, seg = id & 7;
    const __half* src = (buf ? ql : qh)
        + ((size_t)b * LSEQ + q0 + r) * DM + h * DKH + seg * 8;
    uint4 val = *(const uint4*)src;
    *(uint4*)(qbuf + buf * 4096 + r * 128 + ((seg ^ (r & 7)) << 4)) = val;
  }
  for (int j = tid; j < LSEQ; j += 256)
    maskb[j] = (toks[b * LSEQ + j] == 0) ? -1e9f : 0.f;
  __syncthreads();

  // ---- Pass 1: scores, 4 chunks of 256 keys (2-term) ----
  for (int c = 0; c < 4; c++) {
    if (c) __syncthreads();
#pragma unroll
    for (int i = 0; i < 8; i++) {
      int id = tid + i * 256;          // 0..2047
      int r = id >> 3, seg = id & 7;
      const __half* src = kh
          + ((size_t)b * LSEQ + c * 256 + r) * DM + h * DKH + seg * 8;
      uint4 val = *(const uint4*)src;
      *(uint4*)(chunk + r * 128 + ((seg ^ (r & 7)) << 4)) = val;
    }
    __syncthreads();

    float acc[2][4][4];
#pragma unroll
    for (int mt = 0; mt < 2; mt++)
#pragma unroll
      for (int nt = 0; nt < 4; nt++)
#pragma unroll
        for (int e = 0; e < 4; e++) acc[mt][nt][e] = 0.f;

#pragma unroll
    for (int kk = 0; kk < 4; kk++) {
      uint32_t a_h[2][4], a_l[2][4];
#pragma unroll
      for (int mt = 0; mt < 2; mt++) {
        int row = mt * 16 + aRowOff;
        int ci  = kk * 2 + aCSel;
        uint32_t off = row * 128 + ((ci ^ (row & 7)) << 4);
        LDSM4(a_h[mt], qb + off);
        LDSM4(a_l[mt], qb + 4096 + off);
      }
      uint32_t b_h[2][4];
#pragma unroll
      for (int ng = 0; ng < 2; ng++) {
        int row = wid * 32 + ng * 16 + bRowOff;
        int ci  = kk * 2 + bCSel;
        uint32_t off = row * 128 + ((ci ^ (row & 7)) << 4);
        LDSM4(b_h[ng], kb + off);
      }
#pragma unroll
      for (int mt = 0; mt < 2; mt++)
#pragma unroll
        for (int nt = 0; nt < 4; nt++) {
          const int ng = nt >> 1, j = (nt & 1) * 2;
          MMAF16(acc[mt][nt], a_h[mt], b_h[ng][j], b_h[ng][j + 1]);
          MMAF16(acc[mt][nt], a_l[mt], b_h[ng][j], b_h[ng][j + 1]);
        }
    }
#pragma unroll
    for (int mt = 0; mt < 2; mt++)
#pragma unroll
      for (int nt = 0; nt < 4; nt++) {
        int col = c * 256 + wid * 32 + nt * 8 + cT;
        float b0 = maskb[col], b1 = maskb[col + 1];
        int r0 = mt * 16 + rT;
        probs[r0 * PP + col]           = acc[mt][nt][0] * 0.125f + b0;
        probs[r0 * PP + col + 1]       = acc[mt][nt][1] * 0.125f + b1;
        probs[(r0 + 8) * PP + col]     = acc[mt][nt][2] * 0.125f + b0;
        probs[(r0 + 8) * PP + col + 1] = acc[mt][nt][3] * 0.125f + b1;
      }
  }
  __syncthreads();

  // ---- Pass 2: softmax ----
#pragma unroll
  for (int rr = 0; rr < 4; rr++) {
    int r = wid + rr * 8;
    float* pr = &probs[r * PP];
    float m = -1e30f;
    for (int j = lane; j < LSEQ; j += 32) m = fmaxf(m, pr[j]);
#pragma unroll
    for (int off = 16; off > 0; off >>= 1)
      m = fmaxf(m, __shfl_xor_sync(0xFFFFFFFFu, m, off));
    float s = 0.f;
    for (int j = lane; j < LSEQ; j += 32) {
      float e = __expf(pr[j] - m);
      pr[j] = e; s += e;
    }
#pragma unroll
    for (int off = 16; off > 0; off >>= 1)
      s += __shfl_xor_sync(0xFFFFFFFFu, s, off);
    float inv = 1.0f / s;
    if (attn_out) {
      float* ao = attn_out + ((size_t)(b * NH + h) * LSEQ + q0 + r) * LSEQ;
      for (int j = lane; j < LSEQ; j += 32) {
        float p = pr[j] * inv; pr[j] = p; ao[j] = p;
      }
    } else {
      for (int j = lane; j < LSEQ; j += 32) pr[j] *= inv;
    }
  }

  // ---- Pass 3: ctx = P @ V, 8 chunks of 128 keys (2-term, V hi) ----
  // chunk layout: Ph [32x256B]=8192, Pl 8192, Vh [64x256B]=16384
  const uint32_t pb = kb;
  const uint32_t vb = kb + 16384;
  const int mt_w = wid >> 2;
  const int ng_w = wid & 3;
  float cacc[2][4] = {};
  for (int c = 0; c < 8; c++) {
    __syncthreads();
#pragma unroll
    for (int i = 0; i < 2; i++) {
      int id = tid + i * 256;
      int r = id >> 4, seg = id & 15;
      const float* pr = &probs[r * PP + c * 128 + seg * 8];
      float4 p0 = *(const float4*)pr;
      float4 p1 = *(const float4*)(pr + 4);
      __half hh[8], ll[8];
      float pv[8] = {p0.x, p0.y, p0.z, p0.w, p1.x, p1.y, p1.z, p1.w};
#pragma unroll
      for (int e = 0; e < 8; e++) split_h(pv[e], hh[e], ll[e]);
      uint32_t off = r * 256 + ((seg ^ (r & 7)) << 4);
      *(uint4*)(chunk + off)        = *(uint4*)hh;
      *(uint4*)(chunk + 8192 + off) = *(uint4*)ll;
    }
#pragma unroll
    for (int i = 0; i < 4; i++) {
      int id = tid + i * 256;
      int r = id >> 4, seg = id & 15;
      const __half* src = vth
          + ((size_t)(b * NH + h) * DKH + r) * LSEQ + c * 128 + seg * 8;
      uint4 val = *(const uint4*)src;
      *(uint4*)(chunk + 16384 + r * 256 + ((seg ^ (r & 7)) << 4)) = val;
    }
    __syncthreads();
#pragma unroll
    for (int kk = 0; kk < 8; kk++) {
      uint32_t p_h[4], p_l[4];
      {
        int row = mt_w * 16 + aRowOff;
        int ci  = kk * 2 + aCSel;
        uint32_t off = row * 256 + ((ci ^ (row & 7)) << 4);
        LDSM4(p_h, pb + off);
        LDSM4(p_l, pb + 8192 + off);
      }
      uint32_t v_h[4];
      {
        int row = ng_w * 16 + bRowOff;
        int ci  = kk * 2 + bCSel;
        uint32_t off = row * 256 + ((ci ^ (row & 7)) << 4);
        LDSM4(v_h, vb + off);
      }
#pragma unroll
      for (int nt = 0; nt < 2; nt++) {
        const int j = nt * 2;
        MMAF16(cacc[nt], p_h, v_h[j], v_h[j + 1]);
        MMAF16(cacc[nt], p_l, v_h[j], v_h[j + 1]);
      }
    }
  }
#pragma unroll
  for (int nt = 0; nt < 2; nt++) {
    size_t r0 = (size_t)b * LSEQ + q0 + mt_w * 16 + rT;
    size_t c0 = h * DKH + ng_w * 16 + nt * 8 + cT;
    *(__half2*)(ch + r0 * DM + c0) = __halves2half2(
        __float2half_rn(cacc[nt][0]), __float2half_rn(cacc[nt][1]));
    *(__half2*)(ch + (r0 + 8) * DM + c0) = __halves2half2(
        __float2half_rn(cacc[nt][2]), __float2half_rn(cacc[nt][3]));
  }
}

// ================= residual add + LayerNorm (fp32 + fp16 pair out) =========
__global__ void __launch_bounds__(256) ln_res(
    const float* __restrict__ A, const float* __restrict__ Xin,
    float* __restrict__ Xout,
    __half* __restrict__ XH, __half* __restrict__ XL) {
  const int row = blockIdx.x, t = threadIdx.x;
  const float4* a4 = (const float4*)(A + (size_t)row * DM);
  const float4* xi = (const float4*)(Xin + (size_t)row * DM);
  float4 a = a4[t], x = xi[t];
  float v0 = a.x + x.x, v1 = a.y + x.y, v2 = a.z + x.z, v3 = a.w + x.w;
  float s = v0 + v1 + v2 + v3;
  float q = v0 * v0 + v1 * v1 + v2 * v2 + v3 * v3;
#pragma unroll
  for (int off = 16; off > 0; off >>= 1) {
    s += __shfl_xor_sync(0xFFFFFFFFu, s, off);
    q += __shfl_xor_sync(0xFFFFFFFFu, q, off);
  }
  __shared__ float rs[8], rq[8];
  __shared__ float mu_s, rstd_s;
  int warp = t >> 5, lane = t & 31;
  if (lane == 0) { rs[warp] = s; rq[warp] = q; }
  __syncthreads();
  if (t == 0) {
    float S = 0.f, Qq = 0.f;
#pragma unroll
    for (int i = 0; i < 8; i++) { S += rs[i]; Qq += rq[i]; }
    float mu = S * (1.0f / DM);
    float var = Qq * (1.0f / DM) - mu * mu;
    mu_s = mu;
    rstd_s = rsqrtf(var + 1e-5f);
  }
  __syncthreads();
  float mu = mu_s, r = rstd_s;
  float o0 = (v0 - mu) * r, o1 = (v1 - mu) * r;
  float o2 = (v2 - mu) * r, o3 = (v3 - mu) * r;
  ((float4*)(Xout + (size_t)row * DM))[t] = make_float4(o0, o1, o2, o3);
  __half h0, h1, h2, h3, l0, l1, l2, l3;
  split_h(o0, h0, l0); split_h(o1, h1, l1);
  split_h(o2, h2, l2); split_h(o3, h3, l3);
  __half2* H = (__half2*)(XH + (size_t)row * DM);
  __half2* L = (__half2*)(XL + (size_t)row * DM);
  H[2 * t]     = __halves2half2(h0, h1);
  H[2 * t + 1] = __halves2half2(h2, h3);
  L[2 * t]     = __halves2half2(l0, l1);
  L[2 * t + 1] = __halves2half2(l2, l3);
}

// ================= launcher ================================================
extern "C" void kernel_launch(void* const* d_in, const int* in_sizes, int n_in,
                              void* d_out, int out_size) {
  const int*   toks = (const int*)  d_in[0];
  const float* emb  = (const float*)d_in[1];
  const float* pe   = (const float*)d_in[2];
  const float* WQ   = (const float*)d_in[3];
  const float* WK   = (const float*)d_in[4];
  const float* WV   = (const float*)d_in[5];
  const float* WO   = (const float*)d_in[6];
  const float* W1   = (const float*)d_in[7];
  const float* W2   = (const float*)d_in[8];
  float* out = (float*)d_out;

  float *x, *tmp, *v;
  cudaGetSymbolAddress((void**)&x,   g_x);
  cudaGetSymbolAddress((void**)&tmp, g_tmp);
  cudaGetSymbolAddress((void**)&v,   g_v);

  __half *xh,*xl,*qh,*ql,*kh,*vth,*ch,*fh;
  cudaGetSymbolAddress((void**)&xh, g_xh);  cudaGetSymbolAddress((void**)&xl, g_xl);
  cudaGetSymbolAddress((void**)&qh, g_qh);  cudaGetSymbolAddress((void**)&ql, g_ql);
  cudaGetSymbolAddress((void**)&kh, g_kh);
  cudaGetSymbolAddress((void**)&vth, g_vth);
  cudaGetSymbolAddress((void**)&ch, g_ch);
  cudaGetSymbolAddress((void**)&fh, g_fh);

  __half *wqh,*wql,*wkh,*wvh,*woh,*w1h,*w2h;
  cudaGetSymbolAddress((void**)&wqh, g_wqh); cudaGetSymbolAddress((void**)&wql, g_wql);
  cudaGetSymbolAddress((void**)&wkh, g_wkh);
  cudaGetSymbolAddress((void**)&wvh, g_wvh);
  cudaGetSymbolAddress((void**)&woh, g_woh);
  cudaGetSymbolAddress((void**)&w1h, g_w1h);
  cudaGetSymbolAddress((void**)&w2h, g_w2h);

  const size_t XE = (size_t)ROWS * DM;
  const size_t AE = (size_t)NL * B_ * NH * LSEQ * LSEQ;
  float* attn_base = ((size_t)out_size >= XE + AE) ? (out + XE) : nullptr;

  cudaFuncSetAttribute(attn_mma, cudaFuncAttributeMaxDynamicSharedMemorySize, ATT_SMEM);
  cudaFuncSetAttribute(qkv_h,   cudaFuncAttributeMaxDynamicSharedMemorySize, GEMM_SMEM3);
  cudaFuncSetAttribute(gemm1_h, cudaFuncAttributeMaxDynamicSharedMemorySize, GEMM_SMEM1);

  // ---- weight preprocessing ----
  transpose_split_h<<<dim3(DM/32, DM/32, NL), 256>>>(WQ, wqh, wql, DM, DM);
  transpose_split_h<<<dim3(DM/32, DM/32, NL), 256>>>(WK, wkh, nullptr, DM, DM);
  transpose_split_h<<<dim3(DM/32, DM/32, NL), 256>>>(WV, wvh, nullptr, DM, DM);
  transpose_split_h<<<dim3(DM/32, DM/32, NL), 256>>>(WO, woh, nullptr, DM, DM);
  transpose_split_h<<<dim3(DFF/32, DM/32, NL), 256>>>(W1, w1h, nullptr, DM, DFF);
  transpose_split_h<<<dim3(DM/32, DFF/32, NL), 256>>>(W2, w2h, nullptr, DFF, DM);

  embed_kernel<<<ROWS, 256>>>(toks, emb, pe, x, xh, xl);

  const dim3 gQKV (DM / 128, ROWS / 128, 3);       // (8, 32, 3)
  const dim3 gProj(DM / 128, ROWS / 128);          // (8, 32)
  const dim3 gFF1 (DFF / 128, ROWS / 128);         // (32, 32)

  for (int l = 0; l < NL; l++) {
    size_t o1 = (size_t)l * DM * DM;
    size_t o2 = (size_t)l * DM * DFF;

    qkv_h<<<gQKV, 256, GEMM_SMEM3>>>(xh, xl,
                                     wqh + o1, wql + o1,
                                     wkh + o1, wvh + o1,
                                     qh, ql, kh, v);
    vtrans_kernel<<<dim3(LSEQ/32, DKH/32, B_*NH), 256>>>(v, vth);

    float* ao = attn_base ? attn_base + (size_t)l * B_ * NH * LSEQ * LSEQ : nullptr;
    attn_mma<<<dim3(LSEQ/32, NH, B_), 256, ATT_SMEM>>>(
        qh, ql, kh, vth, toks, ao, ch);

    gemm1_h<<<gProj, 256, GEMM_SMEM1>>>(ch, woh + o1,
                                        tmp, nullptr, DM, DM, 0, 0);
    ln_res<<<ROWS, 256>>>(tmp, x, x, xh, xl);

    gemm1_h<<<gFF1, 256, GEMM_SMEM1>>>(xh, w1h + o2,
                                       nullptr, fh, DM, DFF, 2, 1);
    gemm1_h<<<gProj, 256, GEMM_SMEM1>>>(fh, w2h + o2,
                                        tmp, nullptr, DFF, DM, 0, 0);
    float* xdst = (l == NL - 1) ? out : x;
    ln_res<<<ROWS, 256>>>(tmp, x, xdst, xh, xl);
  }
}

// round 17
// speedup vs baseline: 5.3579x; 1.2108x over previous
#include <cuda_runtime.h>
#include <cuda_fp16.h>
#include <cstdint>
#include <math.h>

#define B_   4
#define LSEQ 1024
#define DM   1024
#define NH   16
#define DKH  64
#define DFF  4096
#define NL   2
#define ROWS (B_*LSEQ)   // 4096

// ================= scratch (device globals: allocation-guard safe) =========
__device__ float g_x  [ROWS*DM];
__device__ float g_tmp[ROWS*DM];
__device__ float g_v  [ROWS*DM];
// fp16 activations
__device__ __half g_xh[ROWS*DM],  g_xl[ROWS*DM];
__device__ __half g_qh[ROWS*DM];
__device__ __half g_kh[ROWS*DM];
__device__ __half g_vth[ROWS*DM];
__device__ __half g_ch[ROWS*DM];
__device__ __half g_fh[(size_t)ROWS*DFF];
// fp16 weights (hi only), pre-transposed to [N,K]
__device__ __half g_wqh[NL*DM*DM];
__device__ __half g_wkh[NL*DM*DM];
__device__ __half g_wvh[NL*DM*DM];
__device__ __half g_woh[NL*DM*DM];
__device__ __half g_w1h[(size_t)NL*DM*DFF];
__device__ __half g_w2h[(size_t)NL*DM*DFF];

// ================= PTX helpers (sm_80-baseline; no tcgen05) ================
#define CP_ASYNC16(smem, gptr) \
  asm volatile("cp.async.cg.shared.global [%0], [%1], 16;" \
               :: "r"(smem), "l"(gptr))
#define CP_COMMIT() asm volatile("cp.async.commit_group;" ::: "memory")
#define CP_WAIT1()  asm volatile("cp.async.wait_group 1;" ::: "memory")

#define LDSM4(r, addr) \
  asm volatile("ldmatrix.sync.aligned.m8n8.x4.shared.b16 {%0,%1,%2,%3}, [%4];" \
    : "=r"((r)[0]), "=r"((r)[1]), "=r"((r)[2]), "=r"((r)[3]) : "r"(addr))

#define MMAF16(d, a, b0v, b1v) \
  asm volatile("mma.sync.aligned.m16n8k16.row.col.f32.f16.f16.f32 " \
    "{%0,%1,%2,%3}, {%4,%5,%6,%7}, {%8,%9}, {%0,%1,%2,%3};" \
    : "+f"((d)[0]), "+f"((d)[1]), "+f"((d)[2]), "+f"((d)[3]) \
    : "r"((a)[0]), "r"((a)[1]), "r"((a)[2]), "r"((a)[3]), "r"(b0v), "r"(b1v))

__device__ __forceinline__ uint32_t smem_to_u32(const void* p) {
  uint32_t a;
  asm("{ .reg .u64 t; cvta.to.shared.u64 t, %1; cvt.u32.u64 %0, t; }"
      : "=r"(a) : "l"(p));
  return a;
}

__device__ __forceinline__ void split_h(float v, __half& h, __half& l) {
  h = __float2half_rn(v);
  l = __float2half_rn(v - __half2float(h));
}

// ================= fp16 split GEMM: C = A[M,K] @ Bt[N,K]^T =================
// NTERMS=2: C = (Ah + Al) * Bh   (A-side exact)
// NTERMS=1: C = Ah * Bh
// modes: 0 = fp32 out, 2 = half hi-only out
#define MATB 16384                       // 128 rows x 128 bytes

template<int NTERMS>
__device__ __forceinline__ void load_stage_h(
    uint32_t sbase, const __half* Ah, const __half* Al, const __half* Bh,
    size_t rowA, size_t rowB, int K, int kc, int tid) {
  const int NM = NTERMS + 1;             // 2 or 3 matrices
#pragma unroll
  for (int i = 0; i < NM * 4; i++) {
    int idx = tid + i * 256;
    int mat = idx >> 10;                 // constant per i (256 threads)
    int sub = idx & 1023;
    int row = sub >> 3, seg = sub & 7;
    const __half* base;
    size_t r0;
    if (NTERMS == 1) {
      base = (mat == 0) ? Ah : Bh;
      r0 = (mat == 0) ? rowA : rowB;
    } else {
      base = (mat == 0) ? Ah : (mat == 1) ? Al : Bh;
      r0 = (mat < 2) ? rowA : rowB;
    }
    const __half* g = base + (r0 + row) * (size_t)K + (size_t)kc * 64 + seg * 8;
    uint32_t s = sbase + mat * MATB + row * 128 + ((seg ^ (row & 7)) << 4);
    CP_ASYNC16(s, g);
  }
}

template<int NTERMS, int NSTAGE>
__device__ __forceinline__ void gemm_h_body(
    const __half* Ah, const __half* Al, const __half* Bh,
    float* Cf, __half* CH,
    int K, int N, int mode, bool relu, char* smem, int bx, int by) {
  const uint32_t sbm = smem_to_u32(smem);
  const int STAGEB = (NTERMS + 1) * MATB;
  const int tid = threadIdx.x, wid = tid >> 5, lane = tid & 31;

  const size_t rowA = (size_t)by * 128;
  const size_t rowB = (size_t)bx * 128;
  const int nch = K / 64;

  const int mbase = (wid >> 2) * 64;
  const int nbase = (wid & 3) * 32;

  const int aRowOff = ((lane >> 3) & 1) * 8 + (lane & 7);
  const int aCSel   = (lane >> 4) & 1;
  const int bRowOff = ((lane >> 4) & 1) * 8 + (lane & 7);
  const int bCSel   = (lane >> 3) & 1;

  float acc[4][4][4];
#pragma unroll
  for (int mt = 0; mt < 4; mt++)
#pragma unroll
    for (int nt = 0; nt < 4; nt++)
#pragma unroll
      for (int e = 0; e < 4; e++) acc[mt][nt][e] = 0.f;

#pragma unroll
  for (int s = 0; s < NSTAGE - 1; s++) {
    load_stage_h<NTERMS>(sbm + s * STAGEB, Ah, Al, Bh, rowA, rowB, K, s, tid);
    CP_COMMIT();
  }

  for (int kc = 0; kc < nch; kc++) {
    if (NSTAGE == 2) {
      if (kc + 1 < nch)
        load_stage_h<NTERMS>(sbm + ((kc + 1) & 1) * STAGEB,
                             Ah, Al, Bh, rowA, rowB, K, kc + 1, tid);
      CP_COMMIT();
      CP_WAIT1();
      __syncthreads();
    } else {
      CP_WAIT1();
      __syncthreads();
      if (kc + NSTAGE - 1 < nch)
        load_stage_h<NTERMS>(sbm + ((kc + NSTAGE - 1) % NSTAGE) * STAGEB,
                             Ah, Al, Bh, rowA, rowB, K, kc + NSTAGE - 1, tid);
      CP_COMMIT();
    }

    const uint32_t bufA_h = sbm + (kc % NSTAGE) * STAGEB;
    const uint32_t bufA_l = bufA_h + MATB;
    const uint32_t bufB_h = bufA_h + NTERMS * MATB;

#pragma unroll
    for (int kk = 0; kk < 4; kk++) {
      uint32_t a_h[4][4], a_l[4][4];
#pragma unroll
      for (int mt = 0; mt < 4; mt++) {
        int row = mbase + mt * 16 + aRowOff;
        int ci  = kk * 2 + aCSel;
        uint32_t off = row * 128 + ((ci ^ (row & 7)) << 4);
        LDSM4(a_h[mt], bufA_h + off);
        if (NTERMS == 2) LDSM4(a_l[mt], bufA_l + off);
      }
      uint32_t b_h[2][4];
#pragma unroll
      for (int ng = 0; ng < 2; ng++) {
        int row = nbase + ng * 16 + bRowOff;
        int ci  = kk * 2 + bCSel;
        uint32_t off = row * 128 + ((ci ^ (row & 7)) << 4);
        LDSM4(b_h[ng], bufB_h + off);
      }
#pragma unroll
      for (int mt = 0; mt < 4; mt++)
#pragma unroll
        for (int nt = 0; nt < 4; nt++) {
          const int ng = nt >> 1, j = (nt & 1) * 2;
          MMAF16(acc[mt][nt], a_h[mt], b_h[ng][j], b_h[ng][j + 1]);
          if (NTERMS == 2)
            MMAF16(acc[mt][nt], a_l[mt], b_h[ng][j], b_h[ng][j + 1]);
        }
    }
    __syncthreads();
  }

  const int rT = lane >> 2, cT = (lane & 3) * 2;
#pragma unroll
  for (int mt = 0; mt < 4; mt++) {
#pragma unroll
    for (int nt = 0; nt < 4; nt++) {
      size_t r0 = rowA + mbase + mt * 16 + rT;
      size_t c0 = rowB + nbase + nt * 8 + cT;
      float v0 = acc[mt][nt][0], v1 = acc[mt][nt][1];
      float v2 = acc[mt][nt][2], v3 = acc[mt][nt][3];
      if (relu) {
        v0 = fmaxf(v0, 0.f); v1 = fmaxf(v1, 0.f);
        v2 = fmaxf(v2, 0.f); v3 = fmaxf(v3, 0.f);
      }
      if (mode == 0) {
        *(float2*)(Cf + r0 * N + c0)       = make_float2(v0, v1);
        *(float2*)(Cf + (r0 + 8) * N + c0) = make_float2(v2, v3);
      } else {
        *(__half2*)(CH + r0 * N + c0) =
            __halves2half2(__float2half_rn(v0), __float2half_rn(v1));
        *(__half2*)(CH + (r0 + 8) * N + c0) =
            __halves2half2(__float2half_rn(v2), __float2half_rn(v3));
      }
    }
  }
}

#define GEMM_SMEM2 (2 * 3 * MATB)   // 98304  (2-term, 2 stages, occ 2)
#define GEMM_SMEM1 (3 * 2 * MATB)   // 98304  (1-term, 3 stages, occ 2)
#define QKV_SMEM   GEMM_SMEM2       // max of the two (equal)

// fused QKV: z=0 Q 2-term -> hi; z=1 K 2-term -> hi; z=2 V 1-term -> fp32
__global__ void __launch_bounds__(256, 2) qkv_h(
    const __half* __restrict__ xh, const __half* __restrict__ xl,
    const __half* __restrict__ wqh, const __half* __restrict__ wkh,
    const __half* __restrict__ wvh,
    __half* __restrict__ qh, __half* __restrict__ kh,
    float* __restrict__ v) {
  extern __shared__ char smem[];
  const int z = blockIdx.z;
  if (z == 2) {
    gemm_h_body<1, 3>(xh, nullptr, wvh, v, nullptr, DM, DM, 0, false,
                      smem, blockIdx.x, blockIdx.y);
  } else {
    const __half* Bh = (z == 0) ? wqh : wkh;
    __half* CH = (z == 0) ? qh : kh;
    gemm_h_body<2, 2>(xh, xl, Bh, nullptr, CH, DM, DM, 2, false,
                      smem, blockIdx.x, blockIdx.y);
  }
}

// 1-term GEMM (WO / FF1 / FF2), occupancy 2, 3-stage
__global__ void __launch_bounds__(256, 2) gemm1_h(
    const __half* __restrict__ Ah, const __half* __restrict__ Bh,
    float* __restrict__ Cf, __half* __restrict__ CH,
    int K, int N, int mode, int relu) {
  extern __shared__ char smem[];
  gemm_h_body<1, 3>(Ah, Bh ? Bh : Bh, Bh, Cf, CH, K, N, mode, relu != 0,
                    smem, blockIdx.x, blockIdx.y);
}

// ================= weight transpose (hi only), layer-batched ===============
__global__ void __launch_bounds__(256) transpose_h(
    const float* __restrict__ W, __half* __restrict__ Th, int K, int N) {
  __shared__ float t[32][33];
  const size_t lo = (size_t)blockIdx.z * K * N;
  const int n0 = blockIdx.x * 32, k0 = blockIdx.y * 32;
  const int tx = threadIdx.x & 31, ty = threadIdx.x >> 5;
#pragma unroll
  for (int i = 0; i < 4; i++)
    t[ty + i * 8][tx] = W[lo + (size_t)(k0 + ty + i * 8) * N + n0 + tx];
  __syncthreads();
#pragma unroll
  for (int i = 0; i < 4; i++) {
    int n = n0 + ty + i * 8, k = k0 + tx;
    Th[lo + (size_t)n * K + k] = __float2half_rn(t[tx][ty + i * 8]);
  }
}

// ================= V transpose (hi only): v[row,h*64+d] -> vt[(bh*64+d),l] =
__global__ void __launch_bounds__(256) vtrans_kernel(
    const float* __restrict__ v, __half* __restrict__ vth) {
  __shared__ float t[32][33];
  const int bh = blockIdx.z;
  const int l0 = blockIdx.x * 32, d0 = blockIdx.y * 32;
  const int tx = threadIdx.x & 31, ty = threadIdx.x >> 5;
  const int b = bh >> 4, h = bh & 15;
#pragma unroll
  for (int i = 0; i < 4; i++)
    t[ty + i * 8][tx] =
        v[((size_t)b * LSEQ + l0 + ty + i * 8) * DM + h * DKH + d0 + tx];
  __syncthreads();
#pragma unroll
  for (int i = 0; i < 4; i++) {
    int d = d0 + ty + i * 8, l = l0 + tx;
    vth[((size_t)bh * DKH + d) * LSEQ + l] = __float2half_rn(t[tx][ty + i * 8]);
  }
}

// ================= embedding + PE (fp32 + fp16 pair out) ===================
__global__ void __launch_bounds__(256) embed_kernel(
    const int* __restrict__ toks, const float* __restrict__ emb,
    const float* __restrict__ pe, float* __restrict__ X,
    __half* __restrict__ XH, __half* __restrict__ XL) {
  int row = blockIdx.x;
  int l   = row & (LSEQ - 1);
  int tok = toks[row];
  const float4* e = (const float4*)(emb + (size_t)tok * DM);
  const float4* p = (const float4*)(pe  + (size_t)l   * DM);
  int t = threadIdx.x;
  float4 a = e[t], b = p[t];
  float4 v = make_float4(a.x + b.x, a.y + b.y, a.z + b.z, a.w + b.w);
  ((float4*)(X + (size_t)row * DM))[t] = v;
  __half h0, h1, h2, h3, l0, l1, l2, l3;
  split_h(v.x, h0, l0); split_h(v.y, h1, l1);
  split_h(v.z, h2, l2); split_h(v.w, h3, l3);
  __half2* H = (__half2*)(XH + (size_t)row * DM);
  __half2* L = (__half2*)(XL + (size_t)row * DM);
  H[2 * t]     = __halves2half2(h0, h1);
  H[2 * t + 1] = __halves2half2(h2, h3);
  L[2 * t]     = __halves2half2(l0, l1);
  L[2 * t + 1] = __halves2half2(l2, l3);
}

// ================= fp16 HMMA fused attention ===============================
// Pass 1 (scores): Qh@Kh (1-term). Pass 3 (ctx): Ph@Vh (1-term).
#define PP 1028
#define ATT_PROBS_B (32 * PP * 4)        // 131584
#define ATT_Q_B     4096                 // Q hi (32x64)
#define ATT_MASK_B  4096
#define ATT_CHUNK_B 32768                // K chunk / (Ph + Vh)
#define ATT_SMEM (ATT_PROBS_B + ATT_Q_B + ATT_MASK_B + ATT_CHUNK_B)

__global__ void __launch_bounds__(256, 1) attn_mma(
    const __half* __restrict__ qh, const __half* __restrict__ kh,
    const __half* __restrict__ vth,
    const int* __restrict__ toks, float* __restrict__ attn_out,
    __half* __restrict__ ch) {
  extern __shared__ char asmem[];
  float* probs = (float*)asmem;
  char* qbuf   = asmem + ATT_PROBS_B;
  float* maskb = (float*)(qbuf + ATT_Q_B);
  char* chunk  = qbuf + ATT_Q_B + ATT_MASK_B;
  const uint32_t qb = smem_to_u32(qbuf);
  const uint32_t kb = smem_to_u32(chunk);

  const int b = blockIdx.z, h = blockIdx.y;
  const int q0 = blockIdx.x * 32;
  const int tid = threadIdx.x, wid = tid >> 5, lane = tid & 31;

  const int aRowOff = ((lane >> 3) & 1) * 8 + (lane & 7);
  const int aCSel   = (lane >> 4) & 1;
  const int bRowOff = ((lane >> 4) & 1) * 8 + (lane & 7);
  const int bCSel   = (lane >> 3) & 1;
  const int rT = lane >> 2, cT = (lane & 3) * 2;

  // load Q hi tile (32 rows x 64 half = 128B/row)
  {
    int r = tid >> 3, seg = tid & 7;
    const __half* src = qh + ((size_t)b * LSEQ + q0 + r) * DM + h * DKH + seg * 8;
    uint4 val = *(const uint4*)src;
    *(uint4*)(qbuf + r * 128 + ((seg ^ (r & 7)) << 4)) = val;
  }
  for (int j = tid; j < LSEQ; j += 256)
    maskb[j] = (toks[b * LSEQ + j] == 0) ? -1e9f : 0.f;
  __syncthreads();

  // ---- Pass 1: scores, 4 chunks of 256 keys (1-term) ----
  for (int c = 0; c < 4; c++) {
    if (c) __syncthreads();
#pragma unroll
    for (int i = 0; i < 8; i++) {
      int id = tid + i * 256;          // 0..2047
      int r = id >> 3, seg = id & 7;
      const __half* src = kh
          + ((size_t)b * LSEQ + c * 256 + r) * DM + h * DKH + seg * 8;
      uint4 val = *(const uint4*)src;
      *(uint4*)(chunk + r * 128 + ((seg ^ (r & 7)) << 4)) = val;
    }
    __syncthreads();

    float acc[2][4][4];
#pragma unroll
    for (int mt = 0; mt < 2; mt++)
#pragma unroll
      for (int nt = 0; nt < 4; nt++)
#pragma unroll
        for (int e = 0; e < 4; e++) acc[mt][nt][e] = 0.f;

#pragma unroll
    for (int kk = 0; kk < 4; kk++) {
      uint32_t a_h[2][4];
#pragma unroll
      for (int mt = 0; mt < 2; mt++) {
        int row = mt * 16 + aRowOff;
        int ci  = kk * 2 + aCSel;
        uint32_t off = row * 128 + ((ci ^ (row & 7)) << 4);
        LDSM4(a_h[mt], qb + off);
      }
      uint32_t b_h[2][4];
#pragma unroll
      for (int ng = 0; ng < 2; ng++) {
        int row = wid * 32 + ng * 16 + bRowOff;
        int ci  = kk * 2 + bCSel;
        uint32_t off = row * 128 + ((ci ^ (row & 7)) << 4);
        LDSM4(b_h[ng], kb + off);
      }
#pragma unroll
      for (int mt = 0; mt < 2; mt++)
#pragma unroll
        for (int nt = 0; nt < 4; nt++) {
          const int ng = nt >> 1, j = (nt & 1) * 2;
          MMAF16(acc[mt][nt], a_h[mt], b_h[ng][j], b_h[ng][j + 1]);
        }
    }
#pragma unroll
    for (int mt = 0; mt < 2; mt++)
#pragma unroll
      for (int nt = 0; nt < 4; nt++) {
        int col = c * 256 + wid * 32 + nt * 8 + cT;
        float b0 = maskb[col], b1 = maskb[col + 1];
        int r0 = mt * 16 + rT;
        probs[r0 * PP + col]           = acc[mt][nt][0] * 0.125f + b0;
        probs[r0 * PP + col + 1]       = acc[mt][nt][1] * 0.125f + b1;
        probs[(r0 + 8) * PP + col]     = acc[mt][nt][2] * 0.125f + b0;
        probs[(r0 + 8) * PP + col + 1] = acc[mt][nt][3] * 0.125f + b1;
      }
  }
  __syncthreads();

  // ---- Pass 2: softmax ----
#pragma unroll
  for (int rr = 0; rr < 4; rr++) {
    int r = wid + rr * 8;
    float* pr = &probs[r * PP];
    float m = -1e30f;
    for (int j = lane; j < LSEQ; j += 32) m = fmaxf(m, pr[j]);
#pragma unroll
    for (int off = 16; off > 0; off >>= 1)
      m = fmaxf(m, __shfl_xor_sync(0xFFFFFFFFu, m, off));
    float s = 0.f;
    for (int j = lane; j < LSEQ; j += 32) {
      float e = __expf(pr[j] - m);
      pr[j] = e; s += e;
    }
#pragma unroll
    for (int off = 16; off > 0; off >>= 1)
      s += __shfl_xor_sync(0xFFFFFFFFu, s, off);
    float inv = 1.0f / s;
    if (attn_out) {
      float* ao = attn_out + ((size_t)(b * NH + h) * LSEQ + q0 + r) * LSEQ;
      for (int j = lane; j < LSEQ; j += 32) {
        float p = pr[j] * inv; pr[j] = p; ao[j] = p;
      }
    } else {
      for (int j = lane; j < LSEQ; j += 32) pr[j] *= inv;
    }
  }

  // ---- Pass 3: ctx = P @ V, 8 chunks of 128 keys (1-term) ----
  // chunk layout: Ph [32x256B]=8192, Vh [64x256B]=16384
  const uint32_t pb = kb;
  const uint32_t vb = kb + 8192;
  const int mt_w = wid >> 2;
  const int ng_w = wid & 3;
  float cacc[2][4] = {};
  for (int c = 0; c < 8; c++) {
    __syncthreads();
#pragma unroll
    for (int i = 0; i < 2; i++) {
      int id = tid + i * 256;
      int r = id >> 4, seg = id & 15;
      const float* pr = &probs[r * PP + c * 128 + seg * 8];
      float4 p0 = *(const float4*)pr;
      float4 p1 = *(const float4*)(pr + 4);
      __half hh[8];
      hh[0] = __float2half_rn(p0.x); hh[1] = __float2half_rn(p0.y);
      hh[2] = __float2half_rn(p0.z); hh[3] = __float2half_rn(p0.w);
      hh[4] = __float2half_rn(p1.x); hh[5] = __float2half_rn(p1.y);
      hh[6] = __float2half_rn(p1.z); hh[7] = __float2half_rn(p1.w);
      uint32_t off = r * 256 + ((seg ^ (r & 7)) << 4);
      *(uint4*)(chunk + off) = *(uint4*)hh;
    }
#pragma unroll
    for (int i = 0; i < 4; i++) {
      int id = tid + i * 256;
      int r = id >> 4, seg = id & 15;
      const __half* src = vth
          + ((size_t)(b * NH + h) * DKH + r) * LSEQ + c * 128 + seg * 8;
      uint4 val = *(const uint4*)src;
      *(uint4*)(chunk + 8192 + r * 256 + ((seg ^ (r & 7)) << 4)) = val;
    }
    __syncthreads();
#pragma unroll
    for (int kk = 0; kk < 8; kk++) {
      uint32_t p_h[4];
      {
        int row = mt_w * 16 + aRowOff;
        int ci  = kk * 2 + aCSel;
        uint32_t off = row * 256 + ((ci ^ (row & 7)) << 4);
        LDSM4(p_h, pb + off);
      }
      uint32_t v_h[4];
      {
        int row = ng_w * 16 + bRowOff;
        int ci  = kk * 2 + bCSel;
        uint32_t off = row * 256 + ((ci ^ (row & 7)) << 4);
        LDSM4(v_h, vb + off);
      }
#pragma unroll
      for (int nt = 0; nt < 2; nt++) {
        const int j = nt * 2;
        MMAF16(cacc[nt], p_h, v_h[j], v_h[j + 1]);
      }
    }
  }
#pragma unroll
  for (int nt = 0; nt < 2; nt++) {
    size_t r0 = (size_t)b * LSEQ + q0 + mt_w * 16 + rT;
    size_t c0 = h * DKH + ng_w * 16 + nt * 8 + cT;
    *(__half2*)(ch + r0 * DM + c0) = __halves2half2(
        __float2half_rn(cacc[nt][0]), __float2half_rn(cacc[nt][1]));
    *(__half2*)(ch + (r0 + 8) * DM + c0) = __halves2half2(
        __float2half_rn(cacc[nt][2]), __float2half_rn(cacc[nt][3]));
  }
}

// ================= residual add + LayerNorm (fp32 + fp16 pair out) =========
__global__ void __launch_bounds__(256) ln_res(
    const float* __restrict__ A, const float* __restrict__ Xin,
    float* __restrict__ Xout,
    __half* __restrict__ XH, __half* __restrict__ XL) {
  const int row = blockIdx.x, t = threadIdx.x;
  const float4* a4 = (const float4*)(A + (size_t)row * DM);
  const float4* xi = (const float4*)(Xin + (size_t)row * DM);
  float4 a = a4[t], x = xi[t];
  float v0 = a.x + x.x, v1 = a.y + x.y, v2 = a.z + x.z, v3 = a.w + x.w;
  float s = v0 + v1 + v2 + v3;
  float q = v0 * v0 + v1 * v1 + v2 * v2 + v3 * v3;
#pragma unroll
  for (int off = 16; off > 0; off >>= 1) {
    s += __shfl_xor_sync(0xFFFFFFFFu, s, off);
    q += __shfl_xor_sync(0xFFFFFFFFu, q, off);
  }
  __shared__ float rs[8], rq[8];
  __shared__ float mu_s, rstd_s;
  int warp = t >> 5, lane = t & 31;
  if (lane == 0) { rs[warp] = s; rq[warp] = q; }
  __syncthreads();
  if (t == 0) {
    float S = 0.f, Qq = 0.f;
#pragma unroll
    for (int i = 0; i < 8; i++) { S += rs[i]; Qq += rq[i]; }
    float mu = S * (1.0f / DM);
    float var = Qq * (1.0f / DM) - mu * mu;
    mu_s = mu;
    rstd_s = rsqrtf(var + 1e-5f);
  }
  __syncthreads();
  float mu = mu_s, r = rstd_s;
  float o0 = (v0 - mu) * r, o1 = (v1 - mu) * r;
  float o2 = (v2 - mu) * r, o3 = (v3 - mu) * r;
  ((float4*)(Xout + (size_t)row * DM))[t] = make_float4(o0, o1, o2, o3);
  __half h0, h1, h2, h3, l0, l1, l2, l3;
  split_h(o0, h0, l0); split_h(o1, h1, l1);
  split_h(o2, h2, l2); split_h(o3, h3, l3);
  __half2* H = (__half2*)(XH + (size_t)row * DM);
  __half2* L = (__half2*)(XL + (size_t)row * DM);
  H[2 * t]     = __halves2half2(h0, h1);
  H[2 * t + 1] = __halves2half2(h2, h3);
  L[2 * t]     = __halves2half2(l0, l1);
  L[2 * t + 1] = __halves2half2(l2, l3);
}

// ================= launcher ================================================
extern "C" void kernel_launch(void* const* d_in, const int* in_sizes, int n_in,
                              void* d_out, int out_size) {
  const int*   toks = (const int*)  d_in[0];
  const float* emb  = (const float*)d_in[1];
  const float* pe   = (const float*)d_in[2];
  const float* WQ   = (const float*)d_in[3];
  const float* WK   = (const float*)d_in[4];
  const float* WV   = (const float*)d_in[5];
  const float* WO   = (const float*)d_in[6];
  const float* W1   = (const float*)d_in[7];
  const float* W2   = (const float*)d_in[8];
  float* out = (float*)d_out;

  float *x, *tmp, *v;
  cudaGetSymbolAddress((void**)&x,   g_x);
  cudaGetSymbolAddress((void**)&tmp, g_tmp);
  cudaGetSymbolAddress((void**)&v,   g_v);

  __half *xh,*xl,*qh,*kh,*vth,*ch,*fh;
  cudaGetSymbolAddress((void**)&xh, g_xh);  cudaGetSymbolAddress((void**)&xl, g_xl);
  cudaGetSymbolAddress((void**)&qh, g_qh);
  cudaGetSymbolAddress((void**)&kh, g_kh);
  cudaGetSymbolAddress((void**)&vth, g_vth);
  cudaGetSymbolAddress((void**)&ch, g_ch);
  cudaGetSymbolAddress((void**)&fh, g_fh);

  __half *wqh,*wkh,*wvh,*woh,*w1h,*w2h;
  cudaGetSymbolAddress((void**)&wqh, g_wqh);
  cudaGetSymbolAddress((void**)&wkh, g_wkh);
  cudaGetSymbolAddress((void**)&wvh, g_wvh);
  cudaGetSymbolAddress((void**)&woh, g_woh);
  cudaGetSymbolAddress((void**)&w1h, g_w1h);
  cudaGetSymbolAddress((void**)&w2h, g_w2h);

  const size_t XE = (size_t)ROWS * DM;
  const size_t AE = (size_t)NL * B_ * NH * LSEQ * LSEQ;
  float* attn_base = ((size_t)out_size >= XE + AE) ? (out + XE) : nullptr;

  cudaFuncSetAttribute(attn_mma, cudaFuncAttributeMaxDynamicSharedMemorySize, ATT_SMEM);
  cudaFuncSetAttribute(qkv_h,   cudaFuncAttributeMaxDynamicSharedMemorySize, QKV_SMEM);
  cudaFuncSetAttribute(gemm1_h, cudaFuncAttributeMaxDynamicSharedMemorySize, GEMM_SMEM1);

  // ---- weight preprocessing: transpose, hi only ----
  transpose_h<<<dim3(DM/32, DM/32, NL), 256>>>(WQ, wqh, DM, DM);
  transpose_h<<<dim3(DM/32, DM/32, NL), 256>>>(WK, wkh, DM, DM);
  transpose_h<<<dim3(DM/32, DM/32, NL), 256>>>(WV, wvh, DM, DM);
  transpose_h<<<dim3(DM/32, DM/32, NL), 256>>>(WO, woh, DM, DM);
  transpose_h<<<dim3(DFF/32, DM/32, NL), 256>>>(W1, w1h, DM, DFF);
  transpose_h<<<dim3(DM/32, DFF/32, NL), 256>>>(W2, w2h, DFF, DM);

  embed_kernel<<<ROWS, 256>>>(toks, emb, pe, x, xh, xl);

  const dim3 gQKV (DM / 128, ROWS / 128, 3);       // (8, 32, 3)
  const dim3 gProj(DM / 128, ROWS / 128);          // (8, 32)
  const dim3 gFF1 (DFF / 128, ROWS / 128);         // (32, 32)

  for (int l = 0; l < NL; l++) {
    size_t o1 = (size_t)l * DM * DM;
    size_t o2 = (size_t)l * DM * DFF;

    qkv_h<<<gQKV, 256, QKV_SMEM>>>(xh, xl,
                                   wqh + o1, wkh + o1, wvh + o1,
                                   qh, kh, v);
    vtrans_kernel<<<dim3(LSEQ/32, DKH/32, B_*NH), 256>>>(v, vth);

    float* ao = attn_base ? attn_base + (size_t)l * B_ * NH * LSEQ * LSEQ : nullptr;
    attn_mma<<<dim3(LSEQ/32, NH, B_), 256, ATT_SMEM>>>(
        qh, kh, vth, toks, ao, ch);

    gemm1_h<<<gProj, 256, GEMM_SMEM1>>>(ch, woh + o1,
                                        tmp, nullptr, DM, DM, 0, 0);
    ln_res<<<ROWS, 256>>>(tmp, x, x, xh, xl);

    gemm1_h<<<gFF1, 256, GEMM_SMEM1>>>(xh, w1h + o2,
                                       nullptr, fh, DM, DFF, 2, 1);
    gemm1_h<<<gProj, 256, GEMM_SMEM1>>>(fh, w2h + o2,
                                        tmp, nullptr, DFF, DM, 0, 0);
    float* xdst = (l == NL - 1) ? out : x;
    ln_res<<<ROWS, 256>>>(tmp, x, xdst, xh, xl);
  }
}